// round 4
// baseline (speedup 1.0000x reference)
#include <cuda_runtime.h>
#include <cuda_fp16.h>
#include <math.h>
#include <cstdint>

// ---------------- problem constants ----------------
#define BB 32
#define KK 2048
#define CC 256
#define PP 256
#define SS 16
#define NCOL (BB*PP*SS)      // 131072
#define NP   (BB*PP)         // 8192
#define KP   320             // 259 padded to mult of 32
#define OUTC 119

// output section offsets (floats)
#define OFF_OBJ      0
#define OFF_CENTER   16384
#define OFF_SS       40960
#define OFF_SRES     188416
#define OFF_PSIZE    630784
#define OFF_SEM      655360
#define OFF_CORN     802816
#define OFF_SLOG     999424
#define OFF_OPROB    1155072
#define OFF_SPROB    1163264

// ---------------- scratch (device globals; zero-init guaranteed) ----------------
__device__ __half g_X1a[(size_t)KP * NCOL];   // plane hi (rows 259..319 stay 0)
__device__ __half g_X1b[(size_t)KP * NCOL];   // plane lo
__device__ __half g_A1a[(size_t)CC * NCOL];
__device__ __half g_A1b[(size_t)CC * NCOL];
__device__ __half g_A2a[(size_t)CC * NCOL];
__device__ __half g_A2b[(size_t)CC * NCOL];
__device__ __half g_W1a[CC*KP], g_W1b[CC*KP];
__device__ __half g_W2a[CC*CC], g_W2b[CC*CC];
__device__ __half g_W3a[CC*CC], g_W3b[CC*CC];
__device__ float g_Y [CC * NP];
__device__ float g_Y2[CC * NP];
__device__ float g_Y3[CC * NP];
__device__ float g_NET[OUTC * NP];
__device__ float g_NX[NP * 3];
__device__ int   g_IDX[NP * SS];

// ---------------- asm helpers (base-target: sm_80+) ----------------
__device__ __forceinline__ uint32_t smem_u32(const void* p){
    uint32_t a;
    asm("{ .reg .u64 t; cvta.to.shared.u64 t, %1; cvt.u32.u64 %0, t; }" : "=r"(a) : "l"(p));
    return a;
}
#define CP16(dst, src)  asm volatile("cp.async.cg.shared.global [%0], [%1], 16;" :: "r"(dst), "l"(src))
#define CP_COMMIT()     asm volatile("cp.async.commit_group;" ::: "memory")
#define CP_WAIT1()      asm volatile("cp.async.wait_group 1;" ::: "memory")
#define CP_WAIT0()      asm volatile("cp.async.wait_group 0;" ::: "memory")

#define LDSM_X4(R, addr) \
    asm volatile("ldmatrix.sync.aligned.m8n8.x4.shared.b16 {%0,%1,%2,%3}, [%4];" \
        : "=r"((R)[0]),"=r"((R)[1]),"=r"((R)[2]),"=r"((R)[3]) : "r"(addr))
#define LDSM_X4T(R, addr) \
    asm volatile("ldmatrix.sync.aligned.m8n8.x4.trans.shared.b16 {%0,%1,%2,%3}, [%4];" \
        : "=r"((R)[0]),"=r"((R)[1]),"=r"((R)[2]),"=r"((R)[3]) : "r"(addr))

#define MMA_F16(C, A, b0, b1) \
    asm volatile("mma.sync.aligned.m16n8k16.row.col.f32.f16.f16.f32 " \
        "{%0,%1,%2,%3}, {%4,%5,%6,%7}, {%8,%9}, {%0,%1,%2,%3};" \
        : "+f"((C)[0]),"+f"((C)[1]),"+f"((C)[2]),"+f"((C)[3]) \
        : "r"((A)[0]),"r"((A)[1]),"r"((A)[2]),"r"((A)[3]), "r"(b0),"r"(b1))

// ---------------- misc helpers ----------------
__device__ __forceinline__ float d2_nofma(float ax,float ay,float az,float bx,float by,float bz){
    float dx=ax-bx, dy=ay-by, dz=az-bz;
    return __fadd_rn(__fadd_rn(__fmul_rn(dx,dx),__fmul_rn(dy,dy)),__fmul_rn(dz,dz));
}
__device__ __forceinline__ void split2(float v, __half& h, __half& l){
    h = __float2half(v);
    l = __float2half(v - __half2float(h));
}

// ---------------- FPS: one block per batch ----------------
__global__ __launch_bounds__(1024) void fps_kernel(const float* __restrict__ xyz)
{
    __shared__ float sx[KK], sy[KK], sz[KK];
    __shared__ float rv[32]; __shared__ int ri[32]; __shared__ int sfar;
    const int b = blockIdx.x, tid = threadIdx.x;
    const float* xb = xyz + (size_t)b*KK*3;
    for (int i=tid;i<KK;i+=1024){ sx[i]=xb[i*3+0]; sy[i]=xb[i*3+1]; sz[i]=xb[i*3+2]; }
    __syncthreads();
    const int i0 = tid, i1 = tid + 1024;
    float d0 = 1e10f, d1 = 1e10f;
    int far = 0;
    const float x0=sx[i0], y0=sy[i0], z0=sz[i0];
    const float x1=sx[i1], y1=sy[i1], z1=sz[i1];
    for (int it=0; it<PP; ++it){
        if (tid==0){
            g_NX[(b*PP+it)*3+0]=sx[far];
            g_NX[(b*PP+it)*3+1]=sy[far];
            g_NX[(b*PP+it)*3+2]=sz[far];
        }
        const float cx=sx[far], cy=sy[far], cz=sz[far];
        d0 = fminf(d0, d2_nofma(x0,y0,z0,cx,cy,cz));
        d1 = fminf(d1, d2_nofma(x1,y1,z1,cx,cy,cz));
        float bv = d0; int bi = i0;
        if (d1 > bv){ bv=d1; bi=i1; }
        #pragma unroll
        for (int off=16; off; off>>=1){
            float ov=__shfl_down_sync(0xffffffffu,bv,off);
            int   oi=__shfl_down_sync(0xffffffffu,bi,off);
            if (ov>bv || (ov==bv && oi<bi)){ bv=ov; bi=oi; }
        }
        const int w = tid>>5, lane = tid&31;
        if (lane==0){ rv[w]=bv; ri[w]=bi; }
        __syncthreads();
        if (w==0){
            bv = rv[lane]; bi = ri[lane];
            #pragma unroll
            for (int off=16; off; off>>=1){
                float ov=__shfl_down_sync(0xffffffffu,bv,off);
                int   oi=__shfl_down_sync(0xffffffffu,bi,off);
                if (ov>bv || (ov==bv && oi<bi)){ bv=ov; bi=oi; }
            }
            if (lane==0) sfar = bi;
        }
        __syncthreads();
        far = sfar;
    }
}

// ---------------- ball query ----------------
__global__ __launch_bounds__(256) void ballq_kernel(const float* __restrict__ xyz)
{
    __shared__ float sx[KK], sy[KK], sz[KK];
    const int b = blockIdx.x >> 5;
    const float* xb = xyz + (size_t)b*KK*3;
    for (int i=threadIdx.x;i<KK;i+=256){ sx[i]=xb[i*3+0]; sy[i]=xb[i*3+1]; sz[i]=xb[i*3+2]; }
    __syncthreads();
    const int warp = threadIdx.x>>5, lane = threadIdx.x&31;
    const int w = blockIdx.x*8 + warp;
    const float cx=g_NX[w*3+0], cy=g_NX[w*3+1], cz=g_NX[w*3+2];
    int cnt=0, firstIdx=0; bool haveFirst=false;
    for (int j=0;j<KK;j+=32){
        const int i = j + lane;
        const float dd = d2_nofma(sx[i],sy[i],sz[i],cx,cy,cz);
        const bool within = dd < 0.09f;
        const unsigned mask = __ballot_sync(0xffffffffu, within);
        if (mask){
            if (!haveFirst){ firstIdx = j + __ffs(mask) - 1; haveFirst=true; }
            const int rank = __popc(mask & ((1u<<lane)-1u));
            if (within && (cnt+rank) < SS) g_IDX[w*SS + cnt + rank] = i;
            cnt += __popc(mask);
            if (cnt >= SS) break;
        }
    }
    if (cnt < SS && lane >= cnt && lane < SS) g_IDX[w*SS + lane] = firstIdx;
}

// ---------------- weight prep: fp32 -> 2 fp16 planes (with K pad) ----------------
__global__ void prep_split(const float* __restrict__ src,
                           __half* __restrict__ da, __half* __restrict__ db,
                           int M, int Ksrc, int Kdst)
{
    int t = blockIdx.x*256 + threadIdx.x;
    if (t < M*Kdst){
        int m = t / Kdst, k = t % Kdst;
        float v = (k < Ksrc) ? src[m*Ksrc + k] : 0.0f;
        __half h,l; split2(v,h,l);
        da[t]=h; db[t]=l;
    }
}

// ---------------- gather xyz channels into X1 rows 0..2 ----------------
__global__ void gatherx_kernel(const float* __restrict__ xyz)
{
    int t = blockIdx.x*256 + threadIdx.x;
    int b = t >> 12;
    int p = (t >> 4) & 255;
    int i = g_IDX[t];
    const float* xb = xyz + (size_t)b*KK*3 + (size_t)i*3;
    const float* nc = g_NX + (b*PP + p)*3;
    #pragma unroll
    for (int r=0;r<3;r++){
        float v = (xb[r]-nc[r]) / 0.3f;
        __half h,l; split2(v,h,l);
        g_X1a[(size_t)r*NCOL + t]=h; g_X1b[(size_t)r*NCOL + t]=l;
    }
}

// ---------------- gather features into X1 rows 3..258 ----------------
__global__ __launch_bounds__(256) void gatherf_kernel(const float* __restrict__ features)
{
    __shared__ float row[KK];
    const int c = blockIdx.x, b = blockIdx.y;
    const float* src = features + ((size_t)b*CC + c)*KK;
    for (int i=threadIdx.x;i<KK;i+=256) row[i]=src[i];
    __syncthreads();
    const size_t base = (size_t)(3+c)*NCOL + b*(PP*SS);
    const int* ib = g_IDX + b*(PP*SS);
    #pragma unroll
    for (int it=0; it<16; ++it){
        int cl = it*256 + threadIdx.x;
        float v = row[ib[cl]];
        __half h,l; split2(v,h,l);
        g_X1a[base+cl]=h; g_X1b[base+cl]=l;
    }
}

// ---------------- mma.sync fp16 GEMM (2-plane split, 3 products) ----------------
// C[256][NCOL] = relu(BN(W @ X)); CTA tile 256x64, 8 warps of 64x32, BK=32.
// Layer 3 fuses the 16-sample maxpool and writes g_Y directly.
#define A_PL 20480u            // 256 rows * 80B (32 fp16 + 8 pad)
#define A_BUFS (2u*A_PL)       // 40960
#define B_PL 4608u             // 32 rows * 144B (64 fp16 + 8 pad)
#define B_BUFS (2u*B_PL)       // 9216
#define BUFSZ (A_BUFS + B_BUFS)// 50176
#define SMT (2*BUFSZ)          // 100352

__global__ __launch_bounds__(256, 2) void mma_gemm_kernel(
    const __half* __restrict__ Aa, const __half* __restrict__ Ab, int Kw, int nch,
    const __half* __restrict__ Ba, const __half* __restrict__ Bb,
    __half* __restrict__ Oa, __half* __restrict__ Ob,      // non-null: fp16 split output
    float* __restrict__ Ymax,                               // non-null: fused maxpool output
    const float* __restrict__ gamma, const float* __restrict__ beta,
    const float* __restrict__ mean,  const float* __restrict__ var)
{
    extern __shared__ char smem[];
    const uint32_t sbase = smem_u32(smem);
    const int tid = threadIdx.x, lane = tid & 31, wid = tid >> 5;
    const int wm = wid & 3, wn = wid >> 2;
    const int n0 = blockIdx.x * 64;

    auto stage = [&](int c, int buf){
        const int k0 = c * 32;
        const uint32_t sA = sbase + buf*BUFSZ;
        const uint32_t sB = sA + A_BUFS;
        #pragma unroll
        for (int it=0; it<4; ++it){
            const int idx = it*256 + tid;          // 1024
            const int m = idx >> 2, kg = (idx & 3) * 8;
            const uint32_t d = sA + (uint32_t)m*80u + (uint32_t)kg*2u;
            const size_t so = (size_t)m*Kw + k0 + kg;
            CP16(d,        Aa + so);
            CP16(d + A_PL, Ab + so);
        }
        {
            const int k = tid >> 3, ng = (tid & 7) * 8;
            const uint32_t d = sB + (uint32_t)k*144u + (uint32_t)ng*2u;
            const size_t so = (size_t)(k0+k)*NCOL + n0 + ng;
            CP16(d,        Ba + so);
            CP16(d + B_PL, Bb + so);
        }
    };

    float acc[4][4][4] = {};

    const uint32_t aRow = (uint32_t)((wm*64 + (lane & 15)) * 80) + (uint32_t)(((lane >> 4) << 3) * 2);
    const uint32_t bRow = (uint32_t)(((((lane >> 3) & 1) << 3) + (lane & 7)) * 144)
                        + (uint32_t)((wn*32 + ((lane >> 4) << 3)) * 2);

    auto compute_chunk = [&](int buf){
        const uint32_t aB = sbase + buf*BUFSZ;
        const uint32_t bB = aB + A_BUFS;
        #pragma unroll
        for (int ks=0; ks<2; ++ks){
            uint32_t bfr[2][2][4];
            #pragma unroll
            for (int p=0; p<2; ++p)
                #pragma unroll
                for (int n2=0; n2<2; ++n2)
                    LDSM_X4T(bfr[p][n2], bB + p*B_PL + bRow + (uint32_t)(ks*16*144) + (uint32_t)(n2*32));
            #pragma unroll
            for (int mh=0; mh<2; ++mh){
                uint32_t afr[2][2][4];
                #pragma unroll
                for (int p=0; p<2; ++p)
                    #pragma unroll
                    for (int m2=0; m2<2; ++m2)
                        LDSM_X4(afr[p][m2], aB + p*A_PL + aRow + (uint32_t)((mh*2+m2)*16*80) + (uint32_t)(ks*32));
                #pragma unroll
                for (int m2=0; m2<2; ++m2){
                    const int mi = mh*2 + m2;
                    #pragma unroll
                    for (int ni=0; ni<4; ++ni){
                        const int n2 = ni >> 1, q = (ni & 1) * 2;
                        float* C = acc[mi][ni];
                        MMA_F16(C, afr[0][m2], bfr[0][n2][q], bfr[0][n2][q+1]); // h*h
                        MMA_F16(C, afr[0][m2], bfr[1][n2][q], bfr[1][n2][q+1]); // h*l
                        MMA_F16(C, afr[1][m2], bfr[0][n2][q], bfr[0][n2][q+1]); // l*h
                    }
                }
            }
        }
    };

    stage(0, 0);
    CP_COMMIT();
    for (int c=0; c<nch; ++c){
        if (c+1 < nch){ stage(c+1, (c+1)&1); CP_COMMIT(); CP_WAIT1(); }
        else          { CP_WAIT0(); }
        __syncthreads();
        compute_chunk(c & 1);
        __syncthreads();
    }

    // ---- epilogue: BN + ReLU, then either fp16-split store or fused maxpool ----
    #pragma unroll
    for (int mi=0; mi<4; ++mi){
        const int mlo = wm*64 + mi*16 + (lane >> 2);
        const int mhi = mlo + 8;
        const float s0 = gamma[mlo] * rsqrtf(var[mlo] + 1e-5f);
        const float h0 = beta[mlo] - mean[mlo]*s0;
        const float s1 = gamma[mhi] * rsqrtf(var[mhi] + 1e-5f);
        const float h1 = beta[mhi] - mean[mhi]*s1;
        float vlo[4][2], vhi[4][2];
        #pragma unroll
        for (int ni=0; ni<4; ++ni){
            vlo[ni][0] = fmaxf(acc[mi][ni][0]*s0 + h0, 0.f);
            vlo[ni][1] = fmaxf(acc[mi][ni][1]*s0 + h0, 0.f);
            vhi[ni][0] = fmaxf(acc[mi][ni][2]*s1 + h1, 0.f);
            vhi[ni][1] = fmaxf(acc[mi][ni][3]*s1 + h1, 0.f);
        }
        if (Ymax){
            // fused 16-col maxpool: group g covers ni 2g, 2g+1 (16 cols)
            #pragma unroll
            for (int g=0; g<2; ++g){
                float pl = fmaxf(fmaxf(vlo[2*g][0],vlo[2*g][1]), fmaxf(vlo[2*g+1][0],vlo[2*g+1][1]));
                float ph = fmaxf(fmaxf(vhi[2*g][0],vhi[2*g][1]), fmaxf(vhi[2*g+1][0],vhi[2*g+1][1]));
                #pragma unroll
                for (int off=1; off<4; off<<=1){
                    pl = fmaxf(pl, __shfl_xor_sync(0xffffffffu, pl, off));
                    ph = fmaxf(ph, __shfl_xor_sync(0xffffffffu, ph, off));
                }
                if ((lane & 3) == 0){
                    const int p = (n0 >> 4) + wn*2 + g;
                    Ymax[(size_t)mlo*NP + p] = pl;
                    Ymax[(size_t)mhi*NP + p] = ph;
                }
            }
        } else {
            #pragma unroll
            for (int ni=0; ni<4; ++ni){
                const int n = n0 + wn*32 + ni*8 + (lane & 3)*2;
                const size_t ilo = (size_t)mlo*NCOL + n, ihi = (size_t)mhi*NCOL + n;
                __half ha0,la0, ha1,la1, hb0,lb0, hb1,lb1;
                split2(vlo[ni][0], ha0, la0); split2(vlo[ni][1], ha1, la1);
                split2(vhi[ni][0], hb0, lb0); split2(vhi[ni][1], hb1, lb1);
                __half2 t;
                t.x=ha0; t.y=ha1; *reinterpret_cast<__half2*>(&Oa[ilo]) = t;
                t.x=la0; t.y=la1; *reinterpret_cast<__half2*>(&Ob[ilo]) = t;
                t.x=hb0; t.y=hb1; *reinterpret_cast<__half2*>(&Oa[ihi]) = t;
                t.x=lb0; t.y=lb1; *reinterpret_cast<__half2*>(&Ob[ihi]) = t;
            }
        }
    }
}

// ---------------- SIMT GEMM (proposal FCs) ----------------
#define BMt 64
#define BNt 64
#define BKt 16
__global__ __launch_bounds__(256) void gemm_kernel(
    const float* __restrict__ W, const float* __restrict__ X, float* __restrict__ Out,
    int M, int Kc, int N,
    const float* __restrict__ gamma, const float* __restrict__ beta,
    const float* __restrict__ mean,  const float* __restrict__ var,
    const float* __restrict__ bias, int do_relu)
{
    __shared__ float Ws[BKt][BMt+4];
    __shared__ float Xs[BKt][BNt+4];
    const int tid = threadIdx.x;
    const int tx = tid & 15, ty = tid >> 4;
    const int row0 = blockIdx.y*BMt, col0 = blockIdx.x*BNt;
    float acc[4][4] = {};
    const int wm = tid >> 2;
    const int wk = (tid & 3) * 4;
    const int xk = tid >> 4;
    const int xn = (tid & 15) * 4;

    for (int kt=0; kt<Kc; kt+=BKt){
        float4 wv = make_float4(0.f,0.f,0.f,0.f);
        const int gm = row0 + wm;
        if (gm < M) wv = *reinterpret_cast<const float4*>(&W[(size_t)gm*Kc + kt + wk]);
        Ws[wk+0][wm]=wv.x; Ws[wk+1][wm]=wv.y; Ws[wk+2][wm]=wv.z; Ws[wk+3][wm]=wv.w;
        float4 xv = *reinterpret_cast<const float4*>(&X[(size_t)(kt+xk)*N + col0 + xn]);
        *reinterpret_cast<float4*>(&Xs[xk][xn]) = xv;
        __syncthreads();
        #pragma unroll
        for (int k=0;k<BKt;k++){
            float a0=Ws[k][ty*4+0], a1=Ws[k][ty*4+1], a2=Ws[k][ty*4+2], a3=Ws[k][ty*4+3];
            float b0=Xs[k][tx*4+0], b1=Xs[k][tx*4+1], b2=Xs[k][tx*4+2], b3=Xs[k][tx*4+3];
            acc[0][0]+=a0*b0; acc[0][1]+=a0*b1; acc[0][2]+=a0*b2; acc[0][3]+=a0*b3;
            acc[1][0]+=a1*b0; acc[1][1]+=a1*b1; acc[1][2]+=a1*b2; acc[1][3]+=a1*b3;
            acc[2][0]+=a2*b0; acc[2][1]+=a2*b1; acc[2][2]+=a2*b2; acc[2][3]+=a2*b3;
            acc[3][0]+=a3*b0; acc[3][1]+=a3*b1; acc[3][2]+=a3*b2; acc[3][3]+=a3*b3;
        }
        __syncthreads();
    }
    #pragma unroll
    for (int i=0;i<4;i++){
        const int m = row0 + ty*4 + i;
        if (m >= M) continue;
        float s = 1.f, sh = 0.f;
        if (gamma){
            const float sc = gamma[m] * rsqrtf(var[m] + 1e-5f);
            s = sc; sh = beta[m] - mean[m]*sc;
        } else if (bias){
            sh = bias[m];
        }
        float4 o;
        o.x = acc[i][0]*s + sh; o.y = acc[i][1]*s + sh;
        o.z = acc[i][2]*s + sh; o.w = acc[i][3]*s + sh;
        if (do_relu){
            o.x=fmaxf(o.x,0.f); o.y=fmaxf(o.y,0.f); o.z=fmaxf(o.z,0.f); o.w=fmaxf(o.w,0.f);
        }
        *reinterpret_cast<float4*>(&Out[(size_t)m*N + col0 + tx*4]) = o;
    }
}

// ---------------- head ----------------
__global__ __launch_bounds__(256) void head_kernel(const float* __restrict__ msa,
                                                   float* __restrict__ out)
{
    const int t = blockIdx.x*256 + threadIdx.x;
    #define NT(j) g_NET[(j)*NP + t]
    const float obj0 = NT(0), obj1 = NT(1);
    out[OFF_OBJ + t*2 + 0] = obj0;
    out[OFF_OBJ + t*2 + 1] = obj1;
    const float c0 = g_NX[t*3+0] + NT(2);
    const float c1 = g_NX[t*3+1] + NT(3);
    const float c2 = g_NX[t*3+2] + NT(4);
    out[OFF_CENTER + t*3 + 0] = c0;
    out[OFF_CENTER + t*3 + 1] = c1;
    out[OFF_CENTER + t*3 + 2] = c2;

    float ss[18];
    #pragma unroll
    for (int k=0;k<18;k++){ ss[k] = NT(29+k); out[OFF_SS + t*18 + k] = ss[k]; }
    int best = 0; float bv = ss[0];
    #pragma unroll
    for (int k=1;k<18;k++) if (ss[k] > bv){ bv = ss[k]; best = k; }

    float ps0=0.f, ps1=0.f, ps2=0.f;
    #pragma unroll
    for (int k=0;k<18;k++){
        const float m0=msa[k*3+0], m1=msa[k*3+1], m2=msa[k*3+2];
        const float r0 = NT(47+k*3+0)*m0;
        const float r1 = NT(47+k*3+1)*m1;
        const float r2 = NT(47+k*3+2)*m2;
        out[OFF_SRES + t*54 + k*3 + 0] = r0;
        out[OFF_SRES + t*54 + k*3 + 1] = r1;
        out[OFF_SRES + t*54 + k*3 + 2] = r2;
        if (k == best){ ps0 = r0+m0; ps1 = r1+m1; ps2 = r2+m2; }
    }
    out[OFF_PSIZE + t*3 + 0] = ps0;
    out[OFF_PSIZE + t*3 + 1] = ps1;
    out[OFF_PSIZE + t*3 + 2] = ps2;

    float sm[18];
    #pragma unroll
    for (int k=0;k<18;k++){ sm[k] = NT(101+k); out[OFF_SEM + t*18 + k] = sm[k]; }

    const float cc0 = c0, cc1 = c2, cc2 = -c1;
    const float hx = ps0*0.5f, hy = ps2*0.5f, hz = ps1*0.5f;
    const float SX[8]={1,1,-1,-1,1,1,-1,-1};
    const float SY[8]={1,1,1,1,-1,-1,-1,-1};
    const float SZ[8]={1,-1,-1,1,1,-1,-1,1};
    #pragma unroll
    for (int i=0;i<8;i++){
        out[OFF_CORN + t*24 + i*3 + 0] = cc0 + hx*SX[i];
        out[OFF_CORN + t*24 + i*3 + 1] = cc1 + hy*SY[i];
        out[OFF_CORN + t*24 + i*3 + 2] = cc2 + hz*SZ[i];
    }

    #pragma unroll
    for (int k=0;k<18;k++) out[OFF_SLOG + t*19 + k] = sm[k];
    out[OFF_SLOG + t*19 + 18] = (obj0 <= obj1) ? 0.0f : 1e10f;

    {
        const float mx = fmaxf(obj0,obj1);
        const float e0 = expf(obj0-mx), e1 = expf(obj1-mx);
        out[OFF_OPROB + t] = e1/(e0+e1);
    }
    {
        float mx = sm[0];
        #pragma unroll
        for (int k=1;k<18;k++) mx = fmaxf(mx, sm[k]);
        float e[18], ssum = 0.f;
        #pragma unroll
        for (int k=0;k<18;k++){ e[k] = expf(sm[k]-mx); ssum += e[k]; }
        #pragma unroll
        for (int k=0;k<18;k++) out[OFF_SPROB + t*18 + k] = e[k]/ssum;
    }
    #undef NT
}

// ---------------- host launcher ----------------
extern "C" void kernel_launch(void* const* d_in, const int* in_sizes, int n_in,
                              void* d_out, int out_size)
{
    const float* xyz      = (const float*)d_in[0];
    const float* features = (const float*)d_in[1];
    const float* sa_w1    = (const float*)d_in[2];
    const float* sa_w2    = (const float*)d_in[3];
    const float* sa_w3    = (const float*)d_in[4];
    const float* sa_gamma = (const float*)d_in[5];
    const float* sa_beta  = (const float*)d_in[6];
    const float* sa_mean  = (const float*)d_in[7];
    const float* sa_var   = (const float*)d_in[8];
    const float* p_w1     = (const float*)d_in[9];
    const float* p_w2     = (const float*)d_in[10];
    const float* p_w3     = (const float*)d_in[11];
    const float* p_b3     = (const float*)d_in[12];
    const float* p_gamma  = (const float*)d_in[13];
    const float* p_beta   = (const float*)d_in[14];
    const float* p_mean   = (const float*)d_in[15];
    const float* p_var    = (const float*)d_in[16];
    const float* msa      = (const float*)d_in[17];
    float* out = (float*)d_out;

    cudaFuncSetAttribute(mma_gemm_kernel, cudaFuncAttributeMaxDynamicSharedMemorySize, SMT);

    void *pX1a,*pX1b, *pA1a,*pA1b, *pA2a,*pA2b;
    void *pW1a,*pW1b, *pW2a,*pW2b, *pW3a,*pW3b;
    void *pY, *pY2, *pY3, *pNET;
    cudaGetSymbolAddress(&pX1a, g_X1a); cudaGetSymbolAddress(&pX1b, g_X1b);
    cudaGetSymbolAddress(&pA1a, g_A1a); cudaGetSymbolAddress(&pA1b, g_A1b);
    cudaGetSymbolAddress(&pA2a, g_A2a); cudaGetSymbolAddress(&pA2b, g_A2b);
    cudaGetSymbolAddress(&pW1a, g_W1a); cudaGetSymbolAddress(&pW1b, g_W1b);
    cudaGetSymbolAddress(&pW2a, g_W2a); cudaGetSymbolAddress(&pW2b, g_W2b);
    cudaGetSymbolAddress(&pW3a, g_W3a); cudaGetSymbolAddress(&pW3b, g_W3b);
    cudaGetSymbolAddress(&pY,  g_Y);
    cudaGetSymbolAddress(&pY2, g_Y2);
    cudaGetSymbolAddress(&pY3, g_Y3);
    cudaGetSymbolAddress(&pNET, g_NET);

    fps_kernel<<<BB, 1024>>>(xyz);
    ballq_kernel<<<1024, 256>>>(xyz);
    prep_split<<<(CC*KP + 255)/256, 256>>>(sa_w1, (__half*)pW1a, (__half*)pW1b, CC, 259, KP);
    prep_split<<<(CC*CC + 255)/256, 256>>>(sa_w2, (__half*)pW2a, (__half*)pW2b, CC, CC, CC);
    prep_split<<<(CC*CC + 255)/256, 256>>>(sa_w3, (__half*)pW3a, (__half*)pW3b, CC, CC, CC);
    gatherx_kernel<<<NCOL/256, 256>>>(xyz);
    gatherf_kernel<<<dim3(CC, BB), 256>>>(features);

    const dim3 gg(NCOL/64);
    // layer 1: K=320 (10 chunks)
    mma_gemm_kernel<<<gg, 256, SMT>>>(
        (const __half*)pW1a, (const __half*)pW1b, KP, KP/32,
        (const __half*)pX1a, (const __half*)pX1b,
        (__half*)pA1a, (__half*)pA1b, nullptr,
        sa_gamma+0, sa_beta+0, sa_mean+0, sa_var+0);
    // layer 2
    mma_gemm_kernel<<<gg, 256, SMT>>>(
        (const __half*)pW2a, (const __half*)pW2b, CC, CC/32,
        (const __half*)pA1a, (const __half*)pA1b,
        (__half*)pA2a, (__half*)pA2b, nullptr,
        sa_gamma+256, sa_beta+256, sa_mean+256, sa_var+256);
    // layer 3 -> fused maxpool into g_Y
    mma_gemm_kernel<<<gg, 256, SMT>>>(
        (const __half*)pW3a, (const __half*)pW3b, CC, CC/32,
        (const __half*)pA2a, (const __half*)pA2b,
        nullptr, nullptr, (float*)pY,
        sa_gamma+512, sa_beta+512, sa_mean+512, sa_var+512);

    gemm_kernel<<<dim3(NP/BNt, CC/BMt), 256>>>(p_w1, (const float*)pY, (float*)pY2,
        CC, CC, NP, p_gamma+0, p_beta+0, p_mean+0, p_var+0, nullptr, 1);
    gemm_kernel<<<dim3(NP/BNt, CC/BMt), 256>>>(p_w2, (const float*)pY2, (float*)pY3,
        CC, CC, NP, p_gamma+256, p_beta+256, p_mean+256, p_var+256, nullptr, 1);
    gemm_kernel<<<dim3(NP/BNt, (OUTC+BMt-1)/BMt), 256>>>(p_w3, (const float*)pY3, (float*)pNET,
        OUTC, CC, NP, nullptr, nullptr, nullptr, nullptr, p_b3, 0);

    head_kernel<<<NP/256, 256>>>(msa, out);
}

// round 5
// speedup vs baseline: 1.7056x; 1.7056x over previous
#include <cuda_runtime.h>
#include <cuda_fp16.h>
#include <math.h>
#include <cstdint>

// ---------------- problem constants ----------------
#define BB 32
#define KK 2048
#define CC 256
#define PP 256
#define SS 16
#define NCOL (BB*PP*SS)      // 131072
#define NP   (BB*PP)         // 8192
#define KP   320             // 259 padded to mult of 32
#define OUTC 119

// output section offsets (floats)
#define OFF_OBJ      0
#define OFF_CENTER   16384
#define OFF_SS       40960
#define OFF_SRES     188416
#define OFF_PSIZE    630784
#define OFF_SEM      655360
#define OFF_CORN     802816
#define OFF_SLOG     999424
#define OFF_OPROB    1155072
#define OFF_SPROB    1163264

// ---------------- scratch (device globals; zero-init guaranteed) ----------------
__device__ __half g_X1a[(size_t)KP * NCOL];   // plane hi (rows 259..319 stay 0)
__device__ __half g_X1b[(size_t)KP * NCOL];   // plane lo
__device__ __half g_A1a[(size_t)CC * NCOL];
__device__ __half g_A1b[(size_t)CC * NCOL];
__device__ __half g_A2a[(size_t)CC * NCOL];
__device__ __half g_A2b[(size_t)CC * NCOL];
__device__ __half g_W1a[CC*KP], g_W1b[CC*KP];
__device__ __half g_W2a[CC*CC], g_W2b[CC*CC];
__device__ __half g_W3a[CC*CC], g_W3b[CC*CC];
__device__ float g_Y [CC * NP];
__device__ float g_Y2[CC * NP];
__device__ float g_Y3[CC * NP];
__device__ float g_NET[OUTC * NP];
__device__ float g_NX[NP * 3];
__device__ int   g_IDX[NP * SS];

// ---------------- asm helpers (base-target: sm_80+) ----------------
__device__ __forceinline__ uint32_t smem_u32(const void* p){
    uint32_t a;
    asm("{ .reg .u64 t; cvta.to.shared.u64 t, %1; cvt.u32.u64 %0, t; }" : "=r"(a) : "l"(p));
    return a;
}
#define CP16(dst, src)  asm volatile("cp.async.cg.shared.global [%0], [%1], 16;" :: "r"(dst), "l"(src))
#define CP_COMMIT()     asm volatile("cp.async.commit_group;" ::: "memory")
#define CP_WAIT1()      asm volatile("cp.async.wait_group 1;" ::: "memory")
#define CP_WAIT0()      asm volatile("cp.async.wait_group 0;" ::: "memory")

#define LDSM_X4(R, addr) \
    asm volatile("ldmatrix.sync.aligned.m8n8.x4.shared.b16 {%0,%1,%2,%3}, [%4];" \
        : "=r"((R)[0]),"=r"((R)[1]),"=r"((R)[2]),"=r"((R)[3]) : "r"(addr))
#define LDSM_X4T(R, addr) \
    asm volatile("ldmatrix.sync.aligned.m8n8.x4.trans.shared.b16 {%0,%1,%2,%3}, [%4];" \
        : "=r"((R)[0]),"=r"((R)[1]),"=r"((R)[2]),"=r"((R)[3]) : "r"(addr))

#define MMA_F16(C, A, b0, b1) \
    asm volatile("mma.sync.aligned.m16n8k16.row.col.f32.f16.f16.f32 " \
        "{%0,%1,%2,%3}, {%4,%5,%6,%7}, {%8,%9}, {%0,%1,%2,%3};" \
        : "+f"((C)[0]),"+f"((C)[1]),"+f"((C)[2]),"+f"((C)[3]) \
        : "r"((A)[0]),"r"((A)[1]),"r"((A)[2]),"r"((A)[3]), "r"(b0),"r"(b1))

// ---------------- misc helpers ----------------
__device__ __forceinline__ float d2_nofma(float ax,float ay,float az,float bx,float by,float bz){
    float dx=ax-bx, dy=ay-by, dz=az-bz;
    return __fadd_rn(__fadd_rn(__fmul_rn(dx,dx),__fmul_rn(dy,dy)),__fmul_rn(dz,dz));
}
__device__ __forceinline__ void split2(float v, __half& h, __half& l){
    h = __float2half(v);
    l = __float2half(v - __half2float(h));
}

// ---------------- FPS: one block per batch ----------------
__global__ __launch_bounds__(1024) void fps_kernel(const float* __restrict__ xyz)
{
    __shared__ float sx[KK], sy[KK], sz[KK];
    __shared__ float rv[32]; __shared__ int ri[32]; __shared__ int sfar;
    const int b = blockIdx.x, tid = threadIdx.x;
    const float* xb = xyz + (size_t)b*KK*3;
    for (int i=tid;i<KK;i+=1024){ sx[i]=xb[i*3+0]; sy[i]=xb[i*3+1]; sz[i]=xb[i*3+2]; }
    __syncthreads();
    const int i0 = tid, i1 = tid + 1024;
    float d0 = 1e10f, d1 = 1e10f;
    int far = 0;
    const float x0=sx[i0], y0=sy[i0], z0=sz[i0];
    const float x1=sx[i1], y1=sy[i1], z1=sz[i1];
    for (int it=0; it<PP; ++it){
        if (tid==0){
            g_NX[(b*PP+it)*3+0]=sx[far];
            g_NX[(b*PP+it)*3+1]=sy[far];
            g_NX[(b*PP+it)*3+2]=sz[far];
        }
        const float cx=sx[far], cy=sy[far], cz=sz[far];
        d0 = fminf(d0, d2_nofma(x0,y0,z0,cx,cy,cz));
        d1 = fminf(d1, d2_nofma(x1,y1,z1,cx,cy,cz));
        float bv = d0; int bi = i0;
        if (d1 > bv){ bv=d1; bi=i1; }
        #pragma unroll
        for (int off=16; off; off>>=1){
            float ov=__shfl_down_sync(0xffffffffu,bv,off);
            int   oi=__shfl_down_sync(0xffffffffu,bi,off);
            if (ov>bv || (ov==bv && oi<bi)){ bv=ov; bi=oi; }
        }
        const int w = tid>>5, lane = tid&31;
        if (lane==0){ rv[w]=bv; ri[w]=bi; }
        __syncthreads();
        if (w==0){
            bv = rv[lane]; bi = ri[lane];
            #pragma unroll
            for (int off=16; off; off>>=1){
                float ov=__shfl_down_sync(0xffffffffu,bv,off);
                int   oi=__shfl_down_sync(0xffffffffu,bi,off);
                if (ov>bv || (ov==bv && oi<bi)){ bv=ov; bi=oi; }
            }
            if (lane==0) sfar = bi;
        }
        __syncthreads();
        far = sfar;
    }
}

// ---------------- ball query ----------------
__global__ __launch_bounds__(256) void ballq_kernel(const float* __restrict__ xyz)
{
    __shared__ float sx[KK], sy[KK], sz[KK];
    const int b = blockIdx.x >> 5;
    const float* xb = xyz + (size_t)b*KK*3;
    for (int i=threadIdx.x;i<KK;i+=256){ sx[i]=xb[i*3+0]; sy[i]=xb[i*3+1]; sz[i]=xb[i*3+2]; }
    __syncthreads();
    const int warp = threadIdx.x>>5, lane = threadIdx.x&31;
    const int w = blockIdx.x*8 + warp;
    const float cx=g_NX[w*3+0], cy=g_NX[w*3+1], cz=g_NX[w*3+2];
    int cnt=0, firstIdx=0; bool haveFirst=false;
    for (int j=0;j<KK;j+=32){
        const int i = j + lane;
        const float dd = d2_nofma(sx[i],sy[i],sz[i],cx,cy,cz);
        const bool within = dd < 0.09f;
        const unsigned mask = __ballot_sync(0xffffffffu, within);
        if (mask){
            if (!haveFirst){ firstIdx = j + __ffs(mask) - 1; haveFirst=true; }
            const int rank = __popc(mask & ((1u<<lane)-1u));
            if (within && (cnt+rank) < SS) g_IDX[w*SS + cnt + rank] = i;
            cnt += __popc(mask);
            if (cnt >= SS) break;
        }
    }
    if (cnt < SS && lane >= cnt && lane < SS) g_IDX[w*SS + lane] = firstIdx;
}

// ---------------- weight prep: fp32 -> 2 fp16 planes (with K pad) ----------------
__global__ void prep_split(const float* __restrict__ src,
                           __half* __restrict__ da, __half* __restrict__ db,
                           int M, int Ksrc, int Kdst)
{
    int t = blockIdx.x*256 + threadIdx.x;
    if (t < M*Kdst){
        int m = t / Kdst, k = t % Kdst;
        float v = (k < Ksrc) ? src[m*Ksrc + k] : 0.0f;
        __half h,l; split2(v,h,l);
        da[t]=h; db[t]=l;
    }
}

// ---------------- gather xyz channels into X1 rows 0..2 ----------------
__global__ void gatherx_kernel(const float* __restrict__ xyz)
{
    int t = blockIdx.x*256 + threadIdx.x;
    int b = t >> 12;
    int p = (t >> 4) & 255;
    int i = g_IDX[t];
    const float* xb = xyz + (size_t)b*KK*3 + (size_t)i*3;
    const float* nc = g_NX + (b*PP + p)*3;
    #pragma unroll
    for (int r=0;r<3;r++){
        float v = (xb[r]-nc[r]) / 0.3f;
        __half h,l; split2(v,h,l);
        g_X1a[(size_t)r*NCOL + t]=h; g_X1b[(size_t)r*NCOL + t]=l;
    }
}

// ---------------- gather features into X1 rows 3..258 ----------------
__global__ __launch_bounds__(256) void gatherf_kernel(const float* __restrict__ features)
{
    __shared__ float row[KK];
    const int c = blockIdx.x, b = blockIdx.y;
    const float* src = features + ((size_t)b*CC + c)*KK;
    for (int i=threadIdx.x;i<KK;i+=256) row[i]=src[i];
    __syncthreads();
    const size_t base = (size_t)(3+c)*NCOL + b*(PP*SS);
    const int* ib = g_IDX + b*(PP*SS);
    #pragma unroll
    for (int it=0; it<16; ++it){
        int cl = it*256 + threadIdx.x;
        float v = row[ib[cl]];
        __half h,l; split2(v,h,l);
        g_X1a[base+cl]=h; g_X1b[base+cl]=l;
    }
}

// ---------------- mma.sync fp16 GEMM (2-plane split, 3 products) ----------------
// C[256][NCOL] = relu(BN(W @ X)); CTA tile 128x128 (grid.y=2 over M), 8 warps of 64x32, BK=32.
// Layer 3 fuses the 16-sample maxpool and writes g_Y directly.
#define A_PL 10240u            // 128 rows * 80B (32 fp16 + 8 pad)
#define A_BUFS (2u*A_PL)       // 20480
#define B_PL 8704u             // 32 rows * 272B (128 fp16 + 8 pad)
#define B_BUFS (2u*B_PL)       // 17408
#define BUFSZ (A_BUFS + B_BUFS)// 37888
#define SMT (2*BUFSZ)          // 75776

__global__ __launch_bounds__(256) void mma_gemm_kernel(
    const __half* __restrict__ Aa, const __half* __restrict__ Ab, int Kw, int nch,
    const __half* __restrict__ Ba, const __half* __restrict__ Bb,
    __half* __restrict__ Oa, __half* __restrict__ Ob,      // non-null: fp16 split output
    float* __restrict__ Ymax,                               // non-null: fused maxpool output
    const float* __restrict__ gamma, const float* __restrict__ beta,
    const float* __restrict__ mean,  const float* __restrict__ var)
{
    extern __shared__ char smem[];
    const uint32_t sbase = smem_u32(smem);
    const int tid = threadIdx.x, lane = tid & 31, wid = tid >> 5;
    const int wm = wid & 1, wn = wid >> 1;
    const int n0 = blockIdx.x * 128;
    const int mbase = blockIdx.y * 128;

    const size_t aoff = (size_t)mbase * Kw;
    const __half* A0 = Aa + aoff;
    const __half* A1 = Ab + aoff;

    auto stage = [&](int c, int buf){
        const int k0 = c * 32;
        const uint32_t sA = sbase + buf*BUFSZ;
        const uint32_t sB = sA + A_BUFS;
        #pragma unroll
        for (int it=0; it<2; ++it){
            const int idx = it*256 + tid;          // 512
            const int m = idx >> 2, kg = (idx & 3) * 8;
            const uint32_t d = sA + (uint32_t)m*80u + (uint32_t)kg*2u;
            const size_t so = (size_t)m*Kw + k0 + kg;
            CP16(d,        A0 + so);
            CP16(d + A_PL, A1 + so);
        }
        #pragma unroll
        for (int it=0; it<2; ++it){
            const int idx = it*256 + tid;          // 512
            const int k = idx >> 4, ng = (idx & 15) * 8;
            const uint32_t d = sB + (uint32_t)k*272u + (uint32_t)ng*2u;
            const size_t so = (size_t)(k0+k)*NCOL + n0 + ng;
            CP16(d,        Ba + so);
            CP16(d + B_PL, Bb + so);
        }
    };

    float acc[4][4][4] = {};

    const uint32_t aRow = (uint32_t)((wm*64 + (lane & 15)) * 80) + (uint32_t)(((lane >> 4) << 3) * 2);
    const uint32_t bRow = (uint32_t)(((((lane >> 3) & 1) << 3) + (lane & 7)) * 272)
                        + (uint32_t)((wn*32 + ((lane >> 4) << 3)) * 2);

    auto compute_chunk = [&](int buf){
        const uint32_t aB = sbase + buf*BUFSZ;
        const uint32_t bB = aB + A_BUFS;
        #pragma unroll
        for (int ks=0; ks<2; ++ks){
            uint32_t bfr[2][2][4];
            #pragma unroll
            for (int p=0; p<2; ++p)
                #pragma unroll
                for (int n2=0; n2<2; ++n2)
                    LDSM_X4T(bfr[p][n2], bB + p*B_PL + bRow + (uint32_t)(ks*16*272) + (uint32_t)(n2*32));
            #pragma unroll
            for (int mh=0; mh<2; ++mh){
                uint32_t afr[2][2][4];
                #pragma unroll
                for (int p=0; p<2; ++p)
                    #pragma unroll
                    for (int m2=0; m2<2; ++m2)
                        LDSM_X4(afr[p][m2], aB + p*A_PL + aRow + (uint32_t)((mh*2+m2)*16*80) + (uint32_t)(ks*32));
                #pragma unroll
                for (int m2=0; m2<2; ++m2){
                    const int mi = mh*2 + m2;
                    #pragma unroll
                    for (int ni=0; ni<4; ++ni){
                        const int n2 = ni >> 1, q = (ni & 1) * 2;
                        float* C = acc[mi][ni];
                        MMA_F16(C, afr[0][m2], bfr[0][n2][q], bfr[0][n2][q+1]); // h*h
                        MMA_F16(C, afr[0][m2], bfr[1][n2][q], bfr[1][n2][q+1]); // h*l
                        MMA_F16(C, afr[1][m2], bfr[0][n2][q], bfr[0][n2][q+1]); // l*h
                    }
                }
            }
        }
    };

    stage(0, 0);
    CP_COMMIT();
    for (int c=0; c<nch; ++c){
        if (c+1 < nch){ stage(c+1, (c+1)&1); CP_COMMIT(); CP_WAIT1(); }
        else          { CP_WAIT0(); }
        __syncthreads();
        compute_chunk(c & 1);
        __syncthreads();
    }

    // ---- epilogue: BN + ReLU, then fp16-split store OR fused 16-col maxpool ----
    #pragma unroll
    for (int mi=0; mi<4; ++mi){
        const int mlo = mbase + wm*64 + mi*16 + (lane >> 2);
        const int mhi = mlo + 8;
        const float s0 = gamma[mlo] * rsqrtf(var[mlo] + 1e-5f);
        const float h0 = beta[mlo] - mean[mlo]*s0;
        const float s1 = gamma[mhi] * rsqrtf(var[mhi] + 1e-5f);
        const float h1 = beta[mhi] - mean[mhi]*s1;
        float vlo[4][2], vhi[4][2];
        #pragma unroll
        for (int ni=0; ni<4; ++ni){
            vlo[ni][0] = fmaxf(acc[mi][ni][0]*s0 + h0, 0.f);
            vlo[ni][1] = fmaxf(acc[mi][ni][1]*s0 + h0, 0.f);
            vhi[ni][0] = fmaxf(acc[mi][ni][2]*s1 + h1, 0.f);
            vhi[ni][1] = fmaxf(acc[mi][ni][3]*s1 + h1, 0.f);
        }
        if (Ymax){
            #pragma unroll
            for (int g=0; g<2; ++g){
                float pl = fmaxf(fmaxf(vlo[2*g][0],vlo[2*g][1]), fmaxf(vlo[2*g+1][0],vlo[2*g+1][1]));
                float ph = fmaxf(fmaxf(vhi[2*g][0],vhi[2*g][1]), fmaxf(vhi[2*g+1][0],vhi[2*g+1][1]));
                #pragma unroll
                for (int off=1; off<4; off<<=1){
                    pl = fmaxf(pl, __shfl_xor_sync(0xffffffffu, pl, off));
                    ph = fmaxf(ph, __shfl_xor_sync(0xffffffffu, ph, off));
                }
                if ((lane & 3) == 0){
                    const int p = (n0 >> 4) + wn*2 + g;
                    Ymax[(size_t)mlo*NP + p] = pl;
                    Ymax[(size_t)mhi*NP + p] = ph;
                }
            }
        } else {
            #pragma unroll
            for (int ni=0; ni<4; ++ni){
                const int n = n0 + wn*32 + ni*8 + (lane & 3)*2;
                const size_t ilo = (size_t)mlo*NCOL + n, ihi = (size_t)mhi*NCOL + n;
                __half ha0,la0, ha1,la1, hb0,lb0, hb1,lb1;
                split2(vlo[ni][0], ha0, la0); split2(vlo[ni][1], ha1, la1);
                split2(vhi[ni][0], hb0, lb0); split2(vhi[ni][1], hb1, lb1);
                __half2 t;
                t.x=ha0; t.y=ha1; *reinterpret_cast<__half2*>(&Oa[ilo]) = t;
                t.x=la0; t.y=la1; *reinterpret_cast<__half2*>(&Ob[ilo]) = t;
                t.x=hb0; t.y=hb1; *reinterpret_cast<__half2*>(&Oa[ihi]) = t;
                t.x=lb0; t.y=lb1; *reinterpret_cast<__half2*>(&Ob[ihi]) = t;
            }
        }
    }
}

// ---------------- SIMT GEMM (proposal FCs) ----------------
#define BMt 64
#define BNt 64
#define BKt 16
__global__ __launch_bounds__(256) void gemm_kernel(
    const float* __restrict__ W, const float* __restrict__ X, float* __restrict__ Out,
    int M, int Kc, int N,
    const float* __restrict__ gamma, const float* __restrict__ beta,
    const float* __restrict__ mean,  const float* __restrict__ var,
    const float* __restrict__ bias, int do_relu)
{
    __shared__ float Ws[BKt][BMt+4];
    __shared__ float Xs[BKt][BNt+4];
    const int tid = threadIdx.x;
    const int tx = tid & 15, ty = tid >> 4;
    const int row0 = blockIdx.y*BMt, col0 = blockIdx.x*BNt;
    float acc[4][4] = {};
    const int wm = tid >> 2;
    const int wk = (tid & 3) * 4;
    const int xk = tid >> 4;
    const int xn = (tid & 15) * 4;

    for (int kt=0; kt<Kc; kt+=BKt){
        float4 wv = make_float4(0.f,0.f,0.f,0.f);
        const int gm = row0 + wm;
        if (gm < M) wv = *reinterpret_cast<const float4*>(&W[(size_t)gm*Kc + kt + wk]);
        Ws[wk+0][wm]=wv.x; Ws[wk+1][wm]=wv.y; Ws[wk+2][wm]=wv.z; Ws[wk+3][wm]=wv.w;
        float4 xv = *reinterpret_cast<const float4*>(&X[(size_t)(kt+xk)*N + col0 + xn]);
        *reinterpret_cast<float4*>(&Xs[xk][xn]) = xv;
        __syncthreads();
        #pragma unroll
        for (int k=0;k<BKt;k++){
            float a0=Ws[k][ty*4+0], a1=Ws[k][ty*4+1], a2=Ws[k][ty*4+2], a3=Ws[k][ty*4+3];
            float b0=Xs[k][tx*4+0], b1=Xs[k][tx*4+1], b2=Xs[k][tx*4+2], b3=Xs[k][tx*4+3];
            acc[0][0]+=a0*b0; acc[0][1]+=a0*b1; acc[0][2]+=a0*b2; acc[0][3]+=a0*b3;
            acc[1][0]+=a1*b0; acc[1][1]+=a1*b1; acc[1][2]+=a1*b2; acc[1][3]+=a1*b3;
            acc[2][0]+=a2*b0; acc[2][1]+=a2*b1; acc[2][2]+=a2*b2; acc[2][3]+=a2*b3;
            acc[3][0]+=a3*b0; acc[3][1]+=a3*b1; acc[3][2]+=a3*b2; acc[3][3]+=a3*b3;
        }
        __syncthreads();
    }
    #pragma unroll
    for (int i=0;i<4;i++){
        const int m = row0 + ty*4 + i;
        if (m >= M) continue;
        float s = 1.f, sh = 0.f;
        if (gamma){
            const float sc = gamma[m] * rsqrtf(var[m] + 1e-5f);
            s = sc; sh = beta[m] - mean[m]*sc;
        } else if (bias){
            sh = bias[m];
        }
        float4 o;
        o.x = acc[i][0]*s + sh; o.y = acc[i][1]*s + sh;
        o.z = acc[i][2]*s + sh; o.w = acc[i][3]*s + sh;
        if (do_relu){
            o.x=fmaxf(o.x,0.f); o.y=fmaxf(o.y,0.f); o.z=fmaxf(o.z,0.f); o.w=fmaxf(o.w,0.f);
        }
        *reinterpret_cast<float4*>(&Out[(size_t)m*N + col0 + tx*4]) = o;
    }
}

// ---------------- head ----------------
__global__ __launch_bounds__(256) void head_kernel(const float* __restrict__ msa,
                                                   float* __restrict__ out)
{
    const int t = blockIdx.x*256 + threadIdx.x;
    #define NT(j) g_NET[(j)*NP + t]
    const float obj0 = NT(0), obj1 = NT(1);
    out[OFF_OBJ + t*2 + 0] = obj0;
    out[OFF_OBJ + t*2 + 1] = obj1;
    const float c0 = g_NX[t*3+0] + NT(2);
    const float c1 = g_NX[t*3+1] + NT(3);
    const float c2 = g_NX[t*3+2] + NT(4);
    out[OFF_CENTER + t*3 + 0] = c0;
    out[OFF_CENTER + t*3 + 1] = c1;
    out[OFF_CENTER + t*3 + 2] = c2;

    float ss[18];
    #pragma unroll
    for (int k=0;k<18;k++){ ss[k] = NT(29+k); out[OFF_SS + t*18 + k] = ss[k]; }
    int best = 0; float bv = ss[0];
    #pragma unroll
    for (int k=1;k<18;k++) if (ss[k] > bv){ bv = ss[k]; best = k; }

    float ps0=0.f, ps1=0.f, ps2=0.f;
    #pragma unroll
    for (int k=0;k<18;k++){
        const float m0=msa[k*3+0], m1=msa[k*3+1], m2=msa[k*3+2];
        const float r0 = NT(47+k*3+0)*m0;
        const float r1 = NT(47+k*3+1)*m1;
        const float r2 = NT(47+k*3+2)*m2;
        out[OFF_SRES + t*54 + k*3 + 0] = r0;
        out[OFF_SRES + t*54 + k*3 + 1] = r1;
        out[OFF_SRES + t*54 + k*3 + 2] = r2;
        if (k == best){ ps0 = r0+m0; ps1 = r1+m1; ps2 = r2+m2; }
    }
    out[OFF_PSIZE + t*3 + 0] = ps0;
    out[OFF_PSIZE + t*3 + 1] = ps1;
    out[OFF_PSIZE + t*3 + 2] = ps2;

    float sm[18];
    #pragma unroll
    for (int k=0;k<18;k++){ sm[k] = NT(101+k); out[OFF_SEM + t*18 + k] = sm[k]; }

    const float cc0 = c0, cc1 = c2, cc2 = -c1;
    const float hx = ps0*0.5f, hy = ps2*0.5f, hz = ps1*0.5f;
    const float SX[8]={1,1,-1,-1,1,1,-1,-1};
    const float SY[8]={1,1,1,1,-1,-1,-1,-1};
    const float SZ[8]={1,-1,-1,1,1,-1,-1,1};
    #pragma unroll
    for (int i=0;i<8;i++){
        out[OFF_CORN + t*24 + i*3 + 0] = cc0 + hx*SX[i];
        out[OFF_CORN + t*24 + i*3 + 1] = cc1 + hy*SY[i];
        out[OFF_CORN + t*24 + i*3 + 2] = cc2 + hz*SZ[i];
    }

    #pragma unroll
    for (int k=0;k<18;k++) out[OFF_SLOG + t*19 + k] = sm[k];
    out[OFF_SLOG + t*19 + 18] = (obj0 <= obj1) ? 0.0f : 1e10f;

    {
        const float mx = fmaxf(obj0,obj1);
        const float e0 = expf(obj0-mx), e1 = expf(obj1-mx);
        out[OFF_OPROB + t] = e1/(e0+e1);
    }
    {
        float mx = sm[0];
        #pragma unroll
        for (int k=1;k<18;k++) mx = fmaxf(mx, sm[k]);
        float e[18], ssum = 0.f;
        #pragma unroll
        for (int k=0;k<18;k++){ e[k] = expf(sm[k]-mx); ssum += e[k]; }
        #pragma unroll
        for (int k=0;k<18;k++) out[OFF_SPROB + t*18 + k] = e[k]/ssum;
    }
    #undef NT
}

// ---------------- host launcher ----------------
extern "C" void kernel_launch(void* const* d_in, const int* in_sizes, int n_in,
                              void* d_out, int out_size)
{
    const float* xyz      = (const float*)d_in[0];
    const float* features = (const float*)d_in[1];
    const float* sa_w1    = (const float*)d_in[2];
    const float* sa_w2    = (const float*)d_in[3];
    const float* sa_w3    = (const float*)d_in[4];
    const float* sa_gamma = (const float*)d_in[5];
    const float* sa_beta  = (const float*)d_in[6];
    const float* sa_mean  = (const float*)d_in[7];
    const float* sa_var   = (const float*)d_in[8];
    const float* p_w1     = (const float*)d_in[9];
    const float* p_w2     = (const float*)d_in[10];
    const float* p_w3     = (const float*)d_in[11];
    const float* p_b3     = (const float*)d_in[12];
    const float* p_gamma  = (const float*)d_in[13];
    const float* p_beta   = (const float*)d_in[14];
    const float* p_mean   = (const float*)d_in[15];
    const float* p_var    = (const float*)d_in[16];
    const float* msa      = (const float*)d_in[17];
    float* out = (float*)d_out;

    cudaFuncSetAttribute(mma_gemm_kernel, cudaFuncAttributeMaxDynamicSharedMemorySize, SMT);

    void *pX1a,*pX1b, *pA1a,*pA1b, *pA2a,*pA2b;
    void *pW1a,*pW1b, *pW2a,*pW2b, *pW3a,*pW3b;
    void *pY, *pY2, *pY3, *pNET;
    cudaGetSymbolAddress(&pX1a, g_X1a); cudaGetSymbolAddress(&pX1b, g_X1b);
    cudaGetSymbolAddress(&pA1a, g_A1a); cudaGetSymbolAddress(&pA1b, g_A1b);
    cudaGetSymbolAddress(&pA2a, g_A2a); cudaGetSymbolAddress(&pA2b, g_A2b);
    cudaGetSymbolAddress(&pW1a, g_W1a); cudaGetSymbolAddress(&pW1b, g_W1b);
    cudaGetSymbolAddress(&pW2a, g_W2a); cudaGetSymbolAddress(&pW2b, g_W2b);
    cudaGetSymbolAddress(&pW3a, g_W3a); cudaGetSymbolAddress(&pW3b, g_W3b);
    cudaGetSymbolAddress(&pY,  g_Y);
    cudaGetSymbolAddress(&pY2, g_Y2);
    cudaGetSymbolAddress(&pY3, g_Y3);
    cudaGetSymbolAddress(&pNET, g_NET);

    fps_kernel<<<BB, 1024>>>(xyz);
    ballq_kernel<<<1024, 256>>>(xyz);
    prep_split<<<(CC*KP + 255)/256, 256>>>(sa_w1, (__half*)pW1a, (__half*)pW1b, CC, 259, KP);
    prep_split<<<(CC*CC + 255)/256, 256>>>(sa_w2, (__half*)pW2a, (__half*)pW2b, CC, CC, CC);
    prep_split<<<(CC*CC + 255)/256, 256>>>(sa_w3, (__half*)pW3a, (__half*)pW3b, CC, CC, CC);
    gatherx_kernel<<<NCOL/256, 256>>>(xyz);
    gatherf_kernel<<<dim3(CC, BB), 256>>>(features);

    const dim3 gg(NCOL/128, 2);
    // layer 1: K=320 (10 chunks)
    mma_gemm_kernel<<<gg, 256, SMT>>>(
        (const __half*)pW1a, (const __half*)pW1b, KP, KP/32,
        (const __half*)pX1a, (const __half*)pX1b,
        (__half*)pA1a, (__half*)pA1b, nullptr,
        sa_gamma+0, sa_beta+0, sa_mean+0, sa_var+0);
    // layer 2
    mma_gemm_kernel<<<gg, 256, SMT>>>(
        (const __half*)pW2a, (const __half*)pW2b, CC, CC/32,
        (const __half*)pA1a, (const __half*)pA1b,
        (__half*)pA2a, (__half*)pA2b, nullptr,
        sa_gamma+256, sa_beta+256, sa_mean+256, sa_var+256);
    // layer 3 -> fused maxpool into g_Y
    mma_gemm_kernel<<<gg, 256, SMT>>>(
        (const __half*)pW3a, (const __half*)pW3b, CC, CC/32,
        (const __half*)pA2a, (const __half*)pA2b,
        nullptr, nullptr, (float*)pY,
        sa_gamma+512, sa_beta+512, sa_mean+512, sa_var+512);

    gemm_kernel<<<dim3(NP/BNt, CC/BMt), 256>>>(p_w1, (const float*)pY, (float*)pY2,
        CC, CC, NP, p_gamma+0, p_beta+0, p_mean+0, p_var+0, nullptr, 1);
    gemm_kernel<<<dim3(NP/BNt, CC/BMt), 256>>>(p_w2, (const float*)pY2, (float*)pY3,
        CC, CC, NP, p_gamma+256, p_beta+256, p_mean+256, p_var+256, nullptr, 1);
    gemm_kernel<<<dim3(NP/BNt, (OUTC+BMt-1)/BMt), 256>>>(p_w3, (const float*)pY3, (float*)pNET,
        OUTC, CC, NP, nullptr, nullptr, nullptr, nullptr, p_b3, 0);

    head_kernel<<<NP/256, 256>>>(msa, out);
}

// round 6
// speedup vs baseline: 1.9083x; 1.1189x over previous
#include <cuda_runtime.h>
#include <cuda_fp16.h>
#include <math.h>
#include <cstdint>

// ---------------- problem constants ----------------
#define BB 32
#define KK 2048
#define CC 256
#define PP 256
#define SS 16
#define NCOL (BB*PP*SS)      // 131072
#define NP   (BB*PP)         // 8192
#define KP   288             // 259 padded to mult of 32
#define OUTC 119
#define MP3  128             // p_w3 M padded

// output section offsets (floats)
#define OFF_OBJ      0
#define OFF_CENTER   16384
#define OFF_SS       40960
#define OFF_SRES     188416
#define OFF_PSIZE    630784
#define OFF_SEM      655360
#define OFF_CORN     802816
#define OFF_SLOG     999424
#define OFF_OPROB    1155072
#define OFF_SPROB    1163264

// ---------------- scratch (device globals; zero-init guaranteed) ----------------
__device__ __half g_X1a[(size_t)KP * NCOL];   // plane hi (rows 259..287 stay 0)
__device__ __half g_X1b[(size_t)KP * NCOL];   // plane lo
__device__ __half g_A1a[(size_t)CC * NCOL];
__device__ __half g_A1b[(size_t)CC * NCOL];
__device__ __half g_A2a[(size_t)CC * NCOL];
__device__ __half g_A2b[(size_t)CC * NCOL];
__device__ __half g_W1a[CC*KP], g_W1b[CC*KP];
__device__ __half g_W2a[CC*CC], g_W2b[CC*CC];
__device__ __half g_W3a[CC*CC], g_W3b[CC*CC];
__device__ __half g_P1a[CC*CC], g_P1b[CC*CC];
__device__ __half g_P2a[CC*CC], g_P2b[CC*CC];
__device__ __half g_P3a[MP3*CC], g_P3b[MP3*CC];
__device__ float  g_B3P[MP3];
__device__ __half g_Ya [CC*NP], g_Yb [CC*NP];   // pooled features, split planes
__device__ __half g_Y2a[CC*NP], g_Y2b[CC*NP];
__device__ __half g_Y3a[CC*NP], g_Y3b[CC*NP];
__device__ float  g_NET[MP3 * NP];
__device__ float  g_NX[NP * 3];
__device__ int    g_IDX[NP * SS];

// ---------------- asm helpers (base-target: sm_80+) ----------------
__device__ __forceinline__ uint32_t smem_u32(const void* p){
    uint32_t a;
    asm("{ .reg .u64 t; cvta.to.shared.u64 t, %1; cvt.u32.u64 %0, t; }" : "=r"(a) : "l"(p));
    return a;
}
#define CP16(dst, src)  asm volatile("cp.async.cg.shared.global [%0], [%1], 16;" :: "r"(dst), "l"(src))
#define CP_COMMIT()     asm volatile("cp.async.commit_group;" ::: "memory")
#define CP_WAIT2()      asm volatile("cp.async.wait_group 2;" ::: "memory")
#define CP_WAIT1()      asm volatile("cp.async.wait_group 1;" ::: "memory")
#define CP_WAIT0()      asm volatile("cp.async.wait_group 0;" ::: "memory")

#define LDSM_X4(R, addr) \
    asm volatile("ldmatrix.sync.aligned.m8n8.x4.shared.b16 {%0,%1,%2,%3}, [%4];" \
        : "=r"((R)[0]),"=r"((R)[1]),"=r"((R)[2]),"=r"((R)[3]) : "r"(addr))
#define LDSM_X4T(R, addr) \
    asm volatile("ldmatrix.sync.aligned.m8n8.x4.trans.shared.b16 {%0,%1,%2,%3}, [%4];" \
        : "=r"((R)[0]),"=r"((R)[1]),"=r"((R)[2]),"=r"((R)[3]) : "r"(addr))

#define MMA_F16(C, A, b0, b1) \
    asm volatile("mma.sync.aligned.m16n8k16.row.col.f32.f16.f16.f32 " \
        "{%0,%1,%2,%3}, {%4,%5,%6,%7}, {%8,%9}, {%0,%1,%2,%3};" \
        : "+f"((C)[0]),"+f"((C)[1]),"+f"((C)[2]),"+f"((C)[3]) \
        : "r"((A)[0]),"r"((A)[1]),"r"((A)[2]),"r"((A)[3]), "r"(b0),"r"(b1))

// ---------------- misc helpers ----------------
__device__ __forceinline__ float d2_nofma(float ax,float ay,float az,float bx,float by,float bz){
    float dx=ax-bx, dy=ay-by, dz=az-bz;
    return __fadd_rn(__fadd_rn(__fmul_rn(dx,dx),__fmul_rn(dy,dy)),__fmul_rn(dz,dz));
}
__device__ __forceinline__ void split2(float v, __half& h, __half& l){
    h = __float2half(v);
    l = __float2half(v - __half2float(h));
}

// ---------------- FPS: one block per batch ----------------
__global__ __launch_bounds__(1024) void fps_kernel(const float* __restrict__ xyz)
{
    __shared__ float sx[KK], sy[KK], sz[KK];
    __shared__ float rv[32]; __shared__ int ri[32]; __shared__ int sfar;
    const int b = blockIdx.x, tid = threadIdx.x;
    const float* xb = xyz + (size_t)b*KK*3;
    for (int i=tid;i<KK;i+=1024){ sx[i]=xb[i*3+0]; sy[i]=xb[i*3+1]; sz[i]=xb[i*3+2]; }
    __syncthreads();
    const int i0 = tid, i1 = tid + 1024;
    float d0 = 1e10f, d1 = 1e10f;
    int far = 0;
    const float x0=sx[i0], y0=sy[i0], z0=sz[i0];
    const float x1=sx[i1], y1=sy[i1], z1=sz[i1];
    for (int it=0; it<PP; ++it){
        if (tid==0){
            g_NX[(b*PP+it)*3+0]=sx[far];
            g_NX[(b*PP+it)*3+1]=sy[far];
            g_NX[(b*PP+it)*3+2]=sz[far];
        }
        const float cx=sx[far], cy=sy[far], cz=sz[far];
        d0 = fminf(d0, d2_nofma(x0,y0,z0,cx,cy,cz));
        d1 = fminf(d1, d2_nofma(x1,y1,z1,cx,cy,cz));
        float bv = d0; int bi = i0;
        if (d1 > bv){ bv=d1; bi=i1; }
        #pragma unroll
        for (int off=16; off; off>>=1){
            float ov=__shfl_down_sync(0xffffffffu,bv,off);
            int   oi=__shfl_down_sync(0xffffffffu,bi,off);
            if (ov>bv || (ov==bv && oi<bi)){ bv=ov; bi=oi; }
        }
        const int w = tid>>5, lane = tid&31;
        if (lane==0){ rv[w]=bv; ri[w]=bi; }
        __syncthreads();
        if (w==0){
            bv = rv[lane]; bi = ri[lane];
            #pragma unroll
            for (int off=16; off; off>>=1){
                float ov=__shfl_down_sync(0xffffffffu,bv,off);
                int   oi=__shfl_down_sync(0xffffffffu,bi,off);
                if (ov>bv || (ov==bv && oi<bi)){ bv=ov; bi=oi; }
            }
            if (lane==0) sfar = bi;
        }
        __syncthreads();
        far = sfar;
    }
}

// ---------------- ball query ----------------
__global__ __launch_bounds__(256) void ballq_kernel(const float* __restrict__ xyz)
{
    __shared__ float sx[KK], sy[KK], sz[KK];
    const int b = blockIdx.x >> 5;
    const float* xb = xyz + (size_t)b*KK*3;
    for (int i=threadIdx.x;i<KK;i+=256){ sx[i]=xb[i*3+0]; sy[i]=xb[i*3+1]; sz[i]=xb[i*3+2]; }
    __syncthreads();
    const int warp = threadIdx.x>>5, lane = threadIdx.x&31;
    const int w = blockIdx.x*8 + warp;
    const float cx=g_NX[w*3+0], cy=g_NX[w*3+1], cz=g_NX[w*3+2];
    int cnt=0, firstIdx=0; bool haveFirst=false;
    for (int j=0;j<KK;j+=32){
        const int i = j + lane;
        const float dd = d2_nofma(sx[i],sy[i],sz[i],cx,cy,cz);
        const bool within = dd < 0.09f;
        const unsigned mask = __ballot_sync(0xffffffffu, within);
        if (mask){
            if (!haveFirst){ firstIdx = j + __ffs(mask) - 1; haveFirst=true; }
            const int rank = __popc(mask & ((1u<<lane)-1u));
            if (within && (cnt+rank) < SS) g_IDX[w*SS + cnt + rank] = i;
            cnt += __popc(mask);
            if (cnt >= SS) break;
        }
    }
    if (cnt < SS && lane >= cnt && lane < SS) g_IDX[w*SS + lane] = firstIdx;
}

// ---------------- weight prep: fp32 -> 2 fp16 planes (with M/K pad) ----------------
__global__ void prep_split(const float* __restrict__ src,
                           __half* __restrict__ da, __half* __restrict__ db,
                           int Msrc, int Ksrc, int Kdst, int total)
{
    int t = blockIdx.x*256 + threadIdx.x;
    if (t < total){
        int m = t / Kdst, k = t % Kdst;
        float v = (m < Msrc && k < Ksrc) ? src[m*Ksrc + k] : 0.0f;
        __half h,l; split2(v,h,l);
        da[t]=h; db[t]=l;
    }
}
__global__ void prep_bias(const float* __restrict__ src)
{
    int t = threadIdx.x;
    if (t < MP3) g_B3P[t] = (t < OUTC) ? src[t] : 0.0f;
}

// ---------------- gather xyz channels into X1 rows 0..2 ----------------
__global__ void gatherx_kernel(const float* __restrict__ xyz)
{
    int t = blockIdx.x*256 + threadIdx.x;
    int b = t >> 12;
    int p = (t >> 4) & 255;
    int i = g_IDX[t];
    const float* xb = xyz + (size_t)b*KK*3 + (size_t)i*3;
    const float* nc = g_NX + (b*PP + p)*3;
    #pragma unroll
    for (int r=0;r<3;r++){
        float v = (xb[r]-nc[r]) / 0.3f;
        __half h,l; split2(v,h,l);
        g_X1a[(size_t)r*NCOL + t]=h; g_X1b[(size_t)r*NCOL + t]=l;
    }
}

// ---------------- gather features into X1 rows 3..258 ----------------
__global__ __launch_bounds__(256) void gatherf_kernel(const float* __restrict__ features)
{
    __shared__ float row[KK];
    const int c = blockIdx.x, b = blockIdx.y;
    const float* src = features + ((size_t)b*CC + c)*KK;
    for (int i=threadIdx.x;i<KK;i+=256) row[i]=src[i];
    __syncthreads();
    const size_t base = (size_t)(3+c)*NCOL + b*(PP*SS);
    const int* ib = g_IDX + b*(PP*SS);
    #pragma unroll
    for (int it=0; it<16; ++it){
        int cl = it*256 + threadIdx.x;
        float v = row[ib[cl]];
        __half h,l; split2(v,h,l);
        g_X1a[base+cl]=h; g_X1b[base+cl]=l;
    }
}

// ---------------- mma.sync fp16 GEMM (2-plane split, 3 products) ----------------
// CTA tile 128x128 (grid.y over M), 8 warps of 64x32, BK=32, 4-stage cp.async pipeline.
// mode 0: BN+ReLU -> fp16 split planes (Oa/Ob, stride ldO)
// mode 1: BN+ReLU -> fused 16-col maxpool -> fp16 split planes (Oa/Ob, stride NP)
// mode 2: +bias, no relu -> fp32 (OutF, stride ldO)
#define A_PL 10240u            // 128 rows * 80B (32 fp16 + 8 pad)
#define A_BUFS (2u*A_PL)       // 20480
#define B_PL 8704u             // 32 rows * 272B (128 fp16 + 8 pad)
#define B_BUFS (2u*B_PL)       // 17408
#define BUFSZ (A_BUFS + B_BUFS)// 37888
#define SMT (4*BUFSZ)          // 151552

__global__ __launch_bounds__(256) void mma_gemm_kernel(
    const __half* __restrict__ Aa, const __half* __restrict__ Ab, int Kw, int nch,
    const __half* __restrict__ Ba, const __half* __restrict__ Bb, int ldB,
    __half* __restrict__ Oa, __half* __restrict__ Ob, int ldO,
    float* __restrict__ OutF, const float* __restrict__ bias,
    const float* __restrict__ gamma, const float* __restrict__ beta,
    const float* __restrict__ mean,  const float* __restrict__ var,
    int mode)
{
    extern __shared__ char smem[];
    const uint32_t sbase = smem_u32(smem);
    const int tid = threadIdx.x, lane = tid & 31, wid = tid >> 5;
    const int wm = wid & 1, wn = wid >> 1;
    const int n0 = blockIdx.x * 128;
    const int mbase = blockIdx.y * 128;

    const size_t aoff = (size_t)mbase * Kw;
    const __half* A0 = Aa + aoff;
    const __half* A1 = Ab + aoff;

    auto stage = [&](int c, int buf){
        const int k0 = c * 32;
        const uint32_t sA = sbase + buf*BUFSZ;
        const uint32_t sB = sA + A_BUFS;
        #pragma unroll
        for (int it=0; it<2; ++it){
            const int idx = it*256 + tid;          // 512
            const int m = idx >> 2, kg = (idx & 3) * 8;
            const uint32_t d = sA + (uint32_t)m*80u + (uint32_t)kg*2u;
            const size_t so = (size_t)m*Kw + k0 + kg;
            CP16(d,        A0 + so);
            CP16(d + A_PL, A1 + so);
        }
        #pragma unroll
        for (int it=0; it<2; ++it){
            const int idx = it*256 + tid;          // 512
            const int k = idx >> 4, ng = (idx & 15) * 8;
            const uint32_t d = sB + (uint32_t)k*272u + (uint32_t)ng*2u;
            const size_t so = (size_t)(k0+k)*ldB + n0 + ng;
            CP16(d,        Ba + so);
            CP16(d + B_PL, Bb + so);
        }
    };

    float acc[4][4][4] = {};

    const uint32_t aRow = (uint32_t)((wm*64 + (lane & 15)) * 80) + (uint32_t)(((lane >> 4) << 3) * 2);
    const uint32_t bRow = (uint32_t)(((((lane >> 3) & 1) << 3) + (lane & 7)) * 272)
                        + (uint32_t)((wn*32 + ((lane >> 4) << 3)) * 2);

    auto compute_chunk = [&](int buf){
        const uint32_t aB = sbase + buf*BUFSZ;
        const uint32_t bB = aB + A_BUFS;
        #pragma unroll
        for (int ks=0; ks<2; ++ks){
            uint32_t bfr[2][2][4];
            #pragma unroll
            for (int p=0; p<2; ++p)
                #pragma unroll
                for (int n2=0; n2<2; ++n2)
                    LDSM_X4T(bfr[p][n2], bB + p*B_PL + bRow + (uint32_t)(ks*16*272) + (uint32_t)(n2*32));
            #pragma unroll
            for (int mh=0; mh<2; ++mh){
                uint32_t afr[2][2][4];
                #pragma unroll
                for (int p=0; p<2; ++p)
                    #pragma unroll
                    for (int m2=0; m2<2; ++m2)
                        LDSM_X4(afr[p][m2], aB + p*A_PL + aRow + (uint32_t)((mh*2+m2)*16*80) + (uint32_t)(ks*32));
                #pragma unroll
                for (int m2=0; m2<2; ++m2){
                    const int mi = mh*2 + m2;
                    #pragma unroll
                    for (int ni=0; ni<4; ++ni){
                        const int n2 = ni >> 1, q = (ni & 1) * 2;
                        float* C = acc[mi][ni];
                        MMA_F16(C, afr[0][m2], bfr[0][n2][q], bfr[0][n2][q+1]); // h*h
                        MMA_F16(C, afr[0][m2], bfr[1][n2][q], bfr[1][n2][q+1]); // h*l
                        MMA_F16(C, afr[1][m2], bfr[0][n2][q], bfr[0][n2][q+1]); // l*h
                    }
                }
            }
        }
    };

    stage(0, 0); CP_COMMIT();
    stage(1, 1); CP_COMMIT();
    for (int c=0; c<nch; ++c){
        if (c+2 < nch){ stage(c+2, (c+2)&3); CP_COMMIT(); CP_WAIT2(); }
        else if (c+1 < nch){ CP_WAIT1(); }
        else { CP_WAIT0(); }
        __syncthreads();
        compute_chunk(c & 3);
    }

    // ---- epilogue ----
    #pragma unroll
    for (int mi=0; mi<4; ++mi){
        const int mlo = mbase + wm*64 + mi*16 + (lane >> 2);
        const int mhi = mlo + 8;
        float s0, h0, s1, h1;
        if (mode == 2){
            s0 = 1.f; h0 = bias[mlo];
            s1 = 1.f; h1 = bias[mhi];
        } else {
            s0 = gamma[mlo] * rsqrtf(var[mlo] + 1e-5f);
            h0 = beta[mlo] - mean[mlo]*s0;
            s1 = gamma[mhi] * rsqrtf(var[mhi] + 1e-5f);
            h1 = beta[mhi] - mean[mhi]*s1;
        }
        float vlo[4][2], vhi[4][2];
        #pragma unroll
        for (int ni=0; ni<4; ++ni){
            vlo[ni][0] = acc[mi][ni][0]*s0 + h0;
            vlo[ni][1] = acc[mi][ni][1]*s0 + h0;
            vhi[ni][0] = acc[mi][ni][2]*s1 + h1;
            vhi[ni][1] = acc[mi][ni][3]*s1 + h1;
            if (mode != 2){
                vlo[ni][0]=fmaxf(vlo[ni][0],0.f); vlo[ni][1]=fmaxf(vlo[ni][1],0.f);
                vhi[ni][0]=fmaxf(vhi[ni][0],0.f); vhi[ni][1]=fmaxf(vhi[ni][1],0.f);
            }
        }
        if (mode == 1){
            #pragma unroll
            for (int g=0; g<2; ++g){
                float pl = fmaxf(fmaxf(vlo[2*g][0],vlo[2*g][1]), fmaxf(vlo[2*g+1][0],vlo[2*g+1][1]));
                float ph = fmaxf(fmaxf(vhi[2*g][0],vhi[2*g][1]), fmaxf(vhi[2*g+1][0],vhi[2*g+1][1]));
                #pragma unroll
                for (int off=1; off<4; off<<=1){
                    pl = fmaxf(pl, __shfl_xor_sync(0xffffffffu, pl, off));
                    ph = fmaxf(ph, __shfl_xor_sync(0xffffffffu, ph, off));
                }
                if ((lane & 3) == 0){
                    const int p = (n0 >> 4) + wn*2 + g;
                    __half hh, hl;
                    split2(pl, hh, hl);
                    Oa[(size_t)mlo*NP + p] = hh; Ob[(size_t)mlo*NP + p] = hl;
                    split2(ph, hh, hl);
                    Oa[(size_t)mhi*NP + p] = hh; Ob[(size_t)mhi*NP + p] = hl;
                }
            }
        } else if (mode == 0){
            #pragma unroll
            for (int ni=0; ni<4; ++ni){
                const int n = n0 + wn*32 + ni*8 + (lane & 3)*2;
                const size_t ilo = (size_t)mlo*ldO + n, ihi = (size_t)mhi*ldO + n;
                __half ha0,la0, ha1,la1, hb0,lb0, hb1,lb1;
                split2(vlo[ni][0], ha0, la0); split2(vlo[ni][1], ha1, la1);
                split2(vhi[ni][0], hb0, lb0); split2(vhi[ni][1], hb1, lb1);
                __half2 t;
                t.x=ha0; t.y=ha1; *reinterpret_cast<__half2*>(&Oa[ilo]) = t;
                t.x=la0; t.y=la1; *reinterpret_cast<__half2*>(&Ob[ilo]) = t;
                t.x=hb0; t.y=hb1; *reinterpret_cast<__half2*>(&Oa[ihi]) = t;
                t.x=lb0; t.y=lb1; *reinterpret_cast<__half2*>(&Ob[ihi]) = t;
            }
        } else {
            #pragma unroll
            for (int ni=0; ni<4; ++ni){
                const int n = n0 + wn*32 + ni*8 + (lane & 3)*2;
                *reinterpret_cast<float2*>(&OutF[(size_t)mlo*ldO + n]) = make_float2(vlo[ni][0], vlo[ni][1]);
                *reinterpret_cast<float2*>(&OutF[(size_t)mhi*ldO + n]) = make_float2(vhi[ni][0], vhi[ni][1]);
            }
        }
    }
}

// ---------------- head ----------------
__global__ __launch_bounds__(256) void head_kernel(const float* __restrict__ msa,
                                                   float* __restrict__ out)
{
    const int t = blockIdx.x*256 + threadIdx.x;
    #define NT(j) g_NET[(j)*NP + t]
    const float obj0 = NT(0), obj1 = NT(1);
    out[OFF_OBJ + t*2 + 0] = obj0;
    out[OFF_OBJ + t*2 + 1] = obj1;
    const float c0 = g_NX[t*3+0] + NT(2);
    const float c1 = g_NX[t*3+1] + NT(3);
    const float c2 = g_NX[t*3+2] + NT(4);
    out[OFF_CENTER + t*3 + 0] = c0;
    out[OFF_CENTER + t*3 + 1] = c1;
    out[OFF_CENTER + t*3 + 2] = c2;

    float ss[18];
    #pragma unroll
    for (int k=0;k<18;k++){ ss[k] = NT(29+k); out[OFF_SS + t*18 + k] = ss[k]; }
    int best = 0; float bv = ss[0];
    #pragma unroll
    for (int k=1;k<18;k++) if (ss[k] > bv){ bv = ss[k]; best = k; }

    float ps0=0.f, ps1=0.f, ps2=0.f;
    #pragma unroll
    for (int k=0;k<18;k++){
        const float m0=msa[k*3+0], m1=msa[k*3+1], m2=msa[k*3+2];
        const float r0 = NT(47+k*3+0)*m0;
        const float r1 = NT(47+k*3+1)*m1;
        const float r2 = NT(47+k*3+2)*m2;
        out[OFF_SRES + t*54 + k*3 + 0] = r0;
        out[OFF_SRES + t*54 + k*3 + 1] = r1;
        out[OFF_SRES + t*54 + k*3 + 2] = r2;
        if (k == best){ ps0 = r0+m0; ps1 = r1+m1; ps2 = r2+m2; }
    }
    out[OFF_PSIZE + t*3 + 0] = ps0;
    out[OFF_PSIZE + t*3 + 1] = ps1;
    out[OFF_PSIZE + t*3 + 2] = ps2;

    float sm[18];
    #pragma unroll
    for (int k=0;k<18;k++){ sm[k] = NT(101+k); out[OFF_SEM + t*18 + k] = sm[k]; }

    const float cc0 = c0, cc1 = c2, cc2 = -c1;
    const float hx = ps0*0.5f, hy = ps2*0.5f, hz = ps1*0.5f;
    const float SX[8]={1,1,-1,-1,1,1,-1,-1};
    const float SY[8]={1,1,1,1,-1,-1,-1,-1};
    const float SZ[8]={1,-1,-1,1,1,-1,-1,1};
    #pragma unroll
    for (int i=0;i<8;i++){
        out[OFF_CORN + t*24 + i*3 + 0] = cc0 + hx*SX[i];
        out[OFF_CORN + t*24 + i*3 + 1] = cc1 + hy*SY[i];
        out[OFF_CORN + t*24 + i*3 + 2] = cc2 + hz*SZ[i];
    }

    #pragma unroll
    for (int k=0;k<18;k++) out[OFF_SLOG + t*19 + k] = sm[k];
    out[OFF_SLOG + t*19 + 18] = (obj0 <= obj1) ? 0.0f : 1e10f;

    {
        const float mx = fmaxf(obj0,obj1);
        const float e0 = expf(obj0-mx), e1 = expf(obj1-mx);
        out[OFF_OPROB + t] = e1/(e0+e1);
    }
    {
        float mx = sm[0];
        #pragma unroll
        for (int k=1;k<18;k++) mx = fmaxf(mx, sm[k]);
        float e[18], ssum = 0.f;
        #pragma unroll
        for (int k=0;k<18;k++){ e[k] = expf(sm[k]-mx); ssum += e[k]; }
        #pragma unroll
        for (int k=0;k<18;k++) out[OFF_SPROB + t*18 + k] = e[k]/ssum;
    }
    #undef NT
}

// ---------------- host launcher ----------------
extern "C" void kernel_launch(void* const* d_in, const int* in_sizes, int n_in,
                              void* d_out, int out_size)
{
    const float* xyz      = (const float*)d_in[0];
    const float* features = (const float*)d_in[1];
    const float* sa_w1    = (const float*)d_in[2];
    const float* sa_w2    = (const float*)d_in[3];
    const float* sa_w3    = (const float*)d_in[4];
    const float* sa_gamma = (const float*)d_in[5];
    const float* sa_beta  = (const float*)d_in[6];
    const float* sa_mean  = (const float*)d_in[7];
    const float* sa_var   = (const float*)d_in[8];
    const float* p_w1     = (const float*)d_in[9];
    const float* p_w2     = (const float*)d_in[10];
    const float* p_w3     = (const float*)d_in[11];
    const float* p_b3     = (const float*)d_in[12];
    const float* p_gamma  = (const float*)d_in[13];
    const float* p_beta   = (const float*)d_in[14];
    const float* p_mean   = (const float*)d_in[15];
    const float* p_var    = (const float*)d_in[16];
    const float* msa      = (const float*)d_in[17];
    float* out = (float*)d_out;

    cudaFuncSetAttribute(mma_gemm_kernel, cudaFuncAttributeMaxDynamicSharedMemorySize, SMT);

    void *pX1a,*pX1b, *pA1a,*pA1b, *pA2a,*pA2b;
    void *pW1a,*pW1b, *pW2a,*pW2b, *pW3a,*pW3b;
    void *pP1a,*pP1b, *pP2a,*pP2b, *pP3a,*pP3b, *pB3P;
    void *pYa,*pYb, *pY2a,*pY2b, *pY3a,*pY3b, *pNET;
    cudaGetSymbolAddress(&pX1a, g_X1a); cudaGetSymbolAddress(&pX1b, g_X1b);
    cudaGetSymbolAddress(&pA1a, g_A1a); cudaGetSymbolAddress(&pA1b, g_A1b);
    cudaGetSymbolAddress(&pA2a, g_A2a); cudaGetSymbolAddress(&pA2b, g_A2b);
    cudaGetSymbolAddress(&pW1a, g_W1a); cudaGetSymbolAddress(&pW1b, g_W1b);
    cudaGetSymbolAddress(&pW2a, g_W2a); cudaGetSymbolAddress(&pW2b, g_W2b);
    cudaGetSymbolAddress(&pW3a, g_W3a); cudaGetSymbolAddress(&pW3b, g_W3b);
    cudaGetSymbolAddress(&pP1a, g_P1a); cudaGetSymbolAddress(&pP1b, g_P1b);
    cudaGetSymbolAddress(&pP2a, g_P2a); cudaGetSymbolAddress(&pP2b, g_P2b);
    cudaGetSymbolAddress(&pP3a, g_P3a); cudaGetSymbolAddress(&pP3b, g_P3b);
    cudaGetSymbolAddress(&pB3P, g_B3P);
    cudaGetSymbolAddress(&pYa,  g_Ya);  cudaGetSymbolAddress(&pYb,  g_Yb);
    cudaGetSymbolAddress(&pY2a, g_Y2a); cudaGetSymbolAddress(&pY2b, g_Y2b);
    cudaGetSymbolAddress(&pY3a, g_Y3a); cudaGetSymbolAddress(&pY3b, g_Y3b);
    cudaGetSymbolAddress(&pNET, g_NET);

    fps_kernel<<<BB, 1024>>>(xyz);
    ballq_kernel<<<1024, 256>>>(xyz);
    prep_split<<<(CC*KP + 255)/256, 256>>>(sa_w1, (__half*)pW1a, (__half*)pW1b, CC, 259, KP, CC*KP);
    prep_split<<<(CC*CC + 255)/256, 256>>>(sa_w2, (__half*)pW2a, (__half*)pW2b, CC, CC, CC, CC*CC);
    prep_split<<<(CC*CC + 255)/256, 256>>>(sa_w3, (__half*)pW3a, (__half*)pW3b, CC, CC, CC, CC*CC);
    prep_split<<<(CC*CC + 255)/256, 256>>>(p_w1, (__half*)pP1a, (__half*)pP1b, CC, CC, CC, CC*CC);
    prep_split<<<(CC*CC + 255)/256, 256>>>(p_w2, (__half*)pP2a, (__half*)pP2b, CC, CC, CC, CC*CC);
    prep_split<<<(MP3*CC + 255)/256, 256>>>(p_w3, (__half*)pP3a, (__half*)pP3b, OUTC, CC, CC, MP3*CC);
    prep_bias<<<1, MP3>>>(p_b3);
    gatherx_kernel<<<NCOL/256, 256>>>(xyz);
    gatherf_kernel<<<dim3(CC, BB), 256>>>(features);

    const dim3 gg(NCOL/128, 2);
    // SA layer 1: K=288 (9 chunks) -> split planes
    mma_gemm_kernel<<<gg, 256, SMT>>>(
        (const __half*)pW1a, (const __half*)pW1b, KP, KP/32,
        (const __half*)pX1a, (const __half*)pX1b, NCOL,
        (__half*)pA1a, (__half*)pA1b, NCOL,
        nullptr, nullptr,
        sa_gamma+0, sa_beta+0, sa_mean+0, sa_var+0, 0);
    // SA layer 2
    mma_gemm_kernel<<<gg, 256, SMT>>>(
        (const __half*)pW2a, (const __half*)pW2b, CC, CC/32,
        (const __half*)pA1a, (const __half*)pA1b, NCOL,
        (__half*)pA2a, (__half*)pA2b, NCOL,
        nullptr, nullptr,
        sa_gamma+256, sa_beta+256, sa_mean+256, sa_var+256, 0);
    // SA layer 3 -> fused maxpool -> Y split planes
    mma_gemm_kernel<<<gg, 256, SMT>>>(
        (const __half*)pW3a, (const __half*)pW3b, CC, CC/32,
        (const __half*)pA2a, (const __half*)pA2b, NCOL,
        (__half*)pYa, (__half*)pYb, NP,
        nullptr, nullptr,
        sa_gamma+512, sa_beta+512, sa_mean+512, sa_var+512, 1);

    const dim3 gf(NP/128, 2);
    // FC1
    mma_gemm_kernel<<<gf, 256, SMT>>>(
        (const __half*)pP1a, (const __half*)pP1b, CC, CC/32,
        (const __half*)pYa, (const __half*)pYb, NP,
        (__half*)pY2a, (__half*)pY2b, NP,
        nullptr, nullptr,
        p_gamma+0, p_beta+0, p_mean+0, p_var+0, 0);
    // FC2
    mma_gemm_kernel<<<gf, 256, SMT>>>(
        (const __half*)pP2a, (const __half*)pP2b, CC, CC/32,
        (const __half*)pY2a, (const __half*)pY2b, NP,
        (__half*)pY3a, (__half*)pY3b, NP,
        nullptr, nullptr,
        p_gamma+256, p_beta+256, p_mean+256, p_var+256, 0);
    // FC3 (head conv): 128 padded rows, fp32 + bias, no relu
    mma_gemm_kernel<<<dim3(NP/128, 1), 256, SMT>>>(
        (const __half*)pP3a, (const __half*)pP3b, CC, CC/32,
        (const __half*)pY3a, (const __half*)pY3b, NP,
        nullptr, nullptr, NP,
        (float*)pNET, (const float*)pB3P,
        nullptr, nullptr, nullptr, nullptr, 2);

    head_kernel<<<NP/256, 256>>>(msa, out);
}

// round 7
// speedup vs baseline: 2.1215x; 1.1117x over previous
#include <cuda_runtime.h>
#include <cuda_fp16.h>
#include <math.h>
#include <cstdint>

// ---------------- problem constants ----------------
#define BB 32
#define KK 2048
#define CC 256
#define PP 256
#define SS 16
#define NCOL (BB*PP*SS)      // 131072
#define NP   (BB*PP)         // 8192
#define KP   288             // 259 padded to mult of 32
#define OUTC 119
#define MP3  128             // p_w3 M padded

// output section offsets (floats)
#define OFF_OBJ      0
#define OFF_CENTER   16384
#define OFF_SS       40960
#define OFF_SRES     188416
#define OFF_PSIZE    630784
#define OFF_SEM      655360
#define OFF_CORN     802816
#define OFF_SLOG     999424
#define OFF_OPROB    1155072
#define OFF_SPROB    1163264

// ---------------- scratch (device globals; zero-init guaranteed) ----------------
__device__ __half g_X1a[(size_t)KP * NCOL];   // plane hi (rows 259..287 stay 0)
__device__ __half g_X1b[(size_t)KP * NCOL];   // plane lo
__device__ __half g_A1a[(size_t)CC * NCOL];
__device__ __half g_A1b[(size_t)CC * NCOL];
__device__ __half g_A2a[(size_t)CC * NCOL];
__device__ __half g_A2b[(size_t)CC * NCOL];
__device__ __half g_W1a[CC*KP], g_W1b[CC*KP];
__device__ __half g_W2a[CC*CC], g_W2b[CC*CC];
__device__ __half g_W3a[CC*CC], g_W3b[CC*CC];
__device__ __half g_P1a[CC*CC], g_P1b[CC*CC];
__device__ __half g_P2a[CC*CC], g_P2b[CC*CC];
__device__ __half g_P3a[MP3*CC], g_P3b[MP3*CC];
__device__ float  g_B3P[MP3];
__device__ __half g_Ya [CC*NP], g_Yb [CC*NP];   // pooled features, split planes
__device__ __half g_Y2a[CC*NP], g_Y2b[CC*NP];
__device__ __half g_Y3a[CC*NP], g_Y3b[CC*NP];
__device__ float  g_NET[MP3 * NP];
__device__ float  g_NX[NP * 3];
__device__ int    g_IDX[NP * SS];

// ---------------- asm helpers (base-target: sm_80+) ----------------
__device__ __forceinline__ uint32_t smem_u32(const void* p){
    uint32_t a;
    asm("{ .reg .u64 t; cvta.to.shared.u64 t, %1; cvt.u32.u64 %0, t; }" : "=r"(a) : "l"(p));
    return a;
}
#define CP16(dst, src)  asm volatile("cp.async.cg.shared.global [%0], [%1], 16;" :: "r"(dst), "l"(src))
#define CP_COMMIT()     asm volatile("cp.async.commit_group;" ::: "memory")
#define CP_WAIT2()      asm volatile("cp.async.wait_group 2;" ::: "memory")
#define CP_WAIT1()      asm volatile("cp.async.wait_group 1;" ::: "memory")
#define CP_WAIT0()      asm volatile("cp.async.wait_group 0;" ::: "memory")

#define LDSM_X4(R, addr) \
    asm volatile("ldmatrix.sync.aligned.m8n8.x4.shared.b16 {%0,%1,%2,%3}, [%4];" \
        : "=r"((R)[0]),"=r"((R)[1]),"=r"((R)[2]),"=r"((R)[3]) : "r"(addr))
#define LDSM_X4T(R, addr) \
    asm volatile("ldmatrix.sync.aligned.m8n8.x4.trans.shared.b16 {%0,%1,%2,%3}, [%4];" \
        : "=r"((R)[0]),"=r"((R)[1]),"=r"((R)[2]),"=r"((R)[3]) : "r"(addr))

#define MMA_F16(C, A, b0, b1) \
    asm volatile("mma.sync.aligned.m16n8k16.row.col.f32.f16.f16.f32 " \
        "{%0,%1,%2,%3}, {%4,%5,%6,%7}, {%8,%9}, {%0,%1,%2,%3};" \
        : "+f"((C)[0]),"+f"((C)[1]),"+f"((C)[2]),"+f"((C)[3]) \
        : "r"((A)[0]),"r"((A)[1]),"r"((A)[2]),"r"((A)[3]), "r"(b0),"r"(b1))

// ---------------- misc helpers ----------------
__device__ __forceinline__ float d2_nofma(float ax,float ay,float az,float bx,float by,float bz){
    float dx=ax-bx, dy=ay-by, dz=az-bz;
    return __fadd_rn(__fadd_rn(__fmul_rn(dx,dx),__fmul_rn(dy,dy)),__fmul_rn(dz,dz));
}
__device__ __forceinline__ void split2(float v, __half& h, __half& l){
    h = __float2half(v);
    l = __float2half(v - __half2float(h));
}

// ---------------- FPS: one block per batch, redux.sync argmax ----------------
__global__ __launch_bounds__(1024) void fps_kernel(const float* __restrict__ xyz)
{
    __shared__ float sx[KK], sy[KK], sz[KK];
    __shared__ unsigned rv[32]; __shared__ int ri[32]; __shared__ int sfar;
    const int b = blockIdx.x, tid = threadIdx.x;
    const float* xb = xyz + (size_t)b*KK*3;
    for (int i=tid;i<KK;i+=1024){ sx[i]=xb[i*3+0]; sy[i]=xb[i*3+1]; sz[i]=xb[i*3+2]; }
    __syncthreads();
    const int i0 = tid, i1 = tid + 1024;
    float d0 = 1e10f, d1 = 1e10f;
    int far = 0;
    const float x0=sx[i0], y0=sy[i0], z0=sz[i0];
    const float x1=sx[i1], y1=sy[i1], z1=sz[i1];
    const int w = tid>>5, lane = tid&31;
    for (int it=0; it<PP; ++it){
        if (tid==0){
            g_NX[(b*PP+it)*3+0]=sx[far];
            g_NX[(b*PP+it)*3+1]=sy[far];
            g_NX[(b*PP+it)*3+2]=sz[far];
        }
        const float cx=sx[far], cy=sy[far], cz=sz[far];
        d0 = fminf(d0, d2_nofma(x0,y0,z0,cx,cy,cz));
        d1 = fminf(d1, d2_nofma(x1,y1,z1,cx,cy,cz));
        // per-thread: larger dist wins, tie keeps smaller index (i0 < i1)
        float bv = d0; int bi = i0;
        if (d1 > bv){ bv=d1; bi=i1; }
        // warp argmax via redux (dists >= 0 -> fp32 bits monotonic)
        const unsigned vbits = __float_as_uint(bv);
        const unsigned vmax  = __reduce_max_sync(0xffffffffu, vbits);
        const unsigned cand  = (vbits == vmax) ? (unsigned)bi : 0xFFFFFFFFu;
        const unsigned imin  = __reduce_min_sync(0xffffffffu, cand);
        if (lane==0){ rv[w]=vmax; ri[w]=(int)imin; }
        __syncthreads();
        if (w==0){
            const unsigned vb = rv[lane]; const int ib = ri[lane];
            const unsigned vmax2 = __reduce_max_sync(0xffffffffu, vb);
            const unsigned cand2 = (vb == vmax2) ? (unsigned)ib : 0xFFFFFFFFu;
            const unsigned imin2 = __reduce_min_sync(0xffffffffu, cand2);
            if (lane==0) sfar = (int)imin2;
        }
        __syncthreads();
        far = sfar;
    }
}

// ---------------- ball query + fused xyz gather (X1 rows 0..2) ----------------
__global__ __launch_bounds__(256) void ballq_kernel(const float* __restrict__ xyz)
{
    __shared__ float sx[KK], sy[KK], sz[KK];
    __shared__ int sidx[8][SS];
    const int b = blockIdx.x >> 5;
    const float* xb = xyz + (size_t)b*KK*3;
    for (int i=threadIdx.x;i<KK;i+=256){ sx[i]=xb[i*3+0]; sy[i]=xb[i*3+1]; sz[i]=xb[i*3+2]; }
    __syncthreads();
    const int warp = threadIdx.x>>5, lane = threadIdx.x&31;
    const int w = blockIdx.x*8 + warp;
    const float cx=g_NX[w*3+0], cy=g_NX[w*3+1], cz=g_NX[w*3+2];
    int cnt=0, firstIdx=0; bool haveFirst=false;
    for (int j=0;j<KK;j+=32){
        const int i = j + lane;
        const float dd = d2_nofma(sx[i],sy[i],sz[i],cx,cy,cz);
        const bool within = dd < 0.09f;
        const unsigned mask = __ballot_sync(0xffffffffu, within);
        if (mask){
            if (!haveFirst){ firstIdx = j + __ffs(mask) - 1; haveFirst=true; }
            const int rank = __popc(mask & ((1u<<lane)-1u));
            if (within && (cnt+rank) < SS) sidx[warp][cnt+rank] = i;
            cnt += __popc(mask);
            if (cnt >= SS) break;
        }
    }
    if (cnt < SS && lane >= cnt && lane < SS) sidx[warp][lane] = firstIdx;
    __syncwarp();
    if (lane < SS){
        const int i = sidx[warp][lane];
        const int t = w*SS + lane;
        g_IDX[t] = i;
        const float v0 = (sx[i]-cx) / 0.3f;
        const float v1 = (sy[i]-cy) / 0.3f;
        const float v2 = (sz[i]-cz) / 0.3f;
        __half h,l;
        split2(v0,h,l); g_X1a[0*(size_t)NCOL + t]=h; g_X1b[0*(size_t)NCOL + t]=l;
        split2(v1,h,l); g_X1a[1*(size_t)NCOL + t]=h; g_X1b[1*(size_t)NCOL + t]=l;
        split2(v2,h,l); g_X1a[2*(size_t)NCOL + t]=h; g_X1b[2*(size_t)NCOL + t]=l;
    }
}

// ---------------- merged weight prep: all 6 matrices + bias, one launch ----------------
#define PR_W1_END  (CC*KP)                       // 73728
#define PR_W2_END  (PR_W1_END + CC*CC)           // 139264
#define PR_W3_END  (PR_W2_END + CC*CC)           // 204800
#define PR_P1_END  (PR_W3_END + CC*CC)           // 270336
#define PR_P2_END  (PR_P1_END + CC*CC)           // 335872
#define PR_P3_END  (PR_P2_END + MP3*CC)          // 368640
#define PR_TOTAL   (PR_P3_END + MP3)             // 368768

__global__ void prep_all(const float* __restrict__ w1, const float* __restrict__ w2,
                         const float* __restrict__ w3, const float* __restrict__ q1,
                         const float* __restrict__ q2, const float* __restrict__ q3,
                         const float* __restrict__ b3)
{
    const int t = blockIdx.x*256 + threadIdx.x;
    if (t >= PR_TOTAL) return;
    if (t >= PR_P3_END){ const int k = t - PR_P3_END; g_B3P[k] = (k < OUTC) ? b3[k] : 0.0f; return; }
    const float* src; __half *da, *db; int idx, Ksrc, Kdst, Msrc;
    if (t < PR_W1_END){ src=w1; da=g_W1a; db=g_W1b; idx=t;            Ksrc=259; Kdst=KP; Msrc=CC; }
    else if (t < PR_W2_END){ src=w2; da=g_W2a; db=g_W2b; idx=t-PR_W1_END; Ksrc=CC; Kdst=CC; Msrc=CC; }
    else if (t < PR_W3_END){ src=w3; da=g_W3a; db=g_W3b; idx=t-PR_W2_END; Ksrc=CC; Kdst=CC; Msrc=CC; }
    else if (t < PR_P1_END){ src=q1; da=g_P1a; db=g_P1b; idx=t-PR_W3_END; Ksrc=CC; Kdst=CC; Msrc=CC; }
    else if (t < PR_P2_END){ src=q2; da=g_P2a; db=g_P2b; idx=t-PR_P1_END; Ksrc=CC; Kdst=CC; Msrc=CC; }
    else                   { src=q3; da=g_P3a; db=g_P3b; idx=t-PR_P2_END; Ksrc=CC; Kdst=CC; Msrc=OUTC; }
    const int m = idx / Kdst, k = idx % Kdst;
    const float v = (m < Msrc && k < Ksrc) ? src[m*Ksrc + k] : 0.0f;
    __half h,l; split2(v,h,l);
    da[idx]=h; db[idx]=l;
}

// ---------------- gather features into X1 rows 3..258 ----------------
__global__ __launch_bounds__(256) void gatherf_kernel(const float* __restrict__ features)
{
    __shared__ float row[KK];
    const int c = blockIdx.x, b = blockIdx.y;
    const float* src = features + ((size_t)b*CC + c)*KK;
    for (int i=threadIdx.x;i<KK;i+=256) row[i]=src[i];
    __syncthreads();
    const size_t base = (size_t)(3+c)*NCOL + b*(PP*SS);
    const int* ib = g_IDX + b*(PP*SS);
    #pragma unroll
    for (int it=0; it<16; ++it){
        int cl = it*256 + threadIdx.x;
        float v = row[ib[cl]];
        __half h,l; split2(v,h,l);
        g_X1a[base+cl]=h; g_X1b[base+cl]=l;
    }
}

// ---------------- mma.sync fp16 GEMM (2-plane split, 3 products) ----------------
// CTA tile 128x128 (grid.y over M), 8 warps of 64x32, BK=32, 4-stage cp.async pipeline.
// mode 0: BN+ReLU -> fp16 split planes; mode 1: + fused 16-col maxpool; mode 2: +bias -> fp32
#define A_PL 10240u            // 128 rows * 80B (32 fp16 + 8 pad)
#define A_BUFS (2u*A_PL)       // 20480
#define B_PL 8704u             // 32 rows * 272B (128 fp16 + 8 pad)
#define B_BUFS (2u*B_PL)       // 17408
#define BUFSZ (A_BUFS + B_BUFS)// 37888
#define SMT (4*BUFSZ)          // 151552

__global__ __launch_bounds__(256) void mma_gemm_kernel(
    const __half* __restrict__ Aa, const __half* __restrict__ Ab, int Kw, int nch,
    const __half* __restrict__ Ba, const __half* __restrict__ Bb, int ldB,
    __half* __restrict__ Oa, __half* __restrict__ Ob, int ldO,
    float* __restrict__ OutF, const float* __restrict__ bias,
    const float* __restrict__ gamma, const float* __restrict__ beta,
    const float* __restrict__ mean,  const float* __restrict__ var,
    int mode)
{
    extern __shared__ char smem[];
    const uint32_t sbase = smem_u32(smem);
    const int tid = threadIdx.x, lane = tid & 31, wid = tid >> 5;
    const int wm = wid & 1, wn = wid >> 1;
    const int n0 = blockIdx.x * 128;
    const int mbase = blockIdx.y * 128;

    const size_t aoff = (size_t)mbase * Kw;
    const __half* A0 = Aa + aoff;
    const __half* A1 = Ab + aoff;

    auto stage = [&](int c, int buf){
        const int k0 = c * 32;
        const uint32_t sA = sbase + buf*BUFSZ;
        const uint32_t sB = sA + A_BUFS;
        #pragma unroll
        for (int it=0; it<2; ++it){
            const int idx = it*256 + tid;          // 512
            const int m = idx >> 2, kg = (idx & 3) * 8;
            const uint32_t d = sA + (uint32_t)m*80u + (uint32_t)kg*2u;
            const size_t so = (size_t)m*Kw + k0 + kg;
            CP16(d,        A0 + so);
            CP16(d + A_PL, A1 + so);
        }
        #pragma unroll
        for (int it=0; it<2; ++it){
            const int idx = it*256 + tid;          // 512
            const int k = idx >> 4, ng = (idx & 15) * 8;
            const uint32_t d = sB + (uint32_t)k*272u + (uint32_t)ng*2u;
            const size_t so = (size_t)(k0+k)*ldB + n0 + ng;
            CP16(d,        Ba + so);
            CP16(d + B_PL, Bb + so);
        }
    };

    float acc[4][4][4] = {};

    const uint32_t aRow = (uint32_t)((wm*64 + (lane & 15)) * 80) + (uint32_t)(((lane >> 4) << 3) * 2);
    const uint32_t bRow = (uint32_t)(((((lane >> 3) & 1) << 3) + (lane & 7)) * 272)
                        + (uint32_t)((wn*32 + ((lane >> 4) << 3)) * 2);

    auto compute_chunk = [&](int buf){
        const uint32_t aB = sbase + buf*BUFSZ;
        const uint32_t bB = aB + A_BUFS;
        #pragma unroll
        for (int ks=0; ks<2; ++ks){
            uint32_t bfr[2][2][4];
            #pragma unroll
            for (int p=0; p<2; ++p)
                #pragma unroll
                for (int n2=0; n2<2; ++n2)
                    LDSM_X4T(bfr[p][n2], bB + p*B_PL + bRow + (uint32_t)(ks*16*272) + (uint32_t)(n2*32));
            #pragma unroll
            for (int mh=0; mh<2; ++mh){
                uint32_t afr[2][2][4];
                #pragma unroll
                for (int p=0; p<2; ++p)
                    #pragma unroll
                    for (int m2=0; m2<2; ++m2)
                        LDSM_X4(afr[p][m2], aB + p*A_PL + aRow + (uint32_t)((mh*2+m2)*16*80) + (uint32_t)(ks*32));
                #pragma unroll
                for (int m2=0; m2<2; ++m2){
                    const int mi = mh*2 + m2;
                    #pragma unroll
                    for (int ni=0; ni<4; ++ni){
                        const int n2 = ni >> 1, q = (ni & 1) * 2;
                        float* C = acc[mi][ni];
                        MMA_F16(C, afr[0][m2], bfr[0][n2][q], bfr[0][n2][q+1]); // h*h
                        MMA_F16(C, afr[0][m2], bfr[1][n2][q], bfr[1][n2][q+1]); // h*l
                        MMA_F16(C, afr[1][m2], bfr[0][n2][q], bfr[0][n2][q+1]); // l*h
                    }
                }
            }
        }
    };

    stage(0, 0); CP_COMMIT();
    stage(1, 1); CP_COMMIT();
    for (int c=0; c<nch; ++c){
        if (c+2 < nch){ stage(c+2, (c+2)&3); CP_COMMIT(); CP_WAIT2(); }
        else if (c+1 < nch){ CP_WAIT1(); }
        else { CP_WAIT0(); }
        __syncthreads();
        compute_chunk(c & 3);
    }

    // ---- epilogue ----
    #pragma unroll
    for (int mi=0; mi<4; ++mi){
        const int mlo = mbase + wm*64 + mi*16 + (lane >> 2);
        const int mhi = mlo + 8;
        float s0, h0, s1, h1;
        if (mode == 2){
            s0 = 1.f; h0 = bias[mlo];
            s1 = 1.f; h1 = bias[mhi];
        } else {
            s0 = gamma[mlo] * rsqrtf(var[mlo] + 1e-5f);
            h0 = beta[mlo] - mean[mlo]*s0;
            s1 = gamma[mhi] * rsqrtf(var[mhi] + 1e-5f);
            h1 = beta[mhi] - mean[mhi]*s1;
        }
        float vlo[4][2], vhi[4][2];
        #pragma unroll
        for (int ni=0; ni<4; ++ni){
            vlo[ni][0] = acc[mi][ni][0]*s0 + h0;
            vlo[ni][1] = acc[mi][ni][1]*s0 + h0;
            vhi[ni][0] = acc[mi][ni][2]*s1 + h1;
            vhi[ni][1] = acc[mi][ni][3]*s1 + h1;
            if (mode != 2){
                vlo[ni][0]=fmaxf(vlo[ni][0],0.f); vlo[ni][1]=fmaxf(vlo[ni][1],0.f);
                vhi[ni][0]=fmaxf(vhi[ni][0],0.f); vhi[ni][1]=fmaxf(vhi[ni][1],0.f);
            }
        }
        if (mode == 1){
            #pragma unroll
            for (int g=0; g<2; ++g){
                float pl = fmaxf(fmaxf(vlo[2*g][0],vlo[2*g][1]), fmaxf(vlo[2*g+1][0],vlo[2*g+1][1]));
                float ph = fmaxf(fmaxf(vhi[2*g][0],vhi[2*g][1]), fmaxf(vhi[2*g+1][0],vhi[2*g+1][1]));
                #pragma unroll
                for (int off=1; off<4; off<<=1){
                    pl = fmaxf(pl, __shfl_xor_sync(0xffffffffu, pl, off));
                    ph = fmaxf(ph, __shfl_xor_sync(0xffffffffu, ph, off));
                }
                if ((lane & 3) == 0){
                    const int p = (n0 >> 4) + wn*2 + g;
                    __half hh, hl;
                    split2(pl, hh, hl);
                    Oa[(size_t)mlo*NP + p] = hh; Ob[(size_t)mlo*NP + p] = hl;
                    split2(ph, hh, hl);
                    Oa[(size_t)mhi*NP + p] = hh; Ob[(size_t)mhi*NP + p] = hl;
                }
            }
        } else if (mode == 0){
            #pragma unroll
            for (int ni=0; ni<4; ++ni){
                const int n = n0 + wn*32 + ni*8 + (lane & 3)*2;
                const size_t ilo = (size_t)mlo*ldO + n, ihi = (size_t)mhi*ldO + n;
                __half ha0,la0, ha1,la1, hb0,lb0, hb1,lb1;
                split2(vlo[ni][0], ha0, la0); split2(vlo[ni][1], ha1, la1);
                split2(vhi[ni][0], hb0, lb0); split2(vhi[ni][1], hb1, lb1);
                __half2 t;
                t.x=ha0; t.y=ha1; *reinterpret_cast<__half2*>(&Oa[ilo]) = t;
                t.x=la0; t.y=la1; *reinterpret_cast<__half2*>(&Ob[ilo]) = t;
                t.x=hb0; t.y=hb1; *reinterpret_cast<__half2*>(&Oa[ihi]) = t;
                t.x=lb0; t.y=lb1; *reinterpret_cast<__half2*>(&Ob[ihi]) = t;
            }
        } else {
            #pragma unroll
            for (int ni=0; ni<4; ++ni){
                const int n = n0 + wn*32 + ni*8 + (lane & 3)*2;
                *reinterpret_cast<float2*>(&OutF[(size_t)mlo*ldO + n]) = make_float2(vlo[ni][0], vlo[ni][1]);
                *reinterpret_cast<float2*>(&OutF[(size_t)mhi*ldO + n]) = make_float2(vhi[ni][0], vhi[ni][1]);
            }
        }
    }
}

// ---------------- head ----------------
__global__ __launch_bounds__(256) void head_kernel(const float* __restrict__ msa,
                                                   float* __restrict__ out)
{
    const int t = blockIdx.x*256 + threadIdx.x;
    #define NT(j) g_NET[(j)*NP + t]
    const float obj0 = NT(0), obj1 = NT(1);
    out[OFF_OBJ + t*2 + 0] = obj0;
    out[OFF_OBJ + t*2 + 1] = obj1;
    const float c0 = g_NX[t*3+0] + NT(2);
    const float c1 = g_NX[t*3+1] + NT(3);
    const float c2 = g_NX[t*3+2] + NT(4);
    out[OFF_CENTER + t*3 + 0] = c0;
    out[OFF_CENTER + t*3 + 1] = c1;
    out[OFF_CENTER + t*3 + 2] = c2;

    float ss[18];
    #pragma unroll
    for (int k=0;k<18;k++){ ss[k] = NT(29+k); out[OFF_SS + t*18 + k] = ss[k]; }
    int best = 0; float bv = ss[0];
    #pragma unroll
    for (int k=1;k<18;k++) if (ss[k] > bv){ bv = ss[k]; best = k; }

    float ps0=0.f, ps1=0.f, ps2=0.f;
    #pragma unroll
    for (int k=0;k<18;k++){
        const float m0=msa[k*3+0], m1=msa[k*3+1], m2=msa[k*3+2];
        const float r0 = NT(47+k*3+0)*m0;
        const float r1 = NT(47+k*3+1)*m1;
        const float r2 = NT(47+k*3+2)*m2;
        out[OFF_SRES + t*54 + k*3 + 0] = r0;
        out[OFF_SRES + t*54 + k*3 + 1] = r1;
        out[OFF_SRES + t*54 + k*3 + 2] = r2;
        if (k == best){ ps0 = r0+m0; ps1 = r1+m1; ps2 = r2+m2; }
    }
    out[OFF_PSIZE + t*3 + 0] = ps0;
    out[OFF_PSIZE + t*3 + 1] = ps1;
    out[OFF_PSIZE + t*3 + 2] = ps2;

    float sm[18];
    #pragma unroll
    for (int k=0;k<18;k++){ sm[k] = NT(101+k); out[OFF_SEM + t*18 + k] = sm[k]; }

    const float cc0 = c0, cc1 = c2, cc2 = -c1;
    const float hx = ps0*0.5f, hy = ps2*0.5f, hz = ps1*0.5f;
    const float SX[8]={1,1,-1,-1,1,1,-1,-1};
    const float SY[8]={1,1,1,1,-1,-1,-1,-1};
    const float SZ[8]={1,-1,-1,1,1,-1,-1,1};
    #pragma unroll
    for (int i=0;i<8;i++){
        out[OFF_CORN + t*24 + i*3 + 0] = cc0 + hx*SX[i];
        out[OFF_CORN + t*24 + i*3 + 1] = cc1 + hy*SY[i];
        out[OFF_CORN + t*24 + i*3 + 2] = cc2 + hz*SZ[i];
    }

    #pragma unroll
    for (int k=0;k<18;k++) out[OFF_SLOG + t*19 + k] = sm[k];
    out[OFF_SLOG + t*19 + 18] = (obj0 <= obj1) ? 0.0f : 1e10f;

    {
        const float mx = fmaxf(obj0,obj1);
        const float e0 = expf(obj0-mx), e1 = expf(obj1-mx);
        out[OFF_OPROB + t] = e1/(e0+e1);
    }
    {
        float mx = sm[0];
        #pragma unroll
        for (int k=1;k<18;k++) mx = fmaxf(mx, sm[k]);
        float e[18], ssum = 0.f;
        #pragma unroll
        for (int k=0;k<18;k++){ e[k] = expf(sm[k]-mx); ssum += e[k]; }
        #pragma unroll
        for (int k=0;k<18;k++) out[OFF_SPROB + t*18 + k] = e[k]/ssum;
    }
    #undef NT
}

// ---------------- host launcher ----------------
extern "C" void kernel_launch(void* const* d_in, const int* in_sizes, int n_in,
                              void* d_out, int out_size)
{
    const float* xyz      = (const float*)d_in[0];
    const float* features = (const float*)d_in[1];
    const float* sa_w1    = (const float*)d_in[2];
    const float* sa_w2    = (const float*)d_in[3];
    const float* sa_w3    = (const float*)d_in[4];
    const float* sa_gamma = (const float*)d_in[5];
    const float* sa_beta  = (const float*)d_in[6];
    const float* sa_mean  = (const float*)d_in[7];
    const float* sa_var   = (const float*)d_in[8];
    const float* p_w1     = (const float*)d_in[9];
    const float* p_w2     = (const float*)d_in[10];
    const float* p_w3     = (const float*)d_in[11];
    const float* p_b3     = (const float*)d_in[12];
    const float* p_gamma  = (const float*)d_in[13];
    const float* p_beta   = (const float*)d_in[14];
    const float* p_mean   = (const float*)d_in[15];
    const float* p_var    = (const float*)d_in[16];
    const float* msa      = (const float*)d_in[17];
    float* out = (float*)d_out;

    cudaFuncSetAttribute(mma_gemm_kernel, cudaFuncAttributeMaxDynamicSharedMemorySize, SMT);

    void *pX1a,*pX1b, *pA1a,*pA1b, *pA2a,*pA2b;
    void *pW1a,*pW1b, *pW2a,*pW2b, *pW3a,*pW3b;
    void *pP1a,*pP1b, *pP2a,*pP2b, *pP3a,*pP3b, *pB3P;
    void *pYa,*pYb, *pY2a,*pY2b, *pY3a,*pY3b, *pNET;
    cudaGetSymbolAddress(&pX1a, g_X1a); cudaGetSymbolAddress(&pX1b, g_X1b);
    cudaGetSymbolAddress(&pA1a, g_A1a); cudaGetSymbolAddress(&pA1b, g_A1b);
    cudaGetSymbolAddress(&pA2a, g_A2a); cudaGetSymbolAddress(&pA2b, g_A2b);
    cudaGetSymbolAddress(&pW1a, g_W1a); cudaGetSymbolAddress(&pW1b, g_W1b);
    cudaGetSymbolAddress(&pW2a, g_W2a); cudaGetSymbolAddress(&pW2b, g_W2b);
    cudaGetSymbolAddress(&pW3a, g_W3a); cudaGetSymbolAddress(&pW3b, g_W3b);
    cudaGetSymbolAddress(&pP1a, g_P1a); cudaGetSymbolAddress(&pP1b, g_P1b);
    cudaGetSymbolAddress(&pP2a, g_P2a); cudaGetSymbolAddress(&pP2b, g_P2b);
    cudaGetSymbolAddress(&pP3a, g_P3a); cudaGetSymbolAddress(&pP3b, g_P3b);
    cudaGetSymbolAddress(&pB3P, g_B3P);
    cudaGetSymbolAddress(&pYa,  g_Ya);  cudaGetSymbolAddress(&pYb,  g_Yb);
    cudaGetSymbolAddress(&pY2a, g_Y2a); cudaGetSymbolAddress(&pY2b, g_Y2b);
    cudaGetSymbolAddress(&pY3a, g_Y3a); cudaGetSymbolAddress(&pY3b, g_Y3b);
    cudaGetSymbolAddress(&pNET, g_NET);

    fps_kernel<<<BB, 1024>>>(xyz);
    prep_all<<<(PR_TOTAL + 255)/256, 256>>>(sa_w1, sa_w2, sa_w3, p_w1, p_w2, p_w3, p_b3);
    ballq_kernel<<<1024, 256>>>(xyz);
    gatherf_kernel<<<dim3(CC, BB), 256>>>(features);

    const dim3 gg(NCOL/128, 2);
    // SA layer 1: K=288 (9 chunks) -> split planes
    mma_gemm_kernel<<<gg, 256, SMT>>>(
        (const __half*)pW1a, (const __half*)pW1b, KP, KP/32,
        (const __half*)pX1a, (const __half*)pX1b, NCOL,
        (__half*)pA1a, (__half*)pA1b, NCOL,
        nullptr, nullptr,
        sa_gamma+0, sa_beta+0, sa_mean+0, sa_var+0, 0);
    // SA layer 2
    mma_gemm_kernel<<<gg, 256, SMT>>>(
        (const __half*)pW2a, (const __half*)pW2b, CC, CC/32,
        (const __half*)pA1a, (const __half*)pA1b, NCOL,
        (__half*)pA2a, (__half*)pA2b, NCOL,
        nullptr, nullptr,
        sa_gamma+256, sa_beta+256, sa_mean+256, sa_var+256, 0);
    // SA layer 3 -> fused maxpool -> Y split planes
    mma_gemm_kernel<<<gg, 256, SMT>>>(
        (const __half*)pW3a, (const __half*)pW3b, CC, CC/32,
        (const __half*)pA2a, (const __half*)pA2b, NCOL,
        (__half*)pYa, (__half*)pYb, NP,
        nullptr, nullptr,
        sa_gamma+512, sa_beta+512, sa_mean+512, sa_var+512, 1);

    const dim3 gf(NP/128, 2);
    // FC1
    mma_gemm_kernel<<<gf, 256, SMT>>>(
        (const __half*)pP1a, (const __half*)pP1b, CC, CC/32,
        (const __half*)pYa, (const __half*)pYb, NP,
        (__half*)pY2a, (__half*)pY2b, NP,
        nullptr, nullptr,
        p_gamma+0, p_beta+0, p_mean+0, p_var+0, 0);
    // FC2
    mma_gemm_kernel<<<gf, 256, SMT>>>(
        (const __half*)pP2a, (const __half*)pP2b, CC, CC/32,
        (const __half*)pY2a, (const __half*)pY2b, NP,
        (__half*)pY3a, (__half*)pY3b, NP,
        nullptr, nullptr,
        p_gamma+256, p_beta+256, p_mean+256, p_var+256, 0);
    // FC3 (head conv): 128 padded rows, fp32 + bias, no relu
    mma_gemm_kernel<<<dim3(NP/128, 1), 256, SMT>>>(
        (const __half*)pP3a, (const __half*)pP3b, CC, CC/32,
        (const __half*)pY3a, (const __half*)pY3b, NP,
        nullptr, nullptr, NP,
        (float*)pNET, (const float*)pB3P,
        nullptr, nullptr, nullptr, nullptr, 2);

    head_kernel<<<NP/256, 256>>>(msa, out);
}

// round 8
// speedup vs baseline: 2.3014x; 1.0848x over previous
#include <cuda_runtime.h>
#include <cuda_fp16.h>
#include <math.h>
#include <cstdint>

// ---------------- problem constants ----------------
#define BB 32
#define KK 2048
#define CC 256
#define PP 256
#define SS 16
#define NCOL (BB*PP*SS)      // 131072
#define NP   (BB*PP)         // 8192
#define NPTS (BB*KK)         // 65536 distinct (b,point) columns
#define OUTC 119
#define MP3  128             // p_w3 M padded

// output section offsets (floats)
#define OFF_OBJ      0
#define OFF_CENTER   16384
#define OFF_SS       40960
#define OFF_SRES     188416
#define OFF_PSIZE    630784
#define OFF_SEM      655360
#define OFF_CORN     802816
#define OFF_SLOG     999424
#define OFF_OPROB    1155072
#define OFF_SPROB    1163264

// ---------------- scratch (device globals; zero-init guaranteed) ----------------
__device__ __align__(16) __half g_FTa[(size_t)NPTS * CC];  // features^T hi plane [n][c]
__device__ __align__(16) __half g_FTb[(size_t)NPTS * CC];  // lo plane
__device__ __align__(16) __half g_Za [(size_t)NPTS * CC];  // Z = FT @ W1f^T, [n][oc]
__device__ __align__(16) __half g_Zb [(size_t)NPTS * CC];
__device__ __align__(16) __half g_A1a[(size_t)CC * NCOL];
__device__ __align__(16) __half g_A1b[(size_t)CC * NCOL];
__device__ __align__(16) __half g_A2a[(size_t)CC * NCOL];
__device__ __align__(16) __half g_A2b[(size_t)CC * NCOL];
__device__ __half g_W1Ta[CC*CC], g_W1Tb[CC*CC];   // W1 feature part, transposed [c][oc]
__device__ __half g_W2a[CC*CC], g_W2b[CC*CC];
__device__ __half g_W3a[CC*CC], g_W3b[CC*CC];
__device__ __half g_P1a[CC*CC], g_P1b[CC*CC];
__device__ __half g_P2a[CC*CC], g_P2b[CC*CC];
__device__ __half g_P3a[MP3*CC], g_P3b[MP3*CC];
__device__ float  g_B3P[MP3];
__device__ __half g_Ya [CC*NP], g_Yb [CC*NP];
__device__ __half g_Y2a[CC*NP], g_Y2b[CC*NP];
__device__ __half g_Y3a[CC*NP], g_Y3b[CC*NP];
__device__ float  g_NET[MP3 * NP];
__device__ float  g_NX[NP * 3];
__device__ float  g_GX[3 * NCOL];   // normalized grouped xyz (fp32)
__device__ int    g_IDX[NP * SS];

// ---------------- asm helpers (base-target: sm_80+) ----------------
__device__ __forceinline__ uint32_t smem_u32(const void* p){
    uint32_t a;
    asm("{ .reg .u64 t; cvta.to.shared.u64 t, %1; cvt.u32.u64 %0, t; }" : "=r"(a) : "l"(p));
    return a;
}
#define CP16(dst, src)  asm volatile("cp.async.cg.shared.global [%0], [%1], 16;" :: "r"(dst), "l"(src))
#define CP_COMMIT()     asm volatile("cp.async.commit_group;" ::: "memory")
#define CP_WAIT2()      asm volatile("cp.async.wait_group 2;" ::: "memory")
#define CP_WAIT1()      asm volatile("cp.async.wait_group 1;" ::: "memory")
#define CP_WAIT0()      asm volatile("cp.async.wait_group 0;" ::: "memory")

#define LDSM_X4(R, addr) \
    asm volatile("ldmatrix.sync.aligned.m8n8.x4.shared.b16 {%0,%1,%2,%3}, [%4];" \
        : "=r"((R)[0]),"=r"((R)[1]),"=r"((R)[2]),"=r"((R)[3]) : "r"(addr))
#define LDSM_X4T(R, addr) \
    asm volatile("ldmatrix.sync.aligned.m8n8.x4.trans.shared.b16 {%0,%1,%2,%3}, [%4];" \
        : "=r"((R)[0]),"=r"((R)[1]),"=r"((R)[2]),"=r"((R)[3]) : "r"(addr))

#define MMA_F16(C, A, b0, b1) \
    asm volatile("mma.sync.aligned.m16n8k16.row.col.f32.f16.f16.f32 " \
        "{%0,%1,%2,%3}, {%4,%5,%6,%7}, {%8,%9}, {%0,%1,%2,%3};" \
        : "+f"((C)[0]),"+f"((C)[1]),"+f"((C)[2]),"+f"((C)[3]) \
        : "r"((A)[0]),"r"((A)[1]),"r"((A)[2]),"r"((A)[3]), "r"(b0),"r"(b1))

// ---------------- misc helpers ----------------
__device__ __forceinline__ float d2_nofma(float ax,float ay,float az,float bx,float by,float bz){
    float dx=ax-bx, dy=ay-by, dz=az-bz;
    return __fadd_rn(__fadd_rn(__fmul_rn(dx,dx),__fmul_rn(dy,dy)),__fmul_rn(dz,dz));
}
__device__ __forceinline__ void split2(float v, __half& h, __half& l){
    h = __float2half(v);
    l = __float2half(v - __half2float(h));
}

// ---------------- FPS: one block per batch, redux argmax, single barrier ----------------
__global__ __launch_bounds__(1024) void fps_kernel(const float* __restrict__ xyz)
{
    __shared__ float sx[KK], sy[KK], sz[KK];
    __shared__ unsigned rv[2][32]; __shared__ int ri[2][32];
    const int b = blockIdx.x, tid = threadIdx.x;
    const float* xb = xyz + (size_t)b*KK*3;
    for (int i=tid;i<KK;i+=1024){ sx[i]=xb[i*3+0]; sy[i]=xb[i*3+1]; sz[i]=xb[i*3+2]; }
    __syncthreads();
    const int i0 = tid, i1 = tid + 1024;
    float d0 = 1e10f, d1 = 1e10f;
    int far = 0;
    const float x0=sx[i0], y0=sy[i0], z0=sz[i0];
    const float x1=sx[i1], y1=sy[i1], z1=sz[i1];
    const int w = tid>>5, lane = tid&31;
    for (int it=0; it<PP; ++it){
        if (tid==0){
            g_NX[(b*PP+it)*3+0]=sx[far];
            g_NX[(b*PP+it)*3+1]=sy[far];
            g_NX[(b*PP+it)*3+2]=sz[far];
        }
        const float cx=sx[far], cy=sy[far], cz=sz[far];
        d0 = fminf(d0, d2_nofma(x0,y0,z0,cx,cy,cz));
        d1 = fminf(d1, d2_nofma(x1,y1,z1,cx,cy,cz));
        float bv = d0; int bi = i0;
        if (d1 > bv){ bv=d1; bi=i1; }
        const unsigned vbits = __float_as_uint(bv);
        const unsigned vmax  = __reduce_max_sync(0xffffffffu, vbits);
        const unsigned cand  = (vbits == vmax) ? (unsigned)bi : 0xFFFFFFFFu;
        const unsigned imin  = __reduce_min_sync(0xffffffffu, cand);
        const int pb = it & 1;
        if (lane==0){ rv[pb][w]=vmax; ri[pb][w]=(int)imin; }
        __syncthreads();
        // every warp redundantly reduces the 32 warp winners (no 2nd barrier;
        // parity buffers + the single barrier order reuse safely)
        const unsigned vb = rv[pb][lane]; const int ib = ri[pb][lane];
        const unsigned vmax2 = __reduce_max_sync(0xffffffffu, vb);
        const unsigned cand2 = (vb == vmax2) ? (unsigned)ib : 0xFFFFFFFFu;
        far = (int)__reduce_min_sync(0xffffffffu, cand2);
    }
}

// ---------------- ball query + fused normalized-xyz emit (fp32) ----------------
__global__ __launch_bounds__(256) void ballq_kernel(const float* __restrict__ xyz)
{
    __shared__ float sx[KK], sy[KK], sz[KK];
    __shared__ int sidx[8][SS];
    const int b = blockIdx.x >> 5;
    const float* xb = xyz + (size_t)b*KK*3;
    for (int i=threadIdx.x;i<KK;i+=256){ sx[i]=xb[i*3+0]; sy[i]=xb[i*3+1]; sz[i]=xb[i*3+2]; }
    __syncthreads();
    const int warp = threadIdx.x>>5, lane = threadIdx.x&31;
    const int w = blockIdx.x*8 + warp;
    const float cx=g_NX[w*3+0], cy=g_NX[w*3+1], cz=g_NX[w*3+2];
    int cnt=0, firstIdx=0; bool haveFirst=false;
    for (int j=0;j<KK;j+=32){
        const int i = j + lane;
        const float dd = d2_nofma(sx[i],sy[i],sz[i],cx,cy,cz);
        const bool within = dd < 0.09f;
        const unsigned mask = __ballot_sync(0xffffffffu, within);
        if (mask){
            if (!haveFirst){ firstIdx = j + __ffs(mask) - 1; haveFirst=true; }
            const int rank = __popc(mask & ((1u<<lane)-1u));
            if (within && (cnt+rank) < SS) sidx[warp][cnt+rank] = i;
            cnt += __popc(mask);
            if (cnt >= SS) break;
        }
    }
    if (cnt < SS && lane >= cnt && lane < SS) sidx[warp][lane] = firstIdx;
    __syncwarp();
    if (lane < SS){
        const int i = sidx[warp][lane];
        const int t = w*SS + lane;
        g_IDX[t] = i;
        g_GX[0*NCOL + t] = (sx[i]-cx) / 0.3f;
        g_GX[1*NCOL + t] = (sy[i]-cy) / 0.3f;
        g_GX[2*NCOL + t] = (sz[i]-cz) / 0.3f;
    }
}

// ---------------- merged weight prep ----------------
#define PR_W1T_END (CC*CC)                       // 65536 (W1 feature part, transposed)
#define PR_W2_END  (PR_W1T_END + CC*CC)
#define PR_W3_END  (PR_W2_END + CC*CC)
#define PR_P1_END  (PR_W3_END + CC*CC)
#define PR_P2_END  (PR_P1_END + CC*CC)
#define PR_P3_END  (PR_P2_END + MP3*CC)
#define PR_TOTAL   (PR_P3_END + MP3)

__global__ void prep_all(const float* __restrict__ w1, const float* __restrict__ w2,
                         const float* __restrict__ w3, const float* __restrict__ q1,
                         const float* __restrict__ q2, const float* __restrict__ q3,
                         const float* __restrict__ b3)
{
    const int t = blockIdx.x*256 + threadIdx.x;
    if (t >= PR_TOTAL) return;
    if (t >= PR_P3_END){ const int k = t - PR_P3_END; g_B3P[k] = (k < OUTC) ? b3[k] : 0.0f; return; }
    float v; __half *da, *db; int idx;
    if (t < PR_W1T_END){
        idx = t;
        const int c = idx >> 8, oc = idx & 255;          // [c][oc]
        v = w1[oc*259 + 3 + c];
        da=g_W1Ta; db=g_W1Tb;
    } else if (t < PR_W2_END){ idx=t-PR_W1T_END; v=w2[idx]; da=g_W2a; db=g_W2b; }
    else if (t < PR_W3_END){ idx=t-PR_W2_END; v=w3[idx]; da=g_W3a; db=g_W3b; }
    else if (t < PR_P1_END){ idx=t-PR_W3_END; v=q1[idx]; da=g_P1a; db=g_P1b; }
    else if (t < PR_P2_END){ idx=t-PR_P1_END; v=q2[idx]; da=g_P2a; db=g_P2b; }
    else {
        idx = t-PR_P2_END;
        const int m = idx >> 8;
        v = (m < OUTC) ? q3[idx] : 0.0f;
        da=g_P3a; db=g_P3b;
    }
    __half h,l; split2(v,h,l);
    da[idx]=h; db[idx]=l;
}

// ---------------- featT: features [b][c][j] fp32 -> FT planes [b*2048+j][c] ----------------
__global__ __launch_bounds__(256) void featT_kernel(const float* __restrict__ features)
{
    __shared__ float tile[32][33];
    const int jt = blockIdx.x*32, ct = blockIdx.y*32, b = blockIdx.z;
    const int tid = threadIdx.x;
    {
        const int cl = tid >> 3, j4 = (tid & 7)*4;
        const float4 v = *reinterpret_cast<const float4*>(
            &features[((size_t)b*CC + ct+cl)*KK + jt + j4]);
        tile[cl][j4+0]=v.x; tile[cl][j4+1]=v.y; tile[cl][j4+2]=v.z; tile[cl][j4+3]=v.w;
    }
    __syncthreads();
    {
        const int jl = tid >> 3, c4 = (tid & 7)*4;
        const size_t base = ((size_t)(b*KK + jt + jl))*CC + ct + c4;
        __half ha,la,hb,lb,hc,lc,hd,ld;
        split2(tile[c4+0][jl], ha, la);
        split2(tile[c4+1][jl], hb, lb);
        split2(tile[c4+2][jl], hc, lc);
        split2(tile[c4+3][jl], hd, ld);
        __half2 x;
        x.x=ha; x.y=hb; *reinterpret_cast<__half2*>(&g_FTa[base+0]) = x;
        x.x=hc; x.y=hd; *reinterpret_cast<__half2*>(&g_FTa[base+2]) = x;
        x.x=la; x.y=lb; *reinterpret_cast<__half2*>(&g_FTb[base+0]) = x;
        x.x=lc; x.y=ld; *reinterpret_cast<__half2*>(&g_FTb[base+2]) = x;
    }
}

// ---------------- asm1: gather Z rows + xyz term + BN/ReLU -> A1 planes ----------------
#define ACOLS 128
__global__ __launch_bounds__(256) void asm1_kernel(const float* __restrict__ w1,
    const float* __restrict__ gamma, const float* __restrict__ beta,
    const float* __restrict__ mean,  const float* __restrict__ var)
{
    __shared__ float sW0[256], sW1[256], sW2[256];
    __shared__ float sScale[256], sShift[256];
    __shared__ float sG0[ACOLS], sG1[ACOLS], sG2[ACOLS];
    __shared__ int   sIdx[ACOLS];
    __shared__ float sT[64][ACOLS+4];
    const int tid = threadIdx.x;
    const int t0 = blockIdx.x * ACOLS;
    const int b  = t0 >> 12;
    {
        const int oc = tid;
        sW0[oc] = w1[oc*259 + 0];
        sW1[oc] = w1[oc*259 + 1];
        sW2[oc] = w1[oc*259 + 2];
        const float sc = gamma[oc]*rsqrtf(var[oc]+1e-5f);
        sScale[oc]=sc; sShift[oc]=beta[oc]-mean[oc]*sc;
    }
    if (tid < ACOLS) sIdx[tid] = g_IDX[t0 + tid];
    for (int i=tid; i<3*ACOLS; i+=256){
        const int r = i >> 7, c = i & 127;
        float v = g_GX[(size_t)r*NCOL + t0 + c];
        if (r==0) sG0[c]=v; else if (r==1) sG1[c]=v; else sG2[c]=v;
    }
    __syncthreads();

    const int cl = tid >> 1;            // column 0..127
    const int part = tid & 1;           // oc sub-half
    const int j = sIdx[cl];
    const size_t zbase = ((size_t)(b*KK + j))*CC;
    const float g0=sG0[cl], g1=sG1[cl], g2=sG2[cl];

    #pragma unroll
    for (int s=0; s<4; ++s){
        const int oc0 = s*64 + part*32;
        const uint4* ph = reinterpret_cast<const uint4*>(&g_Za[zbase + oc0]);
        const uint4* pl = reinterpret_cast<const uint4*>(&g_Zb[zbase + oc0]);
        #pragma unroll
        for (int q=0;q<4;q++){
            const uint4 hv = ph[q], lv = pl[q];
            const __half2* h2 = reinterpret_cast<const __half2*>(&hv);
            const __half2* l2 = reinterpret_cast<const __half2*>(&lv);
            #pragma unroll
            for (int e=0;e<4;e++){
                const float2 hf = __half22float2(h2[e]);
                const float2 lf = __half22float2(l2[e]);
                const int oc = oc0 + q*8 + e*2;
                float v0 = hf.x + lf.x + sW0[oc]*g0 + sW1[oc]*g1 + sW2[oc]*g2;
                float v1 = hf.y + lf.y + sW0[oc+1]*g0 + sW1[oc+1]*g1 + sW2[oc+1]*g2;
                v0 = fmaxf(v0*sScale[oc]   + sShift[oc],   0.f);
                v1 = fmaxf(v1*sScale[oc+1] + sShift[oc+1], 0.f);
                sT[oc   - s*64][cl] = v0;
                sT[oc+1 - s*64][cl] = v1;
            }
        }
        __syncthreads();
        {
            const int r = tid >> 2;              // 0..63
            const int cseg = (tid & 3) * 32;
            const int oc = s*64 + r;
            __half2* da = reinterpret_cast<__half2*>(&g_A1a[(size_t)oc*NCOL + t0 + cseg]);
            __half2* db = reinterpret_cast<__half2*>(&g_A1b[(size_t)oc*NCOL + t0 + cseg]);
            #pragma unroll
            for (int q=0;q<16;q++){
                const float va = sT[r][cseg + 2*q], vb = sT[r][cseg + 2*q + 1];
                __half ha,la,hb,lb;
                split2(va,ha,la); split2(vb,hb,lb);
                __half2 th; th.x=ha; th.y=hb; da[q]=th;
                __half2 tl; tl.x=la; tl.y=lb; db[q]=tl;
            }
        }
        __syncthreads();
    }
}

// ---------------- mma.sync fp16 GEMM (2-plane split, 3 products) ----------------
// CTA tile 128x128, 8 warps of 64x32, BK=32, 4-stage cp.async pipeline.
// mode 0: BN+ReLU -> split planes; mode 1: + fused 16-col maxpool;
// mode 2: +bias -> fp32; mode 3: identity -> split planes
#define A_PL 10240u
#define A_BUFS (2u*A_PL)
#define B_PL 8704u
#define B_BUFS (2u*B_PL)
#define BUFSZ (A_BUFS + B_BUFS)
#define SMT (4*BUFSZ)          // 151552

__global__ __launch_bounds__(256) void mma_gemm_kernel(
    const __half* __restrict__ Aa, const __half* __restrict__ Ab, int Kw, int nch,
    const __half* __restrict__ Ba, const __half* __restrict__ Bb, int ldB,
    __half* __restrict__ Oa, __half* __restrict__ Ob, int ldO,
    float* __restrict__ OutF, const float* __restrict__ bias,
    const float* __restrict__ gamma, const float* __restrict__ beta,
    const float* __restrict__ mean,  const float* __restrict__ var,
    int mode)
{
    extern __shared__ char smem[];
    const uint32_t sbase = smem_u32(smem);
    const int tid = threadIdx.x, lane = tid & 31, wid = tid >> 5;
    const int wm = wid & 1, wn = wid >> 1;
    const int n0 = blockIdx.x * 128;
    const int mbase = blockIdx.y * 128;

    const size_t aoff = (size_t)mbase * Kw;
    const __half* A0 = Aa + aoff;
    const __half* A1 = Ab + aoff;

    auto stage = [&](int c, int buf){
        const int k0 = c * 32;
        const uint32_t sA = sbase + buf*BUFSZ;
        const uint32_t sB = sA + A_BUFS;
        #pragma unroll
        for (int it=0; it<2; ++it){
            const int idx = it*256 + tid;
            const int m = idx >> 2, kg = (idx & 3) * 8;
            const uint32_t d = sA + (uint32_t)m*80u + (uint32_t)kg*2u;
            const size_t so = (size_t)m*Kw + k0 + kg;
            CP16(d,        A0 + so);
            CP16(d + A_PL, A1 + so);
        }
        #pragma unroll
        for (int it=0; it<2; ++it){
            const int idx = it*256 + tid;
            const int k = idx >> 4, ng = (idx & 15) * 8;
            const uint32_t d = sB + (uint32_t)k*272u + (uint32_t)ng*2u;
            const size_t so = (size_t)(k0+k)*ldB + n0 + ng;
            CP16(d,        Ba + so);
            CP16(d + B_PL, Bb + so);
        }
    };

    float acc[4][4][4] = {};

    const uint32_t aRow = (uint32_t)((wm*64 + (lane & 15)) * 80) + (uint32_t)(((lane >> 4) << 3) * 2);
    const uint32_t bRow = (uint32_t)(((((lane >> 3) & 1) << 3) + (lane & 7)) * 272)
                        + (uint32_t)((wn*32 + ((lane >> 4) << 3)) * 2);

    auto compute_chunk = [&](int buf){
        const uint32_t aB = sbase + buf*BUFSZ;
        const uint32_t bB = aB + A_BUFS;
        #pragma unroll
        for (int ks=0; ks<2; ++ks){
            uint32_t bfr[2][2][4];
            #pragma unroll
            for (int p=0; p<2; ++p)
                #pragma unroll
                for (int n2=0; n2<2; ++n2)
                    LDSM_X4T(bfr[p][n2], bB + p*B_PL + bRow + (uint32_t)(ks*16*272) + (uint32_t)(n2*32));
            #pragma unroll
            for (int mh=0; mh<2; ++mh){
                uint32_t afr[2][2][4];
                #pragma unroll
                for (int p=0; p<2; ++p)
                    #pragma unroll
                    for (int m2=0; m2<2; ++m2)
                        LDSM_X4(afr[p][m2], aB + p*A_PL + aRow + (uint32_t)((mh*2+m2)*16*80) + (uint32_t)(ks*32));
                #pragma unroll
                for (int m2=0; m2<2; ++m2){
                    const int mi = mh*2 + m2;
                    #pragma unroll
                    for (int ni=0; ni<4; ++ni){
                        const int n2 = ni >> 1, q = (ni & 1) * 2;
                        float* C = acc[mi][ni];
                        MMA_F16(C, afr[0][m2], bfr[0][n2][q], bfr[0][n2][q+1]); // h*h
                        MMA_F16(C, afr[0][m2], bfr[1][n2][q], bfr[1][n2][q+1]); // h*l
                        MMA_F16(C, afr[1][m2], bfr[0][n2][q], bfr[0][n2][q+1]); // l*h
                    }
                }
            }
        }
    };

    stage(0, 0); CP_COMMIT();
    stage(1, 1); CP_COMMIT();
    for (int c=0; c<nch; ++c){
        if (c+2 < nch){ stage(c+2, (c+2)&3); CP_COMMIT(); CP_WAIT2(); }
        else if (c+1 < nch){ CP_WAIT1(); }
        else { CP_WAIT0(); }
        __syncthreads();
        compute_chunk(c & 3);
    }

    // ---- epilogue ----
    #pragma unroll
    for (int mi=0; mi<4; ++mi){
        const int mlo = mbase + wm*64 + mi*16 + (lane >> 2);
        const int mhi = mlo + 8;
        float s0, h0, s1, h1;
        if (mode == 2){
            s0 = 1.f; h0 = bias[mlo];
            s1 = 1.f; h1 = bias[mhi];
        } else if (mode == 3){
            s0 = 1.f; h0 = 0.f; s1 = 1.f; h1 = 0.f;
        } else {
            s0 = gamma[mlo] * rsqrtf(var[mlo] + 1e-5f);
            h0 = beta[mlo] - mean[mlo]*s0;
            s1 = gamma[mhi] * rsqrtf(var[mhi] + 1e-5f);
            h1 = beta[mhi] - mean[mhi]*s1;
        }
        float vlo[4][2], vhi[4][2];
        #pragma unroll
        for (int ni=0; ni<4; ++ni){
            vlo[ni][0] = acc[mi][ni][0]*s0 + h0;
            vlo[ni][1] = acc[mi][ni][1]*s0 + h0;
            vhi[ni][0] = acc[mi][ni][2]*s1 + h1;
            vhi[ni][1] = acc[mi][ni][3]*s1 + h1;
            if (mode == 0 || mode == 1){
                vlo[ni][0]=fmaxf(vlo[ni][0],0.f); vlo[ni][1]=fmaxf(vlo[ni][1],0.f);
                vhi[ni][0]=fmaxf(vhi[ni][0],0.f); vhi[ni][1]=fmaxf(vhi[ni][1],0.f);
            }
        }
        if (mode == 1){
            #pragma unroll
            for (int g=0; g<2; ++g){
                float pl = fmaxf(fmaxf(vlo[2*g][0],vlo[2*g][1]), fmaxf(vlo[2*g+1][0],vlo[2*g+1][1]));
                float ph = fmaxf(fmaxf(vhi[2*g][0],vhi[2*g][1]), fmaxf(vhi[2*g+1][0],vhi[2*g+1][1]));
                #pragma unroll
                for (int off=1; off<4; off<<=1){
                    pl = fmaxf(pl, __shfl_xor_sync(0xffffffffu, pl, off));
                    ph = fmaxf(ph, __shfl_xor_sync(0xffffffffu, ph, off));
                }
                if ((lane & 3) == 0){
                    const int p = (n0 >> 4) + wn*2 + g;
                    __half hh, hl;
                    split2(pl, hh, hl);
                    Oa[(size_t)mlo*NP + p] = hh; Ob[(size_t)mlo*NP + p] = hl;
                    split2(ph, hh, hl);
                    Oa[(size_t)mhi*NP + p] = hh; Ob[(size_t)mhi*NP + p] = hl;
                }
            }
        } else if (mode == 2){
            #pragma unroll
            for (int ni=0; ni<4; ++ni){
                const int n = n0 + wn*32 + ni*8 + (lane & 3)*2;
                *reinterpret_cast<float2*>(&OutF[(size_t)mlo*ldO + n]) = make_float2(vlo[ni][0], vlo[ni][1]);
                *reinterpret_cast<float2*>(&OutF[(size_t)mhi*ldO + n]) = make_float2(vhi[ni][0], vhi[ni][1]);
            }
        } else {
            #pragma unroll
            for (int ni=0; ni<4; ++ni){
                const int n = n0 + wn*32 + ni*8 + (lane & 3)*2;
                const size_t ilo = (size_t)mlo*ldO + n, ihi = (size_t)mhi*ldO + n;
                __half ha0,la0, ha1,la1, hb0,lb0, hb1,lb1;
                split2(vlo[ni][0], ha0, la0); split2(vlo[ni][1], ha1, la1);
                split2(vhi[ni][0], hb0, lb0); split2(vhi[ni][1], hb1, lb1);
                __half2 t;
                t.x=ha0; t.y=ha1; *reinterpret_cast<__half2*>(&Oa[ilo]) = t;
                t.x=la0; t.y=la1; *reinterpret_cast<__half2*>(&Ob[ilo]) = t;
                t.x=hb0; t.y=hb1; *reinterpret_cast<__half2*>(&Oa[ihi]) = t;
                t.x=lb0; t.y=lb1; *reinterpret_cast<__half2*>(&Ob[ihi]) = t;
            }
        }
    }
}

// ---------------- head ----------------
__global__ __launch_bounds__(256) void head_kernel(const float* __restrict__ msa,
                                                   float* __restrict__ out)
{
    const int t = blockIdx.x*256 + threadIdx.x;
    #define NT(j) g_NET[(j)*NP + t]
    const float obj0 = NT(0), obj1 = NT(1);
    out[OFF_OBJ + t*2 + 0] = obj0;
    out[OFF_OBJ + t*2 + 1] = obj1;
    const float c0 = g_NX[t*3+0] + NT(2);
    const float c1 = g_NX[t*3+1] + NT(3);
    const float c2 = g_NX[t*3+2] + NT(4);
    out[OFF_CENTER + t*3 + 0] = c0;
    out[OFF_CENTER + t*3 + 1] = c1;
    out[OFF_CENTER + t*3 + 2] = c2;

    float ss[18];
    #pragma unroll
    for (int k=0;k<18;k++){ ss[k] = NT(29+k); out[OFF_SS + t*18 + k] = ss[k]; }
    int best = 0; float bv = ss[0];
    #pragma unroll
    for (int k=1;k<18;k++) if (ss[k] > bv){ bv = ss[k]; best = k; }

    float ps0=0.f, ps1=0.f, ps2=0.f;
    #pragma unroll
    for (int k=0;k<18;k++){
        const float m0=msa[k*3+0], m1=msa[k*3+1], m2=msa[k*3+2];
        const float r0 = NT(47+k*3+0)*m0;
        const float r1 = NT(47+k*3+1)*m1;
        const float r2 = NT(47+k*3+2)*m2;
        out[OFF_SRES + t*54 + k*3 + 0] = r0;
        out[OFF_SRES + t*54 + k*3 + 1] = r1;
        out[OFF_SRES + t*54 + k*3 + 2] = r2;
        if (k == best){ ps0 = r0+m0; ps1 = r1+m1; ps2 = r2+m2; }
    }
    out[OFF_PSIZE + t*3 + 0] = ps0;
    out[OFF_PSIZE + t*3 + 1] = ps1;
    out[OFF_PSIZE + t*3 + 2] = ps2;

    float sm[18];
    #pragma unroll
    for (int k=0;k<18;k++){ sm[k] = NT(101+k); out[OFF_SEM + t*18 + k] = sm[k]; }

    const float cc0 = c0, cc1 = c2, cc2 = -c1;
    const float hx = ps0*0.5f, hy = ps2*0.5f, hz = ps1*0.5f;
    const float SX[8]={1,1,-1,-1,1,1,-1,-1};
    const float SY[8]={1,1,1,1,-1,-1,-1,-1};
    const float SZ[8]={1,-1,-1,1,1,-1,-1,1};
    #pragma unroll
    for (int i=0;i<8;i++){
        out[OFF_CORN + t*24 + i*3 + 0] = cc0 + hx*SX[i];
        out[OFF_CORN + t*24 + i*3 + 1] = cc1 + hy*SY[i];
        out[OFF_CORN + t*24 + i*3 + 2] = cc2 + hz*SZ[i];
    }

    #pragma unroll
    for (int k=0;k<18;k++) out[OFF_SLOG + t*19 + k] = sm[k];
    out[OFF_SLOG + t*19 + 18] = (obj0 <= obj1) ? 0.0f : 1e10f;

    {
        const float mx = fmaxf(obj0,obj1);
        const float e0 = expf(obj0-mx), e1 = expf(obj1-mx);
        out[OFF_OPROB + t] = e1/(e0+e1);
    }
    {
        float mx = sm[0];
        #pragma unroll
        for (int k=1;k<18;k++) mx = fmaxf(mx, sm[k]);
        float e[18], ssum = 0.f;
        #pragma unroll
        for (int k=0;k<18;k++){ e[k] = expf(sm[k]-mx); ssum += e[k]; }
        #pragma unroll
        for (int k=0;k<18;k++) out[OFF_SPROB + t*18 + k] = e[k]/ssum;
    }
    #undef NT
}

// ---------------- host launcher ----------------
extern "C" void kernel_launch(void* const* d_in, const int* in_sizes, int n_in,
                              void* d_out, int out_size)
{
    const float* xyz      = (const float*)d_in[0];
    const float* features = (const float*)d_in[1];
    const float* sa_w1    = (const float*)d_in[2];
    const float* sa_w2    = (const float*)d_in[3];
    const float* sa_w3    = (const float*)d_in[4];
    const float* sa_gamma = (const float*)d_in[5];
    const float* sa_beta  = (const float*)d_in[6];
    const float* sa_mean  = (const float*)d_in[7];
    const float* sa_var   = (const float*)d_in[8];
    const float* p_w1     = (const float*)d_in[9];
    const float* p_w2     = (const float*)d_in[10];
    const float* p_w3     = (const float*)d_in[11];
    const float* p_b3     = (const float*)d_in[12];
    const float* p_gamma  = (const float*)d_in[13];
    const float* p_beta   = (const float*)d_in[14];
    const float* p_mean   = (const float*)d_in[15];
    const float* p_var    = (const float*)d_in[16];
    const float* msa      = (const float*)d_in[17];
    float* out = (float*)d_out;

    cudaFuncSetAttribute(mma_gemm_kernel, cudaFuncAttributeMaxDynamicSharedMemorySize, SMT);

    void *pFTa,*pFTb, *pZa,*pZb, *pA1a,*pA1b, *pA2a,*pA2b;
    void *pW1Ta,*pW1Tb, *pW2a,*pW2b, *pW3a,*pW3b;
    void *pP1a,*pP1b, *pP2a,*pP2b, *pP3a,*pP3b, *pB3P;
    void *pYa,*pYb, *pY2a,*pY2b, *pY3a,*pY3b, *pNET;
    cudaGetSymbolAddress(&pFTa, g_FTa); cudaGetSymbolAddress(&pFTb, g_FTb);
    cudaGetSymbolAddress(&pZa,  g_Za);  cudaGetSymbolAddress(&pZb,  g_Zb);
    cudaGetSymbolAddress(&pA1a, g_A1a); cudaGetSymbolAddress(&pA1b, g_A1b);
    cudaGetSymbolAddress(&pA2a, g_A2a); cudaGetSymbolAddress(&pA2b, g_A2b);
    cudaGetSymbolAddress(&pW1Ta, g_W1Ta); cudaGetSymbolAddress(&pW1Tb, g_W1Tb);
    cudaGetSymbolAddress(&pW2a, g_W2a); cudaGetSymbolAddress(&pW2b, g_W2b);
    cudaGetSymbolAddress(&pW3a, g_W3a); cudaGetSymbolAddress(&pW3b, g_W3b);
    cudaGetSymbolAddress(&pP1a, g_P1a); cudaGetSymbolAddress(&pP1b, g_P1b);
    cudaGetSymbolAddress(&pP2a, g_P2a); cudaGetSymbolAddress(&pP2b, g_P2b);
    cudaGetSymbolAddress(&pP3a, g_P3a); cudaGetSymbolAddress(&pP3b, g_P3b);
    cudaGetSymbolAddress(&pB3P, g_B3P);
    cudaGetSymbolAddress(&pYa,  g_Ya);  cudaGetSymbolAddress(&pYb,  g_Yb);
    cudaGetSymbolAddress(&pY2a, g_Y2a); cudaGetSymbolAddress(&pY2b, g_Y2b);
    cudaGetSymbolAddress(&pY3a, g_Y3a); cudaGetSymbolAddress(&pY3b, g_Y3b);
    cudaGetSymbolAddress(&pNET, g_NET);

    fps_kernel<<<BB, 1024>>>(xyz);
    prep_all<<<(PR_TOTAL + 255)/256, 256>>>(sa_w1, sa_w2, sa_w3, p_w1, p_w2, p_w3, p_b3);
    featT_kernel<<<dim3(KK/32, CC/32, BB), 256>>>(features);
    ballq_kernel<<<1024, 256>>>(xyz);

    // Z = FT @ W1f^T : M=65536, N=256, K=256, identity epilogue -> Z planes [n][oc]
    mma_gemm_kernel<<<dim3(2, NPTS/128), 256, SMT>>>(
        (const __half*)pFTa, (const __half*)pFTb, CC, CC/32,
        (const __half*)pW1Ta, (const __half*)pW1Tb, CC,
        (__half*)pZa, (__half*)pZb, CC,
        nullptr, nullptr,
        nullptr, nullptr, nullptr, nullptr, 3);

    // layer-1 assembly: gather Z + xyz term + BN/ReLU -> A1 planes
    asm1_kernel<<<NCOL/ACOLS, 256>>>(sa_w1, sa_gamma+0, sa_beta+0, sa_mean+0, sa_var+0);

    const dim3 gg(NCOL/128, 2);
    // SA layer 2
    mma_gemm_kernel<<<gg, 256, SMT>>>(
        (const __half*)pW2a, (const __half*)pW2b, CC, CC/32,
        (const __half*)pA1a, (const __half*)pA1b, NCOL,
        (__half*)pA2a, (__half*)pA2b, NCOL,
        nullptr, nullptr,
        sa_gamma+256, sa_beta+256, sa_mean+256, sa_var+256, 0);
    // SA layer 3 -> fused maxpool -> Y split planes
    mma_gemm_kernel<<<gg, 256, SMT>>>(
        (const __half*)pW3a, (const __half*)pW3b, CC, CC/32,
        (const __half*)pA2a, (const __half*)pA2b, NCOL,
        (__half*)pYa, (__half*)pYb, NP,
        nullptr, nullptr,
        sa_gamma+512, sa_beta+512, sa_mean+512, sa_var+512, 1);

    const dim3 gf(NP/128, 2);
    // FC1
    mma_gemm_kernel<<<gf, 256, SMT>>>(
        (const __half*)pP1a, (const __half*)pP1b, CC, CC/32,
        (const __half*)pYa, (const __half*)pYb, NP,
        (__half*)pY2a, (__half*)pY2b, NP,
        nullptr, nullptr,
        p_gamma+0, p_beta+0, p_mean+0, p_var+0, 0);
    // FC2
    mma_gemm_kernel<<<gf, 256, SMT>>>(
        (const __half*)pP2a, (const __half*)pP2b, CC, CC/32,
        (const __half*)pY2a, (const __half*)pY2b, NP,
        (__half*)pY3a, (__half*)pY3b, NP,
        nullptr, nullptr,
        p_gamma+256, p_beta+256, p_mean+256, p_var+256, 0);
    // FC3 (head conv): 128 padded rows, fp32 + bias, no relu
    mma_gemm_kernel<<<dim3(NP/128, 1), 256, SMT>>>(
        (const __half*)pP3a, (const __half*)pP3b, CC, CC/32,
        (const __half*)pY3a, (const __half*)pY3b, NP,
        nullptr, nullptr, NP,
        (float*)pNET, (const float*)pB3P,
        nullptr, nullptr, nullptr, nullptr, 2);

    head_kernel<<<NP/256, 256>>>(msa, out);
}

// round 9
// speedup vs baseline: 2.3025x; 1.0005x over previous
#include <cuda_runtime.h>
#include <cuda_fp16.h>
#include <math.h>
#include <cstdint>

// ---------------- problem constants ----------------
#define BB 32
#define KK 2048
#define CC 256
#define PP 256
#define SS 16
#define NCOL (BB*PP*SS)      // 131072
#define NP   (BB*PP)         // 8192
#define NPTS (BB*KK)         // 65536 distinct (b,point) columns
#define OUTC 119
#define MP3  128             // p_w3 M padded

// output section offsets (floats)
#define OFF_OBJ      0
#define OFF_CENTER   16384
#define OFF_SS       40960
#define OFF_SRES     188416
#define OFF_PSIZE    630784
#define OFF_SEM      655360
#define OFF_CORN     802816
#define OFF_SLOG     999424
#define OFF_OPROB    1155072
#define OFF_SPROB    1163264

// ---------------- scratch (device globals; zero-init guaranteed) ----------------
__device__ __align__(16) __half g_FTa[(size_t)NPTS * CC];  // features^T hi plane [n][c]
__device__ __align__(16) __half g_FTb[(size_t)NPTS * CC];  // lo plane
__device__ __align__(16) __half g_Za [(size_t)NPTS * CC];  // Z = FT @ W1f^T, [n][oc]
__device__ __align__(16) __half g_Zb [(size_t)NPTS * CC];
__device__ __align__(16) __half g_A1a[(size_t)CC * NCOL];
__device__ __align__(16) __half g_A1b[(size_t)CC * NCOL];
__device__ __align__(16) __half g_A2a[(size_t)CC * NCOL];
__device__ __align__(16) __half g_A2b[(size_t)CC * NCOL];
__device__ __half g_W1Ta[CC*CC], g_W1Tb[CC*CC];   // W1 feature part, transposed [c][oc]
__device__ __half g_W2a[CC*CC], g_W2b[CC*CC];
__device__ __half g_W3a[CC*CC], g_W3b[CC*CC];
__device__ __half g_P1a[CC*CC], g_P1b[CC*CC];
__device__ __half g_P2a[CC*CC], g_P2b[CC*CC];
__device__ __half g_P3a[MP3*CC], g_P3b[MP3*CC];
__device__ float  g_B3P[MP3];
__device__ __half g_Ya [CC*NP], g_Yb [CC*NP];
__device__ __half g_Y2a[CC*NP], g_Y2b[CC*NP];
__device__ __half g_Y3a[CC*NP], g_Y3b[CC*NP];
__device__ float  g_NET[MP3 * NP];
__device__ float  g_NX[NP * 3];
__device__ float  g_GX[3 * NCOL];   // normalized grouped xyz (fp32)
__device__ int    g_IDX[NP * SS];

// ---------------- asm helpers (base-target: sm_80+) ----------------
__device__ __forceinline__ uint32_t smem_u32(const void* p){
    uint32_t a;
    asm("{ .reg .u64 t; cvta.to.shared.u64 t, %1; cvt.u32.u64 %0, t; }" : "=r"(a) : "l"(p));
    return a;
}
#define CP16(dst, src)  asm volatile("cp.async.cg.shared.global [%0], [%1], 16;" :: "r"(dst), "l"(src))
#define CP_COMMIT()     asm volatile("cp.async.commit_group;" ::: "memory")
#define CP_WAIT2()      asm volatile("cp.async.wait_group 2;" ::: "memory")
#define CP_WAIT1()      asm volatile("cp.async.wait_group 1;" ::: "memory")
#define CP_WAIT0()      asm volatile("cp.async.wait_group 0;" ::: "memory")

#define LDSM_X4(R, addr) \
    asm volatile("ldmatrix.sync.aligned.m8n8.x4.shared.b16 {%0,%1,%2,%3}, [%4];" \
        : "=r"((R)[0]),"=r"((R)[1]),"=r"((R)[2]),"=r"((R)[3]) : "r"(addr))
#define LDSM_X4T(R, addr) \
    asm volatile("ldmatrix.sync.aligned.m8n8.x4.trans.shared.b16 {%0,%1,%2,%3}, [%4];" \
        : "=r"((R)[0]),"=r"((R)[1]),"=r"((R)[2]),"=r"((R)[3]) : "r"(addr))

#define MMA_F16(C, A, b0, b1) \
    asm volatile("mma.sync.aligned.m16n8k16.row.col.f32.f16.f16.f32 " \
        "{%0,%1,%2,%3}, {%4,%5,%6,%7}, {%8,%9}, {%0,%1,%2,%3};" \
        : "+f"((C)[0]),"+f"((C)[1]),"+f"((C)[2]),"+f"((C)[3]) \
        : "r"((A)[0]),"r"((A)[1]),"r"((A)[2]),"r"((A)[3]), "r"(b0),"r"(b1))

// ---------------- misc helpers ----------------
__device__ __forceinline__ float d2_nofma(float ax,float ay,float az,float bx,float by,float bz){
    float dx=ax-bx, dy=ay-by, dz=az-bz;
    return __fadd_rn(__fadd_rn(__fmul_rn(dx,dx),__fmul_rn(dy,dy)),__fmul_rn(dz,dz));
}
__device__ __forceinline__ void split2(float v, __half& h, __half& l){
    h = __float2half(v);
    l = __float2half(v - __half2float(h));
}

// ---------------- FPS: one block per batch, 256 thr x 8 pts, redux argmax ----------------
__global__ __launch_bounds__(256) void fps_kernel(const float* __restrict__ xyz)
{
    __shared__ float sx[KK], sy[KK], sz[KK];
    __shared__ unsigned rv[2][8]; __shared__ int ri[2][8];
    const int b = blockIdx.x, tid = threadIdx.x;
    const float* xb = xyz + (size_t)b*KK*3;
    for (int i=tid;i<KK;i+=256){ sx[i]=xb[i*3+0]; sy[i]=xb[i*3+1]; sz[i]=xb[i*3+2]; }
    __syncthreads();
    float px[8], py[8], pz[8], pd[8];
    #pragma unroll
    for (int k=0;k<8;k++){
        const int i = tid + k*256;
        px[k]=sx[i]; py[k]=sy[i]; pz[k]=sz[i]; pd[k]=1e10f;
    }
    int far = 0;
    const int w = tid>>5, lane = tid&31;
    for (int it=0; it<PP; ++it){
        if (tid==0){
            g_NX[(b*PP+it)*3+0]=sx[far];
            g_NX[(b*PP+it)*3+1]=sy[far];
            g_NX[(b*PP+it)*3+2]=sz[far];
        }
        const float cx=sx[far], cy=sy[far], cz=sz[far];
        float bv = -1.f; int bi = 0;
        #pragma unroll
        for (int k=0;k<8;k++){
            pd[k] = fminf(pd[k], d2_nofma(px[k],py[k],pz[k],cx,cy,cz));
            if (pd[k] > bv){ bv = pd[k]; bi = tid + k*256; }   // strict > keeps earliest idx
        }
        const unsigned vbits = __float_as_uint(bv);
        const unsigned vmax  = __reduce_max_sync(0xffffffffu, vbits);
        const unsigned cand  = (vbits == vmax) ? (unsigned)bi : 0xFFFFFFFFu;
        const unsigned imin  = __reduce_min_sync(0xffffffffu, cand);
        const int pb = it & 1;
        if (lane==0){ rv[pb][w]=vmax; ri[pb][w]=(int)imin; }
        __syncthreads();
        const unsigned vb = (lane<8) ? rv[pb][lane] : 0u;
        const int      ib = (lane<8) ? ri[pb][lane] : 0x7FFFFFFF;
        const unsigned vmax2 = __reduce_max_sync(0xffffffffu, vb);
        const unsigned cand2 = (vb == vmax2) ? (unsigned)ib : 0xFFFFFFFFu;
        far = (int)__reduce_min_sync(0xffffffffu, cand2);
    }
}

// ---------------- ball query + fused normalized-xyz emit (fp32) ----------------
__global__ __launch_bounds__(256) void ballq_kernel(const float* __restrict__ xyz)
{
    __shared__ float sx[KK], sy[KK], sz[KK];
    __shared__ int sidx[8][SS];
    const int b = blockIdx.x >> 5;
    const float* xb = xyz + (size_t)b*KK*3;
    for (int i=threadIdx.x;i<KK;i+=256){ sx[i]=xb[i*3+0]; sy[i]=xb[i*3+1]; sz[i]=xb[i*3+2]; }
    __syncthreads();
    const int warp = threadIdx.x>>5, lane = threadIdx.x&31;
    const int w = blockIdx.x*8 + warp;
    const float cx=g_NX[w*3+0], cy=g_NX[w*3+1], cz=g_NX[w*3+2];
    int cnt=0, firstIdx=0; bool haveFirst=false;
    for (int j=0;j<KK;j+=32){
        const int i = j + lane;
        const float dd = d2_nofma(sx[i],sy[i],sz[i],cx,cy,cz);
        const bool within = dd < 0.09f;
        const unsigned mask = __ballot_sync(0xffffffffu, within);
        if (mask){
            if (!haveFirst){ firstIdx = j + __ffs(mask) - 1; haveFirst=true; }
            const int rank = __popc(mask & ((1u<<lane)-1u));
            if (within && (cnt+rank) < SS) sidx[warp][cnt+rank] = i;
            cnt += __popc(mask);
            if (cnt >= SS) break;
        }
    }
    if (cnt < SS && lane >= cnt && lane < SS) sidx[warp][lane] = firstIdx;
    __syncwarp();
    if (lane < SS){
        const int i = sidx[warp][lane];
        const int t = w*SS + lane;
        g_IDX[t] = i;
        g_GX[0*NCOL + t] = (sx[i]-cx) / 0.3f;
        g_GX[1*NCOL + t] = (sy[i]-cy) / 0.3f;
        g_GX[2*NCOL + t] = (sz[i]-cz) / 0.3f;
    }
}

// ---------------- merged weight prep ----------------
#define PR_W1T_END (CC*CC)
#define PR_W2_END  (PR_W1T_END + CC*CC)
#define PR_W3_END  (PR_W2_END + CC*CC)
#define PR_P1_END  (PR_W3_END + CC*CC)
#define PR_P2_END  (PR_P1_END + CC*CC)
#define PR_P3_END  (PR_P2_END + MP3*CC)
#define PR_TOTAL   (PR_P3_END + MP3)

__global__ void prep_all(const float* __restrict__ w1, const float* __restrict__ w2,
                         const float* __restrict__ w3, const float* __restrict__ q1,
                         const float* __restrict__ q2, const float* __restrict__ q3,
                         const float* __restrict__ b3)
{
    const int t = blockIdx.x*256 + threadIdx.x;
    if (t >= PR_TOTAL) return;
    if (t >= PR_P3_END){ const int k = t - PR_P3_END; g_B3P[k] = (k < OUTC) ? b3[k] : 0.0f; return; }
    float v; __half *da, *db; int idx;
    if (t < PR_W1T_END){
        idx = t;
        const int c = idx >> 8, oc = idx & 255;
        v = w1[oc*259 + 3 + c];
        da=g_W1Ta; db=g_W1Tb;
    } else if (t < PR_W2_END){ idx=t-PR_W1T_END; v=w2[idx]; da=g_W2a; db=g_W2b; }
    else if (t < PR_W3_END){ idx=t-PR_W2_END; v=w3[idx]; da=g_W3a; db=g_W3b; }
    else if (t < PR_P1_END){ idx=t-PR_W3_END; v=q1[idx]; da=g_P1a; db=g_P1b; }
    else if (t < PR_P2_END){ idx=t-PR_P1_END; v=q2[idx]; da=g_P2a; db=g_P2b; }
    else {
        idx = t-PR_P2_END;
        const int m = idx >> 8;
        v = (m < OUTC) ? q3[idx] : 0.0f;
        da=g_P3a; db=g_P3b;
    }
    __half h,l; split2(v,h,l);
    da[idx]=h; db[idx]=l;
}

// ---------------- featT: features [b][c][j] fp32 -> FT planes [b*2048+j][c] ----------------
__global__ __launch_bounds__(256) void featT_kernel(const float* __restrict__ features)
{
    __shared__ float tile[32][33];
    const int jt = blockIdx.x*32, ct = blockIdx.y*32, b = blockIdx.z;
    const int tid = threadIdx.x;
    {
        const int cl = tid >> 3, j4 = (tid & 7)*4;
        const float4 v = *reinterpret_cast<const float4*>(
            &features[((size_t)b*CC + ct+cl)*KK + jt + j4]);
        tile[cl][j4+0]=v.x; tile[cl][j4+1]=v.y; tile[cl][j4+2]=v.z; tile[cl][j4+3]=v.w;
    }
    __syncthreads();
    {
        const int jl = tid >> 3, c4 = (tid & 7)*4;
        const size_t base = ((size_t)(b*KK + jt + jl))*CC + ct + c4;
        __half ha,la,hb,lb,hc,lc,hd,ld;
        split2(tile[c4+0][jl], ha, la);
        split2(tile[c4+1][jl], hb, lb);
        split2(tile[c4+2][jl], hc, lc);
        split2(tile[c4+3][jl], hd, ld);
        __half2 x;
        x.x=ha; x.y=hb; *reinterpret_cast<__half2*>(&g_FTa[base+0]) = x;
        x.x=hc; x.y=hd; *reinterpret_cast<__half2*>(&g_FTa[base+2]) = x;
        x.x=la; x.y=lb; *reinterpret_cast<__half2*>(&g_FTb[base+0]) = x;
        x.x=lc; x.y=ld; *reinterpret_cast<__half2*>(&g_FTb[base+2]) = x;
    }
}

// ---------------- asm1: gather Z rows + xyz term + BN/ReLU -> A1 planes ----------------
#define ACOLS 128
__global__ __launch_bounds__(256) void asm1_kernel(const float* __restrict__ w1,
    const float* __restrict__ gamma, const float* __restrict__ beta,
    const float* __restrict__ mean,  const float* __restrict__ var)
{
    __shared__ float sW0[256], sW1[256], sW2[256];
    __shared__ float sScale[256], sShift[256];
    __shared__ float sG0[ACOLS], sG1[ACOLS], sG2[ACOLS];
    __shared__ int   sIdx[ACOLS];
    __shared__ float sT[64][ACOLS+4];
    const int tid = threadIdx.x;
    const int t0 = blockIdx.x * ACOLS;
    const int b  = t0 >> 12;
    {
        const int oc = tid;
        sW0[oc] = w1[oc*259 + 0];
        sW1[oc] = w1[oc*259 + 1];
        sW2[oc] = w1[oc*259 + 2];
        const float sc = gamma[oc]*rsqrtf(var[oc]+1e-5f);
        sScale[oc]=sc; sShift[oc]=beta[oc]-mean[oc]*sc;
    }
    if (tid < ACOLS) sIdx[tid] = g_IDX[t0 + tid];
    for (int i=tid; i<3*ACOLS; i+=256){
        const int r = i >> 7, c = i & 127;
        float v = g_GX[(size_t)r*NCOL + t0 + c];
        if (r==0) sG0[c]=v; else if (r==1) sG1[c]=v; else sG2[c]=v;
    }
    __syncthreads();

    const int cl = tid >> 1;
    const int part = tid & 1;
    const int j = sIdx[cl];
    const size_t zbase = ((size_t)(b*KK + j))*CC;
    const float g0=sG0[cl], g1=sG1[cl], g2=sG2[cl];

    #pragma unroll
    for (int s=0; s<4; ++s){
        const int oc0 = s*64 + part*32;
        const uint4* ph = reinterpret_cast<const uint4*>(&g_Za[zbase + oc0]);
        const uint4* pl = reinterpret_cast<const uint4*>(&g_Zb[zbase + oc0]);
        #pragma unroll
        for (int q=0;q<4;q++){
            const uint4 hv = ph[q], lv = pl[q];
            const __half2* h2 = reinterpret_cast<const __half2*>(&hv);
            const __half2* l2 = reinterpret_cast<const __half2*>(&lv);
            #pragma unroll
            for (int e=0;e<4;e++){
                const float2 hf = __half22float2(h2[e]);
                const float2 lf = __half22float2(l2[e]);
                const int oc = oc0 + q*8 + e*2;
                float v0 = hf.x + lf.x + sW0[oc]*g0 + sW1[oc]*g1 + sW2[oc]*g2;
                float v1 = hf.y + lf.y + sW0[oc+1]*g0 + sW1[oc+1]*g1 + sW2[oc+1]*g2;
                v0 = fmaxf(v0*sScale[oc]   + sShift[oc],   0.f);
                v1 = fmaxf(v1*sScale[oc+1] + sShift[oc+1], 0.f);
                sT[oc   - s*64][cl] = v0;
                sT[oc+1 - s*64][cl] = v1;
            }
        }
        __syncthreads();
        {
            const int r = tid >> 2;
            const int cseg = (tid & 3) * 32;
            const int oc = s*64 + r;
            __half2* da = reinterpret_cast<__half2*>(&g_A1a[(size_t)oc*NCOL + t0 + cseg]);
            __half2* db = reinterpret_cast<__half2*>(&g_A1b[(size_t)oc*NCOL + t0 + cseg]);
            #pragma unroll
            for (int q=0;q<16;q++){
                const float va = sT[r][cseg + 2*q], vb = sT[r][cseg + 2*q + 1];
                __half ha,la,hb,lb;
                split2(va,ha,la); split2(vb,hb,lb);
                __half2 th; th.x=ha; th.y=hb; da[q]=th;
                __half2 tl; tl.x=la; tl.y=lb; db[q]=tl;
            }
        }
        __syncthreads();
    }
}

// ---------------- shared GEMM geometry ----------------
#define A_PL 10240u
#define A_BUFS (2u*A_PL)       // hi+lo per stage (20480)
#define B_PL 8704u
#define B_BUFS (2u*B_PL)       // 17408
#define BUFSZ (A_BUFS + B_BUFS)
#define SMT (4*BUFSZ)          // 151552 (streaming kernel)
#define B_CH (2u*B_PL)         // 17408 per resident chunk (hi+lo)
#define BRES_B (8u*B_CH)       // 139264
#define SMT2 (BRES_B + 4u*A_BUFS)  // 221184 (B-resident kernel)

// ---------------- streaming mma kernel (Z, FC1, FC2, FC3) ----------------
// mode 0: BN+ReLU -> split planes; mode 2: +bias -> fp32; mode 3: identity -> split planes
__global__ __launch_bounds__(256) void mma_gemm_kernel(
    const __half* __restrict__ Aa, const __half* __restrict__ Ab, int Kw, int nch,
    const __half* __restrict__ Ba, const __half* __restrict__ Bb, int ldB,
    __half* __restrict__ Oa, __half* __restrict__ Ob, int ldO,
    float* __restrict__ OutF, const float* __restrict__ bias,
    const float* __restrict__ gamma, const float* __restrict__ beta,
    const float* __restrict__ mean,  const float* __restrict__ var,
    int mode)
{
    extern __shared__ char smem[];
    const uint32_t sbase = smem_u32(smem);
    const int tid = threadIdx.x, lane = tid & 31, wid = tid >> 5;
    const int wm = wid & 1, wn = wid >> 1;
    const int n0 = blockIdx.x * 128;
    const int mbase = blockIdx.y * 128;

    const size_t aoff = (size_t)mbase * Kw;
    const __half* A0 = Aa + aoff;
    const __half* A1 = Ab + aoff;

    auto stage = [&](int c, int buf){
        const int k0 = c * 32;
        const uint32_t sA = sbase + buf*BUFSZ;
        const uint32_t sB = sA + A_BUFS;
        #pragma unroll
        for (int it=0; it<2; ++it){
            const int idx = it*256 + tid;
            const int m = idx >> 2, kg = (idx & 3) * 8;
            const uint32_t d = sA + (uint32_t)m*80u + (uint32_t)kg*2u;
            const size_t so = (size_t)m*Kw + k0 + kg;
            CP16(d,        A0 + so);
            CP16(d + A_PL, A1 + so);
        }
        #pragma unroll
        for (int it=0; it<2; ++it){
            const int idx = it*256 + tid;
            const int k = idx >> 4, ng = (idx & 15) * 8;
            const uint32_t d = sB + (uint32_t)k*272u + (uint32_t)ng*2u;
            const size_t so = (size_t)(k0+k)*ldB + n0 + ng;
            CP16(d,        Ba + so);
            CP16(d + B_PL, Bb + so);
        }
    };

    float acc[4][4][4] = {};

    const uint32_t aRow = (uint32_t)((wm*64 + (lane & 15)) * 80) + (uint32_t)(((lane >> 4) << 3) * 2);
    const uint32_t bRow = (uint32_t)(((((lane >> 3) & 1) << 3) + (lane & 7)) * 272)
                        + (uint32_t)((wn*32 + ((lane >> 4) << 3)) * 2);

    auto compute_chunk = [&](int buf){
        const uint32_t aB = sbase + buf*BUFSZ;
        const uint32_t bB = aB + A_BUFS;
        #pragma unroll
        for (int ks=0; ks<2; ++ks){
            uint32_t bfr[2][2][4];
            #pragma unroll
            for (int p=0; p<2; ++p)
                #pragma unroll
                for (int n2=0; n2<2; ++n2)
                    LDSM_X4T(bfr[p][n2], bB + p*B_PL + bRow + (uint32_t)(ks*16*272) + (uint32_t)(n2*32));
            #pragma unroll
            for (int mh=0; mh<2; ++mh){
                uint32_t afr[2][2][4];
                #pragma unroll
                for (int p=0; p<2; ++p)
                    #pragma unroll
                    for (int m2=0; m2<2; ++m2)
                        LDSM_X4(afr[p][m2], aB + p*A_PL + aRow + (uint32_t)((mh*2+m2)*16*80) + (uint32_t)(ks*32));
                #pragma unroll
                for (int m2=0; m2<2; ++m2){
                    const int mi = mh*2 + m2;
                    #pragma unroll
                    for (int ni=0; ni<4; ++ni){
                        const int n2 = ni >> 1, q = (ni & 1) * 2;
                        float* C = acc[mi][ni];
                        MMA_F16(C, afr[0][m2], bfr[0][n2][q], bfr[0][n2][q+1]);
                        MMA_F16(C, afr[0][m2], bfr[1][n2][q], bfr[1][n2][q+1]);
                        MMA_F16(C, afr[1][m2], bfr[0][n2][q], bfr[0][n2][q+1]);
                    }
                }
            }
        }
    };

    stage(0, 0); CP_COMMIT();
    stage(1, 1); CP_COMMIT();
    for (int c=0; c<nch; ++c){
        if (c+2 < nch){ stage(c+2, (c+2)&3); CP_COMMIT(); CP_WAIT2(); }
        else if (c+1 < nch){ CP_WAIT1(); }
        else { CP_WAIT0(); }
        __syncthreads();
        compute_chunk(c & 3);
    }

    // ---- epilogue ----
    #pragma unroll
    for (int mi=0; mi<4; ++mi){
        const int mlo = mbase + wm*64 + mi*16 + (lane >> 2);
        const int mhi = mlo + 8;
        float s0, h0, s1, h1;
        if (mode == 2){
            s0 = 1.f; h0 = bias[mlo];
            s1 = 1.f; h1 = bias[mhi];
        } else if (mode == 3){
            s0 = 1.f; h0 = 0.f; s1 = 1.f; h1 = 0.f;
        } else {
            s0 = gamma[mlo] * rsqrtf(var[mlo] + 1e-5f);
            h0 = beta[mlo] - mean[mlo]*s0;
            s1 = gamma[mhi] * rsqrtf(var[mhi] + 1e-5f);
            h1 = beta[mhi] - mean[mhi]*s1;
        }
        float vlo[4][2], vhi[4][2];
        #pragma unroll
        for (int ni=0; ni<4; ++ni){
            vlo[ni][0] = acc[mi][ni][0]*s0 + h0;
            vlo[ni][1] = acc[mi][ni][1]*s0 + h0;
            vhi[ni][0] = acc[mi][ni][2]*s1 + h1;
            vhi[ni][1] = acc[mi][ni][3]*s1 + h1;
            if (mode == 0){
                vlo[ni][0]=fmaxf(vlo[ni][0],0.f); vlo[ni][1]=fmaxf(vlo[ni][1],0.f);
                vhi[ni][0]=fmaxf(vhi[ni][0],0.f); vhi[ni][1]=fmaxf(vhi[ni][1],0.f);
            }
        }
        if (mode == 2){
            #pragma unroll
            for (int ni=0; ni<4; ++ni){
                const int n = n0 + wn*32 + ni*8 + (lane & 3)*2;
                *reinterpret_cast<float2*>(&OutF[(size_t)mlo*ldO + n]) = make_float2(vlo[ni][0], vlo[ni][1]);
                *reinterpret_cast<float2*>(&OutF[(size_t)mhi*ldO + n]) = make_float2(vhi[ni][0], vhi[ni][1]);
            }
        } else {
            #pragma unroll
            for (int ni=0; ni<4; ++ni){
                const int n = n0 + wn*32 + ni*8 + (lane & 3)*2;
                const size_t ilo = (size_t)mlo*ldO + n, ihi = (size_t)mhi*ldO + n;
                __half ha0,la0, ha1,la1, hb0,lb0, hb1,lb1;
                split2(vlo[ni][0], ha0, la0); split2(vlo[ni][1], ha1, la1);
                split2(vhi[ni][0], hb0, lb0); split2(vhi[ni][1], hb1, lb1);
                __half2 t;
                t.x=ha0; t.y=ha1; *reinterpret_cast<__half2*>(&Oa[ilo]) = t;
                t.x=la0; t.y=la1; *reinterpret_cast<__half2*>(&Ob[ilo]) = t;
                t.x=hb0; t.y=hb1; *reinterpret_cast<__half2*>(&Oa[ihi]) = t;
                t.x=lb0; t.y=lb1; *reinterpret_cast<__half2*>(&Ob[ihi]) = t;
            }
        }
    }
}

// ---------------- B-resident mma kernel (SA layers 2,3): full M=256 per CTA ----------------
// B tile (K=256 x N=128) lives in smem; loops both M halves streaming only W chunks.
// mode 0: BN+ReLU -> split planes (ldO); mode 1: + fused 16-col maxpool (stride NP)
__global__ __launch_bounds__(256) void mma_gemm_bres_kernel(
    const __half* __restrict__ Aa, const __half* __restrict__ Ab,
    const __half* __restrict__ Ba, const __half* __restrict__ Bb, int ldB,
    __half* __restrict__ Oa, __half* __restrict__ Ob, int ldO,
    const float* __restrict__ gamma, const float* __restrict__ beta,
    const float* __restrict__ mean,  const float* __restrict__ var,
    int mode)
{
    extern __shared__ char smem[];
    const uint32_t sbase = smem_u32(smem);
    const int tid = threadIdx.x, lane = tid & 31, wid = tid >> 5;
    const int wm = wid & 1, wn = wid >> 1;
    const int n0 = blockIdx.x * 128;

    // stage the FULL B tile (8 chunks) as one commit group
    for (int c=0; c<8; ++c){
        #pragma unroll
        for (int it=0; it<2; ++it){
            const int idx = it*256 + tid;
            const int k = idx >> 4, ng = (idx & 15) * 8;
            const uint32_t d = sbase + (uint32_t)c*B_CH + (uint32_t)k*272u + (uint32_t)ng*2u;
            const size_t so = (size_t)(c*32+k)*ldB + n0 + ng;
            CP16(d,        Ba + so);
            CP16(d + B_PL, Bb + so);
        }
    }
    CP_COMMIT();

    auto stageA = [&](int cc, int buf){
        const int half = cc >> 3, k0 = (cc & 7) * 32;
        const __half* A0 = Aa + (size_t)(half*128)*CC;
        const __half* A1 = Ab + (size_t)(half*128)*CC;
        #pragma unroll
        for (int it=0; it<2; ++it){
            const int idx = it*256 + tid;
            const int m = idx >> 2, kg = (idx & 3) * 8;
            const uint32_t d = sbase + BRES_B + (uint32_t)buf*A_BUFS + (uint32_t)m*80u + (uint32_t)kg*2u;
            const size_t so = (size_t)m*CC + k0 + kg;
            CP16(d,        A0 + so);
            CP16(d + A_PL, A1 + so);
        }
    };

    float acc[4][4][4] = {};

    const uint32_t aRow = (uint32_t)((wm*64 + (lane & 15)) * 80) + (uint32_t)(((lane >> 4) << 3) * 2);
    const uint32_t bRow = (uint32_t)(((((lane >> 3) & 1) << 3) + (lane & 7)) * 272)
                        + (uint32_t)((wn*32 + ((lane >> 4) << 3)) * 2);

    auto compute_chunk = [&](int cc){
        const uint32_t aB = sbase + BRES_B + (uint32_t)(cc&3)*A_BUFS;
        const uint32_t bB = sbase + (uint32_t)(cc&7)*B_CH;
        #pragma unroll
        for (int ks=0; ks<2; ++ks){
            uint32_t bfr[2][2][4];
            #pragma unroll
            for (int p=0; p<2; ++p)
                #pragma unroll
                for (int n2=0; n2<2; ++n2)
                    LDSM_X4T(bfr[p][n2], bB + p*B_PL + bRow + (uint32_t)(ks*16*272) + (uint32_t)(n2*32));
            #pragma unroll
            for (int mh=0; mh<2; ++mh){
                uint32_t afr[2][2][4];
                #pragma unroll
                for (int p=0; p<2; ++p)
                    #pragma unroll
                    for (int m2=0; m2<2; ++m2)
                        LDSM_X4(afr[p][m2], aB + p*A_PL + aRow + (uint32_t)((mh*2+m2)*16*80) + (uint32_t)(ks*32));
                #pragma unroll
                for (int m2=0; m2<2; ++m2){
                    const int mi = mh*2 + m2;
                    #pragma unroll
                    for (int ni=0; ni<4; ++ni){
                        const int n2 = ni >> 1, q = (ni & 1) * 2;
                        float* C = acc[mi][ni];
                        MMA_F16(C, afr[0][m2], bfr[0][n2][q], bfr[0][n2][q+1]);
                        MMA_F16(C, afr[0][m2], bfr[1][n2][q], bfr[1][n2][q+1]);
                        MMA_F16(C, afr[1][m2], bfr[0][n2][q], bfr[0][n2][q+1]);
                    }
                }
            }
        }
    };

    auto epilogue = [&](int mbase){
        #pragma unroll
        for (int mi=0; mi<4; ++mi){
            const int mlo = mbase + wm*64 + mi*16 + (lane >> 2);
            const int mhi = mlo + 8;
            const float s0 = gamma[mlo] * rsqrtf(var[mlo] + 1e-5f);
            const float h0 = beta[mlo] - mean[mlo]*s0;
            const float s1 = gamma[mhi] * rsqrtf(var[mhi] + 1e-5f);
            const float h1 = beta[mhi] - mean[mhi]*s1;
            float vlo[4][2], vhi[4][2];
            #pragma unroll
            for (int ni=0; ni<4; ++ni){
                vlo[ni][0] = fmaxf(acc[mi][ni][0]*s0 + h0, 0.f);
                vlo[ni][1] = fmaxf(acc[mi][ni][1]*s0 + h0, 0.f);
                vhi[ni][0] = fmaxf(acc[mi][ni][2]*s1 + h1, 0.f);
                vhi[ni][1] = fmaxf(acc[mi][ni][3]*s1 + h1, 0.f);
            }
            if (mode == 1){
                #pragma unroll
                for (int g=0; g<2; ++g){
                    float pl = fmaxf(fmaxf(vlo[2*g][0],vlo[2*g][1]), fmaxf(vlo[2*g+1][0],vlo[2*g+1][1]));
                    float ph = fmaxf(fmaxf(vhi[2*g][0],vhi[2*g][1]), fmaxf(vhi[2*g+1][0],vhi[2*g+1][1]));
                    #pragma unroll
                    for (int off=1; off<4; off<<=1){
                        pl = fmaxf(pl, __shfl_xor_sync(0xffffffffu, pl, off));
                        ph = fmaxf(ph, __shfl_xor_sync(0xffffffffu, ph, off));
                    }
                    if ((lane & 3) == 0){
                        const int p = (n0 >> 4) + wn*2 + g;
                        __half hh, hl;
                        split2(pl, hh, hl);
                        Oa[(size_t)mlo*NP + p] = hh; Ob[(size_t)mlo*NP + p] = hl;
                        split2(ph, hh, hl);
                        Oa[(size_t)mhi*NP + p] = hh; Ob[(size_t)mhi*NP + p] = hl;
                    }
                }
            } else {
                #pragma unroll
                for (int ni=0; ni<4; ++ni){
                    const int n = n0 + wn*32 + ni*8 + (lane & 3)*2;
                    const size_t ilo = (size_t)mlo*ldO + n, ihi = (size_t)mhi*ldO + n;
                    __half ha0,la0, ha1,la1, hb0,lb0, hb1,lb1;
                    split2(vlo[ni][0], ha0, la0); split2(vlo[ni][1], ha1, la1);
                    split2(vhi[ni][0], hb0, lb0); split2(vhi[ni][1], hb1, lb1);
                    __half2 t;
                    t.x=ha0; t.y=ha1; *reinterpret_cast<__half2*>(&Oa[ilo]) = t;
                    t.x=la0; t.y=la1; *reinterpret_cast<__half2*>(&Ob[ilo]) = t;
                    t.x=hb0; t.y=hb1; *reinterpret_cast<__half2*>(&Oa[ihi]) = t;
                    t.x=lb0; t.y=lb1; *reinterpret_cast<__half2*>(&Ob[ihi]) = t;
                }
            }
        }
    };

    stageA(0, 0); CP_COMMIT();
    stageA(1, 1); CP_COMMIT();
    for (int cc=0; cc<16; ++cc){
        if (cc+2 < 16){ stageA(cc+2, (cc+2)&3); CP_COMMIT(); CP_WAIT2(); }
        else if (cc+1 < 16){ CP_WAIT1(); }
        else { CP_WAIT0(); }
        __syncthreads();
        compute_chunk(cc);
        if (cc == 7){
            epilogue(0);
            #pragma unroll
            for (int mi=0; mi<4; ++mi)
                #pragma unroll
                for (int ni=0; ni<4; ++ni)
                    #pragma unroll
                    for (int e=0; e<4; ++e) acc[mi][ni][e] = 0.f;
        }
    }
    epilogue(128);
}

// ---------------- head ----------------
__global__ __launch_bounds__(256) void head_kernel(const float* __restrict__ msa,
                                                   float* __restrict__ out)
{
    const int t = blockIdx.x*256 + threadIdx.x;
    #define NT(j) g_NET[(j)*NP + t]
    const float obj0 = NT(0), obj1 = NT(1);
    out[OFF_OBJ + t*2 + 0] = obj0;
    out[OFF_OBJ + t*2 + 1] = obj1;
    const float c0 = g_NX[t*3+0] + NT(2);
    const float c1 = g_NX[t*3+1] + NT(3);
    const float c2 = g_NX[t*3+2] + NT(4);
    out[OFF_CENTER + t*3 + 0] = c0;
    out[OFF_CENTER + t*3 + 1] = c1;
    out[OFF_CENTER + t*3 + 2] = c2;

    float ss[18];
    #pragma unroll
    for (int k=0;k<18;k++){ ss[k] = NT(29+k); out[OFF_SS + t*18 + k] = ss[k]; }
    int best = 0; float bv = ss[0];
    #pragma unroll
    for (int k=1;k<18;k++) if (ss[k] > bv){ bv = ss[k]; best = k; }

    float ps0=0.f, ps1=0.f, ps2=0.f;
    #pragma unroll
    for (int k=0;k<18;k++){
        const float m0=msa[k*3+0], m1=msa[k*3+1], m2=msa[k*3+2];
        const float r0 = NT(47+k*3+0)*m0;
        const float r1 = NT(47+k*3+1)*m1;
        const float r2 = NT(47+k*3+2)*m2;
        out[OFF_SRES + t*54 + k*3 + 0] = r0;
        out[OFF_SRES + t*54 + k*3 + 1] = r1;
        out[OFF_SRES + t*54 + k*3 + 2] = r2;
        if (k == best){ ps0 = r0+m0; ps1 = r1+m1; ps2 = r2+m2; }
    }
    out[OFF_PSIZE + t*3 + 0] = ps0;
    out[OFF_PSIZE + t*3 + 1] = ps1;
    out[OFF_PSIZE + t*3 + 2] = ps2;

    float sm[18];
    #pragma unroll
    for (int k=0;k<18;k++){ sm[k] = NT(101+k); out[OFF_SEM + t*18 + k] = sm[k]; }

    const float cc0 = c0, cc1 = c2, cc2 = -c1;
    const float hx = ps0*0.5f, hy = ps2*0.5f, hz = ps1*0.5f;
    const float SX[8]={1,1,-1,-1,1,1,-1,-1};
    const float SY[8]={1,1,1,1,-1,-1,-1,-1};
    const float SZ[8]={1,-1,-1,1,1,-1,-1,1};
    #pragma unroll
    for (int i=0;i<8;i++){
        out[OFF_CORN + t*24 + i*3 + 0] = cc0 + hx*SX[i];
        out[OFF_CORN + t*24 + i*3 + 1] = cc1 + hy*SY[i];
        out[OFF_CORN + t*24 + i*3 + 2] = cc2 + hz*SZ[i];
    }

    #pragma unroll
    for (int k=0;k<18;k++) out[OFF_SLOG + t*19 + k] = sm[k];
    out[OFF_SLOG + t*19 + 18] = (obj0 <= obj1) ? 0.0f : 1e10f;

    {
        const float mx = fmaxf(obj0,obj1);
        const float e0 = expf(obj0-mx), e1 = expf(obj1-mx);
        out[OFF_OPROB + t] = e1/(e0+e1);
    }
    {
        float mx = sm[0];
        #pragma unroll
        for (int k=1;k<18;k++) mx = fmaxf(mx, sm[k]);
        float e[18], ssum = 0.f;
        #pragma unroll
        for (int k=0;k<18;k++){ e[k] = expf(sm[k]-mx); ssum += e[k]; }
        #pragma unroll
        for (int k=0;k<18;k++) out[OFF_SPROB + t*18 + k] = e[k]/ssum;
    }
    #undef NT
}

// ---------------- host launcher ----------------
extern "C" void kernel_launch(void* const* d_in, const int* in_sizes, int n_in,
                              void* d_out, int out_size)
{
    const float* xyz      = (const float*)d_in[0];
    const float* features = (const float*)d_in[1];
    const float* sa_w1    = (const float*)d_in[2];
    const float* sa_w2    = (const float*)d_in[3];
    const float* sa_w3    = (const float*)d_in[4];
    const float* sa_gamma = (const float*)d_in[5];
    const float* sa_beta  = (const float*)d_in[6];
    const float* sa_mean  = (const float*)d_in[7];
    const float* sa_var   = (const float*)d_in[8];
    const float* p_w1     = (const float*)d_in[9];
    const float* p_w2     = (const float*)d_in[10];
    const float* p_w3     = (const float*)d_in[11];
    const float* p_b3     = (const float*)d_in[12];
    const float* p_gamma  = (const float*)d_in[13];
    const float* p_beta   = (const float*)d_in[14];
    const float* p_mean   = (const float*)d_in[15];
    const float* p_var    = (const float*)d_in[16];
    const float* msa      = (const float*)d_in[17];
    float* out = (float*)d_out;

    cudaFuncSetAttribute(mma_gemm_kernel, cudaFuncAttributeMaxDynamicSharedMemorySize, SMT);
    cudaFuncSetAttribute(mma_gemm_bres_kernel, cudaFuncAttributeMaxDynamicSharedMemorySize, SMT2);

    void *pFTa,*pFTb, *pZa,*pZb, *pA1a,*pA1b, *pA2a,*pA2b;
    void *pW1Ta,*pW1Tb, *pW2a,*pW2b, *pW3a,*pW3b;
    void *pP1a,*pP1b, *pP2a,*pP2b, *pP3a,*pP3b, *pB3P;
    void *pYa,*pYb, *pY2a,*pY2b, *pY3a,*pY3b, *pNET;
    cudaGetSymbolAddress(&pFTa, g_FTa); cudaGetSymbolAddress(&pFTb, g_FTb);
    cudaGetSymbolAddress(&pZa,  g_Za);  cudaGetSymbolAddress(&pZb,  g_Zb);
    cudaGetSymbolAddress(&pA1a, g_A1a); cudaGetSymbolAddress(&pA1b, g_A1b);
    cudaGetSymbolAddress(&pA2a, g_A2a); cudaGetSymbolAddress(&pA2b, g_A2b);
    cudaGetSymbolAddress(&pW1Ta, g_W1Ta); cudaGetSymbolAddress(&pW1Tb, g_W1Tb);
    cudaGetSymbolAddress(&pW2a, g_W2a); cudaGetSymbolAddress(&pW2b, g_W2b);
    cudaGetSymbolAddress(&pW3a, g_W3a); cudaGetSymbolAddress(&pW3b, g_W3b);
    cudaGetSymbolAddress(&pP1a, g_P1a); cudaGetSymbolAddress(&pP1b, g_P1b);
    cudaGetSymbolAddress(&pP2a, g_P2a); cudaGetSymbolAddress(&pP2b, g_P2b);
    cudaGetSymbolAddress(&pP3a, g_P3a); cudaGetSymbolAddress(&pP3b, g_P3b);
    cudaGetSymbolAddress(&pB3P, g_B3P);
    cudaGetSymbolAddress(&pYa,  g_Ya);  cudaGetSymbolAddress(&pYb,  g_Yb);
    cudaGetSymbolAddress(&pY2a, g_Y2a); cudaGetSymbolAddress(&pY2b, g_Y2b);
    cudaGetSymbolAddress(&pY3a, g_Y3a); cudaGetSymbolAddress(&pY3b, g_Y3b);
    cudaGetSymbolAddress(&pNET, g_NET);

    fps_kernel<<<BB, 256>>>(xyz);
    prep_all<<<(PR_TOTAL + 255)/256, 256>>>(sa_w1, sa_w2, sa_w3, p_w1, p_w2, p_w3, p_b3);
    featT_kernel<<<dim3(KK/32, CC/32, BB), 256>>>(features);
    ballq_kernel<<<1024, 256>>>(xyz);

    // Z = FT @ W1f^T : M=65536, N=256, K=256, identity epilogue -> Z planes [n][oc]
    mma_gemm_kernel<<<dim3(2, NPTS/128), 256, SMT>>>(
        (const __half*)pFTa, (const __half*)pFTb, CC, CC/32,
        (const __half*)pW1Ta, (const __half*)pW1Tb, CC,
        (__half*)pZa, (__half*)pZb, CC,
        nullptr, nullptr,
        nullptr, nullptr, nullptr, nullptr, 3);

    // layer-1 assembly: gather Z + xyz term + BN/ReLU -> A1 planes
    asm1_kernel<<<NCOL/ACOLS, 256>>>(sa_w1, sa_gamma+0, sa_beta+0, sa_mean+0, sa_var+0);

    // SA layer 2 (B-resident: A1 read once)
    mma_gemm_bres_kernel<<<NCOL/128, 256, SMT2>>>(
        (const __half*)pW2a, (const __half*)pW2b,
        (const __half*)pA1a, (const __half*)pA1b, NCOL,
        (__half*)pA2a, (__half*)pA2b, NCOL,
        sa_gamma+256, sa_beta+256, sa_mean+256, sa_var+256, 0);
    // SA layer 3 (B-resident) -> fused maxpool -> Y split planes
    mma_gemm_bres_kernel<<<NCOL/128, 256, SMT2>>>(
        (const __half*)pW3a, (const __half*)pW3b,
        (const __half*)pA2a, (const __half*)pA2b, NCOL,
        (__half*)pYa, (__half*)pYb, NP,
        sa_gamma+512, sa_beta+512, sa_mean+512, sa_var+512, 1);

    const dim3 gf(NP/128, 2);
    // FC1
    mma_gemm_kernel<<<gf, 256, SMT>>>(
        (const __half*)pP1a, (const __half*)pP1b, CC, CC/32,
        (const __half*)pYa, (const __half*)pYb, NP,
        (__half*)pY2a, (__half*)pY2b, NP,
        nullptr, nullptr,
        p_gamma+0, p_beta+0, p_mean+0, p_var+0, 0);
    // FC2
    mma_gemm_kernel<<<gf, 256, SMT>>>(
        (const __half*)pP2a, (const __half*)pP2b, CC, CC/32,
        (const __half*)pY2a, (const __half*)pY2b, NP,
        (__half*)pY3a, (__half*)pY3b, NP,
        nullptr, nullptr,
        p_gamma+256, p_beta+256, p_mean+256, p_var+256, 0);
    // FC3 (head conv): 128 padded rows, fp32 + bias, no relu
    mma_gemm_kernel<<<dim3(NP/128, 1), 256, SMT>>>(
        (const __half*)pP3a, (const __half*)pP3b, CC, CC/32,
        (const __half*)pY3a, (const __half*)pY3b, NP,
        nullptr, nullptr, NP,
        (float*)pNET, (const float*)pB3P,
        nullptr, nullptr, nullptr, nullptr, 2);

    head_kernel<<<NP/256, 256>>>(msa, out);
}

// round 13
// speedup vs baseline: 2.5210x; 1.0949x over previous
#include <cuda_runtime.h>
#include <cuda_fp16.h>
#include <math.h>
#include <cstdint>

// ---------------- problem constants ----------------
#define BB 32
#define KK 2048
#define CC 256
#define PP 256
#define SS 16
#define NCOL (BB*PP*SS)      // 131072
#define NP   (BB*PP)         // 8192
#define NPTS (BB*KK)         // 65536 distinct (b,point) columns
#define OUTC 119
#define MP3  128             // p_w3 M padded

// output section offsets (floats)
#define OFF_OBJ      0
#define OFF_CENTER   16384
#define OFF_SS       40960
#define OFF_SRES     188416
#define OFF_PSIZE    630784
#define OFF_SEM      655360
#define OFF_CORN     802816
#define OFF_SLOG     999424
#define OFF_OPROB    1155072
#define OFF_SPROB    1163264

// ---------------- scratch (device globals; zero-init guaranteed) ----------------
__device__ __align__(16) __half g_FTa[(size_t)NPTS * CC];  // features^T hi plane [n][c]
__device__ __align__(16) __half g_FTb[(size_t)NPTS * CC];  // lo plane
__device__ __align__(16) float  g_ZF [(size_t)NPTS * CC];  // Z = FT @ W1f^T, fp32 [n][oc]
__device__ __align__(16) __half g_A1a[(size_t)CC * NCOL];
__device__ __align__(16) __half g_A1b[(size_t)CC * NCOL];
__device__ __align__(16) __half g_A2a[(size_t)CC * NCOL];
__device__ __align__(16) __half g_A2b[(size_t)CC * NCOL];
__device__ __half g_W1Ta[CC*CC], g_W1Tb[CC*CC];   // W1 feature part, transposed [c][oc]
__device__ __half g_W2a[CC*CC], g_W2b[CC*CC];
__device__ __half g_W3a[CC*CC], g_W3b[CC*CC];
__device__ __half g_P1a[CC*CC], g_P1b[CC*CC];
__device__ __half g_P2a[CC*CC], g_P2b[CC*CC];
__device__ __half g_P3a[MP3*CC], g_P3b[MP3*CC];
__device__ float  g_B3P[MP3];
__device__ __half g_Ya [CC*NP], g_Yb [CC*NP];
__device__ __half g_Y2a[CC*NP], g_Y2b[CC*NP];
__device__ __half g_Y3a[CC*NP], g_Y3b[CC*NP];
__device__ float  g_NET[MP3 * NP];
__device__ float  g_NX[NP * 3];
__device__ float  g_GX[3 * NCOL];   // normalized grouped xyz (fp32)
__device__ int    g_IDX[NP * SS];

// ---------------- asm helpers (base-target: sm_80+) ----------------
__device__ __forceinline__ uint32_t smem_u32(const void* p){
    uint32_t a;
    asm("{ .reg .u64 t; cvta.to.shared.u64 t, %1; cvt.u32.u64 %0, t; }" : "=r"(a) : "l"(p));
    return a;
}
#define CP16(dst, src)  asm volatile("cp.async.cg.shared.global [%0], [%1], 16;" :: "r"(dst), "l"(src))
#define CP_COMMIT()     asm volatile("cp.async.commit_group;" ::: "memory")
#define CP_WAIT2()      asm volatile("cp.async.wait_group 2;" ::: "memory")
#define CP_WAIT1()      asm volatile("cp.async.wait_group 1;" ::: "memory")
#define CP_WAIT0()      asm volatile("cp.async.wait_group 0;" ::: "memory")

#define LDSM_X4(R, addr) \
    asm volatile("ldmatrix.sync.aligned.m8n8.x4.shared.b16 {%0,%1,%2,%3}, [%4];" \
        : "=r"((R)[0]),"=r"((R)[1]),"=r"((R)[2]),"=r"((R)[3]) : "r"(addr))
#define LDSM_X4T(R, addr) \
    asm volatile("ldmatrix.sync.aligned.m8n8.x4.trans.shared.b16 {%0,%1,%2,%3}, [%4];" \
        : "=r"((R)[0]),"=r"((R)[1]),"=r"((R)[2]),"=r"((R)[3]) : "r"(addr))

#define MMA_F16(C, A, b0, b1) \
    asm volatile("mma.sync.aligned.m16n8k16.row.col.f32.f16.f16.f32 " \
        "{%0,%1,%2,%3}, {%4,%5,%6,%7}, {%8,%9}, {%0,%1,%2,%3};" \
        : "+f"((C)[0]),"+f"((C)[1]),"+f"((C)[2]),"+f"((C)[3]) \
        : "r"((A)[0]),"r"((A)[1]),"r"((A)[2]),"r"((A)[3]), "r"(b0),"r"(b1))

// ---------------- misc helpers ----------------
__device__ __forceinline__ float d2_nofma(float ax,float ay,float az,float bx,float by,float bz){
    float dx=ax-bx, dy=ay-by, dz=az-bz;
    return __fadd_rn(__fadd_rn(__fmul_rn(dx,dx),__fmul_rn(dy,dy)),__fmul_rn(dz,dz));
}
__device__ __forceinline__ void split2(float v, __half& h, __half& l){
    h = __float2half(v);
    l = __float2half(v - __half2float(h));
}

// ---------------- FPS: one block per batch, 256 thr x 8 pts, redux argmax ----------------
__global__ __launch_bounds__(256) void fps_kernel(const float* __restrict__ xyz)
{
    __shared__ float sx[KK], sy[KK], sz[KK];
    __shared__ unsigned rv[2][8]; __shared__ int ri[2][8];
    const int b = blockIdx.x, tid = threadIdx.x;
    const float* xb = xyz + (size_t)b*KK*3;
    for (int i=tid;i<KK;i+=256){ sx[i]=xb[i*3+0]; sy[i]=xb[i*3+1]; sz[i]=xb[i*3+2]; }
    __syncthreads();
    float px[8], py[8], pz[8], pd[8];
    #pragma unroll
    for (int k=0;k<8;k++){
        const int i = tid + k*256;
        px[k]=sx[i]; py[k]=sy[i]; pz[k]=sz[i]; pd[k]=1e10f;
    }
    int far = 0;
    const int w = tid>>5, lane = tid&31;
    for (int it=0; it<PP; ++it){
        if (tid==0){
            g_NX[(b*PP+it)*3+0]=sx[far];
            g_NX[(b*PP+it)*3+1]=sy[far];
            g_NX[(b*PP+it)*3+2]=sz[far];
        }
        const float cx=sx[far], cy=sy[far], cz=sz[far];
        float bv = -1.f; int bi = 0;
        #pragma unroll
        for (int k=0;k<8;k++){
            pd[k] = fminf(pd[k], d2_nofma(px[k],py[k],pz[k],cx,cy,cz));
            if (pd[k] > bv){ bv = pd[k]; bi = tid + k*256; }   // strict > keeps earliest idx
        }
        const unsigned vbits = __float_as_uint(bv);
        const unsigned vmax  = __reduce_max_sync(0xffffffffu, vbits);
        const unsigned cand  = (vbits == vmax) ? (unsigned)bi : 0xFFFFFFFFu;
        const unsigned imin  = __reduce_min_sync(0xffffffffu, cand);
        const int pb = it & 1;
        if (lane==0){ rv[pb][w]=vmax; ri[pb][w]=(int)imin; }
        __syncthreads();
        const unsigned vb = (lane<8) ? rv[pb][lane] : 0u;
        const int      ib = (lane<8) ? ri[pb][lane] : 0x7FFFFFFF;
        const unsigned vmax2 = __reduce_max_sync(0xffffffffu, vb);
        const unsigned cand2 = (vb == vmax2) ? (unsigned)ib : 0xFFFFFFFFu;
        far = (int)__reduce_min_sync(0xffffffffu, cand2);
    }
}

// ---------------- ball query + fused normalized-xyz emit (fp32) ----------------
__global__ __launch_bounds__(256) void ballq_kernel(const float* __restrict__ xyz)
{
    __shared__ float sx[KK], sy[KK], sz[KK];
    __shared__ int sidx[8][SS];
    const int b = blockIdx.x >> 5;
    const float* xb = xyz + (size_t)b*KK*3;
    for (int i=threadIdx.x;i<KK;i+=256){ sx[i]=xb[i*3+0]; sy[i]=xb[i*3+1]; sz[i]=xb[i*3+2]; }
    __syncthreads();
    const int warp = threadIdx.x>>5, lane = threadIdx.x&31;
    const int w = blockIdx.x*8 + warp;
    const float cx=g_NX[w*3+0], cy=g_NX[w*3+1], cz=g_NX[w*3+2];
    int cnt=0, firstIdx=0; bool haveFirst=false;
    for (int j=0;j<KK;j+=32){
        const int i = j + lane;
        const float dd = d2_nofma(sx[i],sy[i],sz[i],cx,cy,cz);
        const bool within = dd < 0.09f;
        const unsigned mask = __ballot_sync(0xffffffffu, within);
        if (mask){
            if (!haveFirst){ firstIdx = j + __ffs(mask) - 1; haveFirst=true; }
            const int rank = __popc(mask & ((1u<<lane)-1u));
            if (within && (cnt+rank) < SS) sidx[warp][cnt+rank] = i;
            cnt += __popc(mask);
            if (cnt >= SS) break;
        }
    }
    if (cnt < SS && lane >= cnt && lane < SS) sidx[warp][lane] = firstIdx;
    __syncwarp();
    if (lane < SS){
        const int i = sidx[warp][lane];
        const int t = w*SS + lane;
        g_IDX[t] = i;
        g_GX[0*NCOL + t] = (sx[i]-cx) / 0.3f;
        g_GX[1*NCOL + t] = (sy[i]-cy) / 0.3f;
        g_GX[2*NCOL + t] = (sz[i]-cz) / 0.3f;
    }
}

// ---------------- merged weight prep ----------------
#define PR_W1T_END (CC*CC)
#define PR_W2_END  (PR_W1T_END + CC*CC)
#define PR_W3_END  (PR_W2_END + CC*CC)
#define PR_P1_END  (PR_W3_END + CC*CC)
#define PR_P2_END  (PR_P1_END + CC*CC)
#define PR_P3_END  (PR_P2_END + MP3*CC)
#define PR_TOTAL   (PR_P3_END + MP3)

__global__ void prep_all(const float* __restrict__ w1, const float* __restrict__ w2,
                         const float* __restrict__ w3, const float* __restrict__ q1,
                         const float* __restrict__ q2, const float* __restrict__ q3,
                         const float* __restrict__ b3)
{
    const int t = blockIdx.x*256 + threadIdx.x;
    if (t >= PR_TOTAL) return;
    if (t >= PR_P3_END){ const int k = t - PR_P3_END; g_B3P[k] = (k < OUTC) ? b3[k] : 0.0f; return; }
    float v; __half *da, *db; int idx;
    if (t < PR_W1T_END){
        idx = t;
        const int c = idx >> 8, oc = idx & 255;
        v = w1[oc*259 + 3 + c];
        da=g_W1Ta; db=g_W1Tb;
    } else if (t < PR_W2_END){ idx=t-PR_W1T_END; v=w2[idx]; da=g_W2a; db=g_W2b; }
    else if (t < PR_W3_END){ idx=t-PR_W2_END; v=w3[idx]; da=g_W3a; db=g_W3b; }
    else if (t < PR_P1_END){ idx=t-PR_W3_END; v=q1[idx]; da=g_P1a; db=g_P1b; }
    else if (t < PR_P2_END){ idx=t-PR_P1_END; v=q2[idx]; da=g_P2a; db=g_P2b; }
    else {
        idx = t-PR_P2_END;
        const int m = idx >> 8;
        v = (m < OUTC) ? q3[idx] : 0.0f;
        da=g_P3a; db=g_P3b;
    }
    __half h,l; split2(v,h,l);
    da[idx]=h; db[idx]=l;
}

// ---------------- featT: features [b][c][j] fp32 -> FT planes [b*2048+j][c] ----------------
__global__ __launch_bounds__(256) void featT_kernel(const float* __restrict__ features)
{
    __shared__ float tile[32][33];
    const int jt = blockIdx.x*32, ct = blockIdx.y*32, b = blockIdx.z;
    const int tid = threadIdx.x;
    {
        const int cl = tid >> 3, j4 = (tid & 7)*4;
        const float4 v = *reinterpret_cast<const float4*>(
            &features[((size_t)b*CC + ct+cl)*KK + jt + j4]);
        tile[cl][j4+0]=v.x; tile[cl][j4+1]=v.y; tile[cl][j4+2]=v.z; tile[cl][j4+3]=v.w;
    }
    __syncthreads();
    {
        const int jl = tid >> 3, c4 = (tid & 7)*4;
        const size_t base = ((size_t)(b*KK + jt + jl))*CC + ct + c4;
        __half ha,la,hb,lb,hc,lc,hd,ld;
        split2(tile[c4+0][jl], ha, la);
        split2(tile[c4+1][jl], hb, lb);
        split2(tile[c4+2][jl], hc, lc);
        split2(tile[c4+3][jl], hd, ld);
        __half2 x;
        x.x=ha; x.y=hb; *reinterpret_cast<__half2*>(&g_FTa[base+0]) = x;
        x.x=hc; x.y=hd; *reinterpret_cast<__half2*>(&g_FTa[base+2]) = x;
        x.x=la; x.y=lb; *reinterpret_cast<__half2*>(&g_FTb[base+0]) = x;
        x.x=lc; x.y=ld; *reinterpret_cast<__half2*>(&g_FTb[base+2]) = x;
    }
}

// ---------------- asm1: gather fp32 Z rows + xyz term + BN/ReLU -> A1 planes ----------------
#define ACOLS 128
__global__ __launch_bounds__(256) void asm1_kernel(const float* __restrict__ w1,
    const float* __restrict__ gamma, const float* __restrict__ beta,
    const float* __restrict__ mean,  const float* __restrict__ var)
{
    __shared__ float sW0[256], sW1[256], sW2[256];
    __shared__ float sScale[256], sShift[256];
    __shared__ float sG0[ACOLS], sG1[ACOLS], sG2[ACOLS];
    __shared__ int   sIdx[ACOLS];
    __shared__ float sT[64][ACOLS+4];
    const int tid = threadIdx.x;
    const int t0 = blockIdx.x * ACOLS;
    const int b  = t0 >> 12;
    {
        const int oc = tid;
        sW0[oc] = w1[oc*259 + 0];
        sW1[oc] = w1[oc*259 + 1];
        sW2[oc] = w1[oc*259 + 2];
        const float sc = gamma[oc]*rsqrtf(var[oc]+1e-5f);
        sScale[oc]=sc; sShift[oc]=beta[oc]-mean[oc]*sc;
    }
    if (tid < ACOLS) sIdx[tid] = g_IDX[t0 + tid];
    for (int i=tid; i<3*ACOLS; i+=256){
        const int r = i >> 7, c = i & 127;
        float v = g_GX[(size_t)r*NCOL + t0 + c];
        if (r==0) sG0[c]=v; else if (r==1) sG1[c]=v; else sG2[c]=v;
    }
    __syncthreads();

    const int cl = tid >> 1;
    const int part = tid & 1;
    const int j = sIdx[cl];
    const float* zrow = g_ZF + ((size_t)(b*KK + j))*CC;
    const float g0=sG0[cl], g1=sG1[cl], g2=sG2[cl];

    #pragma unroll
    for (int s=0; s<4; ++s){
        const int oc0 = s*64 + part*32;
        const float4* pz = reinterpret_cast<const float4*>(&zrow[oc0]);
        #pragma unroll
        for (int q=0;q<8;q++){
            const float4 zv = pz[q];
            const int oc = oc0 + q*4;
            float v0 = zv.x + sW0[oc  ]*g0 + sW1[oc  ]*g1 + sW2[oc  ]*g2;
            float v1 = zv.y + sW0[oc+1]*g0 + sW1[oc+1]*g1 + sW2[oc+1]*g2;
            float v2 = zv.z + sW0[oc+2]*g0 + sW1[oc+2]*g1 + sW2[oc+2]*g2;
            float v3 = zv.w + sW0[oc+3]*g0 + sW1[oc+3]*g1 + sW2[oc+3]*g2;
            v0 = fmaxf(v0*sScale[oc  ] + sShift[oc  ], 0.f);
            v1 = fmaxf(v1*sScale[oc+1] + sShift[oc+1], 0.f);
            v2 = fmaxf(v2*sScale[oc+2] + sShift[oc+2], 0.f);
            v3 = fmaxf(v3*sScale[oc+3] + sShift[oc+3], 0.f);
            sT[oc   - s*64][cl] = v0;
            sT[oc+1 - s*64][cl] = v1;
            sT[oc+2 - s*64][cl] = v2;
            sT[oc+3 - s*64][cl] = v3;
        }
        __syncthreads();
        {
            const int r = tid >> 2;
            const int cseg = (tid & 3) * 32;
            const int oc = s*64 + r;
            __half2* da = reinterpret_cast<__half2*>(&g_A1a[(size_t)oc*NCOL + t0 + cseg]);
            __half2* db = reinterpret_cast<__half2*>(&g_A1b[(size_t)oc*NCOL + t0 + cseg]);
            #pragma unroll
            for (int q=0;q<16;q++){
                const float va = sT[r][cseg + 2*q], vb = sT[r][cseg + 2*q + 1];
                __half ha,la,hb,lb;
                split2(va,ha,la); split2(vb,hb,lb);
                __half2 th; th.x=ha; th.y=hb; da[q]=th;
                __half2 tl; tl.x=la; tl.y=lb; db[q]=tl;
            }
        }
        __syncthreads();
    }
}

// ---------------- shared GEMM geometry ----------------
#define A_PL 10240u
#define A_BUFS (2u*A_PL)
#define B_PL 8704u
#define B_BUFS (2u*B_PL)
#define BUFSZ (A_BUFS + B_BUFS)
#define SMT (4*BUFSZ)          // 151552 (streaming kernel)
#define B_CH (2u*B_PL)
#define BRES_B (8u*B_CH)       // 139264
#define SMT2 (BRES_B + 4u*A_BUFS)  // 221184 (B-resident kernel)

// ---------------- streaming mma kernel (Z, FC1, FC2, FC3) ----------------
// mode 0: BN+ReLU -> split planes; mode 2: (+bias if non-null) -> fp32; mode 3: identity -> split planes
__global__ __launch_bounds__(256) void mma_gemm_kernel(
    const __half* __restrict__ Aa, const __half* __restrict__ Ab, int Kw, int nch,
    const __half* __restrict__ Ba, const __half* __restrict__ Bb, int ldB,
    __half* __restrict__ Oa, __half* __restrict__ Ob, int ldO,
    float* __restrict__ OutF, const float* __restrict__ bias,
    const float* __restrict__ gamma, const float* __restrict__ beta,
    const float* __restrict__ mean,  const float* __restrict__ var,
    int mode)
{
    extern __shared__ char smem[];
    const uint32_t sbase = smem_u32(smem);
    const int tid = threadIdx.x, lane = tid & 31, wid = tid >> 5;
    const int wm = wid & 1, wn = wid >> 1;
    const int n0 = blockIdx.x * 128;
    const int mbase = blockIdx.y * 128;

    const size_t aoff = (size_t)mbase * Kw;
    const __half* A0 = Aa + aoff;
    const __half* A1 = Ab + aoff;

    auto stage = [&](int c, int buf){
        const int k0 = c * 32;
        const uint32_t sA = sbase + buf*BUFSZ;
        const uint32_t sB = sA + A_BUFS;
        #pragma unroll
        for (int it=0; it<2; ++it){
            const int idx = it*256 + tid;
            const int m = idx >> 2, kg = (idx & 3) * 8;
            const uint32_t d = sA + (uint32_t)m*80u + (uint32_t)kg*2u;
            const size_t so = (size_t)m*Kw + k0 + kg;
            CP16(d,        A0 + so);
            CP16(d + A_PL, A1 + so);
        }
        #pragma unroll
        for (int it=0; it<2; ++it){
            const int idx = it*256 + tid;
            const int k = idx >> 4, ng = (idx & 15) * 8;
            const uint32_t d = sB + (uint32_t)k*272u + (uint32_t)ng*2u;
            const size_t so = (size_t)(k0+k)*ldB + n0 + ng;
            CP16(d,        Ba + so);
            CP16(d + B_PL, Bb + so);
        }
    };

    float acc[4][4][4] = {};

    const uint32_t aRow = (uint32_t)((wm*64 + (lane & 15)) * 80) + (uint32_t)(((lane >> 4) << 3) * 2);
    const uint32_t bRow = (uint32_t)(((((lane >> 3) & 1) << 3) + (lane & 7)) * 272)
                        + (uint32_t)((wn*32 + ((lane >> 4) << 3)) * 2);

    auto compute_chunk = [&](int buf){
        const uint32_t aB = sbase + buf*BUFSZ;
        const uint32_t bB = aB + A_BUFS;
        #pragma unroll
        for (int ks=0; ks<2; ++ks){
            uint32_t bfr[2][2][4];
            #pragma unroll
            for (int p=0; p<2; ++p)
                #pragma unroll
                for (int n2=0; n2<2; ++n2)
                    LDSM_X4T(bfr[p][n2], bB + p*B_PL + bRow + (uint32_t)(ks*16*272) + (uint32_t)(n2*32));
            #pragma unroll
            for (int mh=0; mh<2; ++mh){
                uint32_t afr[2][2][4];
                #pragma unroll
                for (int p=0; p<2; ++p)
                    #pragma unroll
                    for (int m2=0; m2<2; ++m2)
                        LDSM_X4(afr[p][m2], aB + p*A_PL + aRow + (uint32_t)((mh*2+m2)*16*80) + (uint32_t)(ks*32));
                #pragma unroll
                for (int m2=0; m2<2; ++m2){
                    const int mi = mh*2 + m2;
                    #pragma unroll
                    for (int ni=0; ni<4; ++ni){
                        const int n2 = ni >> 1, q = (ni & 1) * 2;
                        float* C = acc[mi][ni];
                        MMA_F16(C, afr[0][m2], bfr[0][n2][q], bfr[0][n2][q+1]);
                        MMA_F16(C, afr[0][m2], bfr[1][n2][q], bfr[1][n2][q+1]);
                        MMA_F16(C, afr[1][m2], bfr[0][n2][q], bfr[0][n2][q+1]);
                    }
                }
            }
        }
    };

    stage(0, 0); CP_COMMIT();
    stage(1, 1); CP_COMMIT();
    for (int c=0; c<nch; ++c){
        if (c+2 < nch){ stage(c+2, (c+2)&3); CP_COMMIT(); CP_WAIT2(); }
        else if (c+1 < nch){ CP_WAIT1(); }
        else { CP_WAIT0(); }
        __syncthreads();
        compute_chunk(c & 3);
    }

    // ---- epilogue ----
    #pragma unroll
    for (int mi=0; mi<4; ++mi){
        const int mlo = mbase + wm*64 + mi*16 + (lane >> 2);
        const int mhi = mlo + 8;
        float s0, h0, s1, h1;
        if (mode == 2){
            s0 = 1.f; s1 = 1.f;
            h0 = bias ? bias[mlo] : 0.f;
            h1 = bias ? bias[mhi] : 0.f;
        } else if (mode == 3){
            s0 = 1.f; h0 = 0.f; s1 = 1.f; h1 = 0.f;
        } else {
            s0 = gamma[mlo] * rsqrtf(var[mlo] + 1e-5f);
            h0 = beta[mlo] - mean[mlo]*s0;
            s1 = gamma[mhi] * rsqrtf(var[mhi] + 1e-5f);
            h1 = beta[mhi] - mean[mhi]*s1;
        }
        float vlo[4][2], vhi[4][2];
        #pragma unroll
        for (int ni=0; ni<4; ++ni){
            vlo[ni][0] = acc[mi][ni][0]*s0 + h0;
            vlo[ni][1] = acc[mi][ni][1]*s0 + h0;
            vhi[ni][0] = acc[mi][ni][2]*s1 + h1;
            vhi[ni][1] = acc[mi][ni][3]*s1 + h1;
            if (mode == 0){
                vlo[ni][0]=fmaxf(vlo[ni][0],0.f); vlo[ni][1]=fmaxf(vlo[ni][1],0.f);
                vhi[ni][0]=fmaxf(vhi[ni][0],0.f); vhi[ni][1]=fmaxf(vhi[ni][1],0.f);
            }
        }
        if (mode == 2){
            #pragma unroll
            for (int ni=0; ni<4; ++ni){
                const int n = n0 + wn*32 + ni*8 + (lane & 3)*2;
                *reinterpret_cast<float2*>(&OutF[(size_t)mlo*ldO + n]) = make_float2(vlo[ni][0], vlo[ni][1]);
                *reinterpret_cast<float2*>(&OutF[(size_t)mhi*ldO + n]) = make_float2(vhi[ni][0], vhi[ni][1]);
            }
        } else {
            #pragma unroll
            for (int ni=0; ni<4; ++ni){
                const int n = n0 + wn*32 + ni*8 + (lane & 3)*2;
                const size_t ilo = (size_t)mlo*ldO + n, ihi = (size_t)mhi*ldO + n;
                __half ha0,la0, ha1,la1, hb0,lb0, hb1,lb1;
                split2(vlo[ni][0], ha0, la0); split2(vlo[ni][1], ha1, la1);
                split2(vhi[ni][0], hb0, lb0); split2(vhi[ni][1], hb1, lb1);
                __half2 t;
                t.x=ha0; t.y=ha1; *reinterpret_cast<__half2*>(&Oa[ilo]) = t;
                t.x=la0; t.y=la1; *reinterpret_cast<__half2*>(&Ob[ilo]) = t;
                t.x=hb0; t.y=hb1; *reinterpret_cast<__half2*>(&Oa[ihi]) = t;
                t.x=lb0; t.y=lb1; *reinterpret_cast<__half2*>(&Ob[ihi]) = t;
            }
        }
    }
}

// ---------------- B-resident mma kernel (SA layers 2,3): full M=256 per CTA ----------------
__global__ __launch_bounds__(256) void mma_gemm_bres_kernel(
    const __half* __restrict__ Aa, const __half* __restrict__ Ab,
    const __half* __restrict__ Ba, const __half* __restrict__ Bb, int ldB,
    __half* __restrict__ Oa, __half* __restrict__ Ob, int ldO,
    const float* __restrict__ gamma, const float* __restrict__ beta,
    const float* __restrict__ mean,  const float* __restrict__ var,
    int mode)
{
    extern __shared__ char smem[];
    const uint32_t sbase = smem_u32(smem);
    const int tid = threadIdx.x, lane = tid & 31, wid = tid >> 5;
    const int wm = wid & 1, wn = wid >> 1;
    const int n0 = blockIdx.x * 128;

    for (int c=0; c<8; ++c){
        #pragma unroll
        for (int it=0; it<2; ++it){
            const int idx = it*256 + tid;
            const int k = idx >> 4, ng = (idx & 15) * 8;
            const uint32_t d = sbase + (uint32_t)c*B_CH + (uint32_t)k*272u + (uint32_t)ng*2u;
            const size_t so = (size_t)(c*32+k)*ldB + n0 + ng;
            CP16(d,        Ba + so);
            CP16(d + B_PL, Bb + so);
        }
    }
    CP_COMMIT();

    auto stageA = [&](int cc, int buf){
        const int half = cc >> 3, k0 = (cc & 7) * 32;
        const __half* A0 = Aa + (size_t)(half*128)*CC;
        const __half* A1 = Ab + (size_t)(half*128)*CC;
        #pragma unroll
        for (int it=0; it<2; ++it){
            const int idx = it*256 + tid;
            const int m = idx >> 2, kg = (idx & 3) * 8;
            const uint32_t d = sbase + BRES_B + (uint32_t)buf*A_BUFS + (uint32_t)m*80u + (uint32_t)kg*2u;
            const size_t so = (size_t)m*CC + k0 + kg;
            CP16(d,        A0 + so);
            CP16(d + A_PL, A1 + so);
        }
    };

    float acc[4][4][4] = {};

    const uint32_t aRow = (uint32_t)((wm*64 + (lane & 15)) * 80) + (uint32_t)(((lane >> 4) << 3) * 2);
    const uint32_t bRow = (uint32_t)(((((lane >> 3) & 1) << 3) + (lane & 7)) * 272)
                        + (uint32_t)((wn*32 + ((lane >> 4) << 3)) * 2);

    auto compute_chunk = [&](int cc){
        const uint32_t aB = sbase + BRES_B + (uint32_t)(cc&3)*A_BUFS;
        const uint32_t bB = sbase + (uint32_t)(cc&7)*B_CH;
        #pragma unroll
        for (int ks=0; ks<2; ++ks){
            uint32_t bfr[2][2][4];
            #pragma unroll
            for (int p=0; p<2; ++p)
                #pragma unroll
                for (int n2=0; n2<2; ++n2)
                    LDSM_X4T(bfr[p][n2], bB + p*B_PL + bRow + (uint32_t)(ks*16*272) + (uint32_t)(n2*32));
            #pragma unroll
            for (int mh=0; mh<2; ++mh){
                uint32_t afr[2][2][4];
                #pragma unroll
                for (int p=0; p<2; ++p)
                    #pragma unroll
                    for (int m2=0; m2<2; ++m2)
                        LDSM_X4(afr[p][m2], aB + p*A_PL + aRow + (uint32_t)((mh*2+m2)*16*80) + (uint32_t)(ks*32));
                #pragma unroll
                for (int m2=0; m2<2; ++m2){
                    const int mi = mh*2 + m2;
                    #pragma unroll
                    for (int ni=0; ni<4; ++ni){
                        const int n2 = ni >> 1, q = (ni & 1) * 2;
                        float* C = acc[mi][ni];
                        MMA_F16(C, afr[0][m2], bfr[0][n2][q], bfr[0][n2][q+1]);
                        MMA_F16(C, afr[0][m2], bfr[1][n2][q], bfr[1][n2][q+1]);
                        MMA_F16(C, afr[1][m2], bfr[0][n2][q], bfr[0][n2][q+1]);
                    }
                }
            }
        }
    };

    auto epilogue = [&](int mbase){
        #pragma unroll
        for (int mi=0; mi<4; ++mi){
            const int mlo = mbase + wm*64 + mi*16 + (lane >> 2);
            const int mhi = mlo + 8;
            const float s0 = gamma[mlo] * rsqrtf(var[mlo] + 1e-5f);
            const float h0 = beta[mlo] - mean[mlo]*s0;
            const float s1 = gamma[mhi] * rsqrtf(var[mhi] + 1e-5f);
            const float h1 = beta[mhi] - mean[mhi]*s1;
            float vlo[4][2], vhi[4][2];
            #pragma unroll
            for (int ni=0; ni<4; ++ni){
                vlo[ni][0] = fmaxf(acc[mi][ni][0]*s0 + h0, 0.f);
                vlo[ni][1] = fmaxf(acc[mi][ni][1]*s0 + h0, 0.f);
                vhi[ni][0] = fmaxf(acc[mi][ni][2]*s1 + h1, 0.f);
                vhi[ni][1] = fmaxf(acc[mi][ni][3]*s1 + h1, 0.f);
            }
            if (mode == 1){
                #pragma unroll
                for (int g=0; g<2; ++g){
                    float pl = fmaxf(fmaxf(vlo[2*g][0],vlo[2*g][1]), fmaxf(vlo[2*g+1][0],vlo[2*g+1][1]));
                    float ph = fmaxf(fmaxf(vhi[2*g][0],vhi[2*g][1]), fmaxf(vhi[2*g+1][0],vhi[2*g+1][1]));
                    #pragma unroll
                    for (int off=1; off<4; off<<=1){
                        pl = fmaxf(pl, __shfl_xor_sync(0xffffffffu, pl, off));
                        ph = fmaxf(ph, __shfl_xor_sync(0xffffffffu, ph, off));
                    }
                    if ((lane & 3) == 0){
                        const int p = (n0 >> 4) + wn*2 + g;
                        __half hh, hl;
                        split2(pl, hh, hl);
                        Oa[(size_t)mlo*NP + p] = hh; Ob[(size_t)mlo*NP + p] = hl;
                        split2(ph, hh, hl);
                        Oa[(size_t)mhi*NP + p] = hh; Ob[(size_t)mhi*NP + p] = hl;
                    }
                }
            } else {
                #pragma unroll
                for (int ni=0; ni<4; ++ni){
                    const int n = n0 + wn*32 + ni*8 + (lane & 3)*2;
                    const size_t ilo = (size_t)mlo*ldO + n, ihi = (size_t)mhi*ldO + n;
                    __half ha0,la0, ha1,la1, hb0,lb0, hb1,lb1;
                    split2(vlo[ni][0], ha0, la0); split2(vlo[ni][1], ha1, la1);
                    split2(vhi[ni][0], hb0, lb0); split2(vhi[ni][1], hb1, lb1);
                    __half2 t;
                    t.x=ha0; t.y=ha1; *reinterpret_cast<__half2*>(&Oa[ilo]) = t;
                    t.x=la0; t.y=la1; *reinterpret_cast<__half2*>(&Ob[ilo]) = t;
                    t.x=hb0; t.y=hb1; *reinterpret_cast<__half2*>(&Oa[ihi]) = t;
                    t.x=lb0; t.y=lb1; *reinterpret_cast<__half2*>(&Ob[ihi]) = t;
                }
            }
        }
    };

    stageA(0, 0); CP_COMMIT();
    stageA(1, 1); CP_COMMIT();
    for (int cc=0; cc<16; ++cc){
        if (cc+2 < 16){ stageA(cc+2, (cc+2)&3); CP_COMMIT(); CP_WAIT2(); }
        else if (cc+1 < 16){ CP_WAIT1(); }
        else { CP_WAIT0(); }
        __syncthreads();
        compute_chunk(cc);
        if (cc == 7){
            epilogue(0);
            #pragma unroll
            for (int mi=0; mi<4; ++mi)
                #pragma unroll
                for (int ni=0; ni<4; ++ni)
                    #pragma unroll
                    for (int e=0; e<4; ++e) acc[mi][ni][e] = 0.f;
        }
    }
    epilogue(128);
}

// ---------------- head ----------------
__global__ __launch_bounds__(256) void head_kernel(const float* __restrict__ msa,
                                                   float* __restrict__ out)
{
    const int t = blockIdx.x*256 + threadIdx.x;
    #define NT(j) g_NET[(j)*NP + t]
    const float obj0 = NT(0), obj1 = NT(1);
    out[OFF_OBJ + t*2 + 0] = obj0;
    out[OFF_OBJ + t*2 + 1] = obj1;
    const float c0 = g_NX[t*3+0] + NT(2);
    const float c1 = g_NX[t*3+1] + NT(3);
    const float c2 = g_NX[t*3+2] + NT(4);
    out[OFF_CENTER + t*3 + 0] = c0;
    out[OFF_CENTER + t*3 + 1] = c1;
    out[OFF_CENTER + t*3 + 2] = c2;

    float ss[18];
    #pragma unroll
    for (int k=0;k<18;k++){ ss[k] = NT(29+k); out[OFF_SS + t*18 + k] = ss[k]; }
    int best = 0; float bv = ss[0];
    #pragma unroll
    for (int k=1;k<18;k++) if (ss[k] > bv){ bv = ss[k]; best = k; }

    float ps0=0.f, ps1=0.f, ps2=0.f;
    #pragma unroll
    for (int k=0;k<18;k++){
        const float m0=msa[k*3+0], m1=msa[k*3+1], m2=msa[k*3+2];
        const float r0 = NT(47+k*3+0)*m0;
        const float r1 = NT(47+k*3+1)*m1;
        const float r2 = NT(47+k*3+2)*m2;
        out[OFF_SRES + t*54 + k*3 + 0] = r0;
        out[OFF_SRES + t*54 + k*3 + 1] = r1;
        out[OFF_SRES + t*54 + k*3 + 2] = r2;
        if (k == best){ ps0 = r0+m0; ps1 = r1+m1; ps2 = r2+m2; }
    }
    out[OFF_PSIZE + t*3 + 0] = ps0;
    out[OFF_PSIZE + t*3 + 1] = ps1;
    out[OFF_PSIZE + t*3 + 2] = ps2;

    float sm[18];
    #pragma unroll
    for (int k=0;k<18;k++){ sm[k] = NT(101+k); out[OFF_SEM + t*18 + k] = sm[k]; }

    const float cc0 = c0, cc1 = c2, cc2 = -c1;
    const float hx = ps0*0.5f, hy = ps2*0.5f, hz = ps1*0.5f;
    const float SX[8]={1,1,-1,-1,1,1,-1,-1};
    const float SY[8]={1,1,1,1,-1,-1,-1,-1};
    const float SZ[8]={1,-1,-1,1,1,-1,-1,1};
    #pragma unroll
    for (int i=0;i<8;i++){
        out[OFF_CORN + t*24 + i*3 + 0] = cc0 + hx*SX[i];
        out[OFF_CORN + t*24 + i*3 + 1] = cc1 + hy*SY[i];
        out[OFF_CORN + t*24 + i*3 + 2] = cc2 + hz*SZ[i];
    }

    #pragma unroll
    for (int k=0;k<18;k++) out[OFF_SLOG + t*19 + k] = sm[k];
    out[OFF_SLOG + t*19 + 18] = (obj0 <= obj1) ? 0.0f : 1e10f;

    {
        const float mx = fmaxf(obj0,obj1);
        const float e0 = expf(obj0-mx), e1 = expf(obj1-mx);
        out[OFF_OPROB + t] = e1/(e0+e1);
    }
    {
        float mx = sm[0];
        #pragma unroll
        for (int k=1;k<18;k++) mx = fmaxf(mx, sm[k]);
        float e[18], ssum = 0.f;
        #pragma unroll
        for (int k=0;k<18;k++){ e[k] = expf(sm[k]-mx); ssum += e[k]; }
        #pragma unroll
        for (int k=0;k<18;k++) out[OFF_SPROB + t*18 + k] = e[k]/ssum;
    }
    #undef NT
}

// ---------------- host launcher ----------------
extern "C" void kernel_launch(void* const* d_in, const int* in_sizes, int n_in,
                              void* d_out, int out_size)
{
    const float* xyz      = (const float*)d_in[0];
    const float* features = (const float*)d_in[1];
    const float* sa_w1    = (const float*)d_in[2];
    const float* sa_w2    = (const float*)d_in[3];
    const float* sa_w3    = (const float*)d_in[4];
    const float* sa_gamma = (const float*)d_in[5];
    const float* sa_beta  = (const float*)d_in[6];
    const float* sa_mean  = (const float*)d_in[7];
    const float* sa_var   = (const float*)d_in[8];
    const float* p_w1     = (const float*)d_in[9];
    const float* p_w2     = (const float*)d_in[10];
    const float* p_w3     = (const float*)d_in[11];
    const float* p_b3     = (const float*)d_in[12];
    const float* p_gamma  = (const float*)d_in[13];
    const float* p_beta   = (const float*)d_in[14];
    const float* p_mean   = (const float*)d_in[15];
    const float* p_var    = (const float*)d_in[16];
    const float* msa      = (const float*)d_in[17];
    float* out = (float*)d_out;

    // one-time resources (resource caching only; per-call work is identical)
    static cudaStream_t s1 = nullptr;
    static cudaEvent_t evF = nullptr, evJ = nullptr;
    if (!s1){
        cudaStreamCreateWithFlags(&s1, cudaStreamNonBlocking);
        cudaEventCreateWithFlags(&evF, cudaEventDisableTiming);
        cudaEventCreateWithFlags(&evJ, cudaEventDisableTiming);
        cudaFuncSetAttribute(mma_gemm_kernel, cudaFuncAttributeMaxDynamicSharedMemorySize, SMT);
        cudaFuncSetAttribute(mma_gemm_bres_kernel, cudaFuncAttributeMaxDynamicSharedMemorySize, SMT2);
    }

    void *pFTa,*pFTb, *pZF, *pA1a,*pA1b, *pA2a,*pA2b;
    void *pW1Ta,*pW1Tb, *pW2a,*pW2b, *pW3a,*pW3b;
    void *pP1a,*pP1b, *pP2a,*pP2b, *pP3a,*pP3b, *pB3P;
    void *pYa,*pYb, *pY2a,*pY2b, *pY3a,*pY3b, *pNET;
    cudaGetSymbolAddress(&pFTa, g_FTa); cudaGetSymbolAddress(&pFTb, g_FTb);
    cudaGetSymbolAddress(&pZF,  g_ZF);
    cudaGetSymbolAddress(&pA1a, g_A1a); cudaGetSymbolAddress(&pA1b, g_A1b);
    cudaGetSymbolAddress(&pA2a, g_A2a); cudaGetSymbolAddress(&pA2b, g_A2b);
    cudaGetSymbolAddress(&pW1Ta, g_W1Ta); cudaGetSymbolAddress(&pW1Tb, g_W1Tb);
    cudaGetSymbolAddress(&pW2a, g_W2a); cudaGetSymbolAddress(&pW2b, g_W2b);
    cudaGetSymbolAddress(&pW3a, g_W3a); cudaGetSymbolAddress(&pW3b, g_W3b);
    cudaGetSymbolAddress(&pP1a, g_P1a); cudaGetSymbolAddress(&pP1b, g_P1b);
    cudaGetSymbolAddress(&pP2a, g_P2a); cudaGetSymbolAddress(&pP2b, g_P2b);
    cudaGetSymbolAddress(&pP3a, g_P3a); cudaGetSymbolAddress(&pP3b, g_P3b);
    cudaGetSymbolAddress(&pB3P, g_B3P);
    cudaGetSymbolAddress(&pYa,  g_Ya);  cudaGetSymbolAddress(&pYb,  g_Yb);
    cudaGetSymbolAddress(&pY2a, g_Y2a); cudaGetSymbolAddress(&pY2b, g_Y2b);
    cudaGetSymbolAddress(&pY3a, g_Y3a); cudaGetSymbolAddress(&pY3b, g_Y3b);
    cudaGetSymbolAddress(&pNET, g_NET);

    // ---- fork: fps -> ballq on side stream; prep/featT/Z on main stream ----
    cudaEventRecord(evF, 0);
    cudaStreamWaitEvent(s1, evF, 0);
    fps_kernel<<<BB, 256, 0, s1>>>(xyz);
    ballq_kernel<<<1024, 256, 0, s1>>>(xyz);
    cudaEventRecord(evJ, s1);

    prep_all<<<(PR_TOTAL + 255)/256, 256>>>(sa_w1, sa_w2, sa_w3, p_w1, p_w2, p_w3, p_b3);
    featT_kernel<<<dim3(KK/32, CC/32, BB), 256>>>(features);

    // Z = FT @ W1f^T : M=65536, N=256, K=256, identity -> fp32 [n][oc]
    mma_gemm_kernel<<<dim3(2, NPTS/128), 256, SMT>>>(
        (const __half*)pFTa, (const __half*)pFTb, CC, CC/32,
        (const __half*)pW1Ta, (const __half*)pW1Tb, CC,
        nullptr, nullptr, CC,
        (float*)pZF, nullptr,
        nullptr, nullptr, nullptr, nullptr, 2);

    // ---- join: asm1 needs Z (main) + ballq outputs (side) ----
    cudaStreamWaitEvent(0, evJ, 0);

    asm1_kernel<<<NCOL/ACOLS, 256>>>(sa_w1, sa_gamma+0, sa_beta+0, sa_mean+0, sa_var+0);

    // SA layer 2 (B-resident)
    mma_gemm_bres_kernel<<<NCOL/128, 256, SMT2>>>(
        (const __half*)pW2a, (const __half*)pW2b,
        (const __half*)pA1a, (const __half*)pA1b, NCOL,
        (__half*)pA2a, (__half*)pA2b, NCOL,
        sa_gamma+256, sa_beta+256, sa_mean+256, sa_var+256, 0);
    // SA layer 3 (B-resident) -> fused maxpool -> Y split planes
    mma_gemm_bres_kernel<<<NCOL/128, 256, SMT2>>>(
        (const __half*)pW3a, (const __half*)pW3b,
        (const __half*)pA2a, (const __half*)pA2b, NCOL,
        (__half*)pYa, (__half*)pYb, NP,
        sa_gamma+512, sa_beta+512, sa_mean+512, sa_var+512, 1);

    const dim3 gf(NP/128, 2);
    // FC1
    mma_gemm_kernel<<<gf, 256, SMT>>>(
        (const __half*)pP1a, (const __half*)pP1b, CC, CC/32,
        (const __half*)pYa, (const __half*)pYb, NP,
        (__half*)pY2a, (__half*)pY2b, NP,
        nullptr, nullptr,
        p_gamma+0, p_beta+0, p_mean+0, p_var+0, 0);
    // FC2
    mma_gemm_kernel<<<gf, 256, SMT>>>(
        (const __half*)pP2a, (const __half*)pP2b, CC, CC/32,
        (const __half*)pY2a, (const __half*)pY2b, NP,
        (__half*)pY3a, (__half*)pY3b, NP,
        nullptr, nullptr,
        p_gamma+256, p_beta+256, p_mean+256, p_var+256, 0);
    // FC3 (head conv): 128 padded rows, fp32 + bias, no relu
    mma_gemm_kernel<<<dim3(NP/128, 1), 256, SMT>>>(
        (const __half*)pP3a, (const __half*)pP3b, CC, CC/32,
        (const __half*)pY3a, (const __half*)pY3b, NP,
        nullptr, nullptr, NP,
        (float*)pNET, (const float*)pB3P,
        nullptr, nullptr, nullptr, nullptr, 2);

    head_kernel<<<NP/256, 256>>>(msa, out);
}

// round 14
// speedup vs baseline: 2.6280x; 1.0424x over previous
#include <cuda_runtime.h>
#include <cuda_fp16.h>
#include <math.h>
#include <cstdint>

// ---------------- problem constants ----------------
#define BB 32
#define KK 2048
#define CC 256
#define PP 256
#define SS 16
#define NCOL (BB*PP*SS)      // 131072
#define NP   (BB*PP)         // 8192
#define NPTS (BB*KK)         // 65536 distinct (b,point) columns
#define OUTC 119
#define MP3  128             // p_w3 M padded

// output section offsets (floats)
#define OFF_OBJ      0
#define OFF_CENTER   16384
#define OFF_SS       40960
#define OFF_SRES     188416
#define OFF_PSIZE    630784
#define OFF_SEM      655360
#define OFF_CORN     802816
#define OFF_SLOG     999424
#define OFF_OPROB    1155072
#define OFF_SPROB    1163264

// ---------------- scratch (device globals; zero-init guaranteed) ----------------
__device__ __align__(16) __half g_FTa[(size_t)NPTS * CC];  // features^T hi plane [n][c]
__device__ __align__(16) __half g_FTb[(size_t)NPTS * CC];  // lo plane
__device__ __align__(16) float  g_ZF [(size_t)NPTS * CC];  // Z = FT @ W1f^T, fp32 [n][oc]
__device__ __align__(16) __half g_A1a[(size_t)CC * NCOL];
__device__ __align__(16) __half g_A1b[(size_t)CC * NCOL];
__device__ __half g_W1Ta[CC*CC], g_W1Tb[CC*CC];   // W1 feature part, transposed [c][oc]
__device__ __half g_W2a[CC*CC], g_W2b[CC*CC];
__device__ __half g_W3a[CC*CC], g_W3b[CC*CC];
__device__ __half g_P1a[CC*CC], g_P1b[CC*CC];
__device__ __half g_P2a[CC*CC], g_P2b[CC*CC];
__device__ __half g_P3a[MP3*CC], g_P3b[MP3*CC];
__device__ float  g_B3P[MP3];
__device__ __half g_Ya [CC*NP], g_Yb [CC*NP];
__device__ __half g_Y2a[CC*NP], g_Y2b[CC*NP];
__device__ __half g_Y3a[CC*NP], g_Y3b[CC*NP];
__device__ float  g_NET[MP3 * NP];
__device__ float  g_NX[NP * 3];
__device__ float  g_GX[3 * NCOL];   // normalized grouped xyz (fp32)
__device__ int    g_IDX[NP * SS];

// ---------------- asm helpers (base-target: sm_80+) ----------------
__device__ __forceinline__ uint32_t smem_u32(const void* p){
    uint32_t a;
    asm("{ .reg .u64 t; cvta.to.shared.u64 t, %1; cvt.u32.u64 %0, t; }" : "=r"(a) : "l"(p));
    return a;
}
#define CP16(dst, src)  asm volatile("cp.async.cg.shared.global [%0], [%1], 16;" :: "r"(dst), "l"(src))
#define CP_COMMIT()     asm volatile("cp.async.commit_group;" ::: "memory")
#define CP_WAIT2()      asm volatile("cp.async.wait_group 2;" ::: "memory")
#define CP_WAIT1()      asm volatile("cp.async.wait_group 1;" ::: "memory")
#define CP_WAIT0()      asm volatile("cp.async.wait_group 0;" ::: "memory")

#define LDSM_X4(R, addr) \
    asm volatile("ldmatrix.sync.aligned.m8n8.x4.shared.b16 {%0,%1,%2,%3}, [%4];" \
        : "=r"((R)[0]),"=r"((R)[1]),"=r"((R)[2]),"=r"((R)[3]) : "r"(addr))
#define LDSM_X4T(R, addr) \
    asm volatile("ldmatrix.sync.aligned.m8n8.x4.trans.shared.b16 {%0,%1,%2,%3}, [%4];" \
        : "=r"((R)[0]),"=r"((R)[1]),"=r"((R)[2]),"=r"((R)[3]) : "r"(addr))

#define MMA_F16(C, A, b0, b1) \
    asm volatile("mma.sync.aligned.m16n8k16.row.col.f32.f16.f16.f32 " \
        "{%0,%1,%2,%3}, {%4,%5,%6,%7}, {%8,%9}, {%0,%1,%2,%3};" \
        : "+f"((C)[0]),"+f"((C)[1]),"+f"((C)[2]),"+f"((C)[3]) \
        : "r"((A)[0]),"r"((A)[1]),"r"((A)[2]),"r"((A)[3]), "r"(b0),"r"(b1))

// ---------------- misc helpers ----------------
__device__ __forceinline__ float d2_nofma(float ax,float ay,float az,float bx,float by,float bz){
    float dx=ax-bx, dy=ay-by, dz=az-bz;
    return __fadd_rn(__fadd_rn(__fmul_rn(dx,dx),__fmul_rn(dy,dy)),__fmul_rn(dz,dz));
}
__device__ __forceinline__ void split2(float v, __half& h, __half& l){
    h = __float2half(v);
    l = __float2half(v - __half2float(h));
}

// ---------------- FPS: one block per batch, 256 thr x 8 pts, redux argmax ----------------
__global__ __launch_bounds__(256) void fps_kernel(const float* __restrict__ xyz)
{
    __shared__ float sx[KK], sy[KK], sz[KK];
    __shared__ unsigned rv[2][8]; __shared__ int ri[2][8];
    const int b = blockIdx.x, tid = threadIdx.x;
    const float* xb = xyz + (size_t)b*KK*3;
    for (int i=tid;i<KK;i+=256){ sx[i]=xb[i*3+0]; sy[i]=xb[i*3+1]; sz[i]=xb[i*3+2]; }
    __syncthreads();
    float px[8], py[8], pz[8], pd[8];
    #pragma unroll
    for (int k=0;k<8;k++){
        const int i = tid + k*256;
        px[k]=sx[i]; py[k]=sy[i]; pz[k]=sz[i]; pd[k]=1e10f;
    }
    int far = 0;
    const int w = tid>>5, lane = tid&31;
    for (int it=0; it<PP; ++it){
        if (tid==0){
            g_NX[(b*PP+it)*3+0]=sx[far];
            g_NX[(b*PP+it)*3+1]=sy[far];
            g_NX[(b*PP+it)*3+2]=sz[far];
        }
        const float cx=sx[far], cy=sy[far], cz=sz[far];
        float bv = -1.f; int bi = 0;
        #pragma unroll
        for (int k=0;k<8;k++){
            pd[k] = fminf(pd[k], d2_nofma(px[k],py[k],pz[k],cx,cy,cz));
            if (pd[k] > bv){ bv = pd[k]; bi = tid + k*256; }
        }
        const unsigned vbits = __float_as_uint(bv);
        const unsigned vmax  = __reduce_max_sync(0xffffffffu, vbits);
        const unsigned cand  = (vbits == vmax) ? (unsigned)bi : 0xFFFFFFFFu;
        const unsigned imin  = __reduce_min_sync(0xffffffffu, cand);
        const int pb = it & 1;
        if (lane==0){ rv[pb][w]=vmax; ri[pb][w]=(int)imin; }
        __syncthreads();
        const unsigned vb = (lane<8) ? rv[pb][lane] : 0u;
        const int      ib = (lane<8) ? ri[pb][lane] : 0x7FFFFFFF;
        const unsigned vmax2 = __reduce_max_sync(0xffffffffu, vb);
        const unsigned cand2 = (vb == vmax2) ? (unsigned)ib : 0xFFFFFFFFu;
        far = (int)__reduce_min_sync(0xffffffffu, cand2);
    }
}

// ---------------- ball query + fused normalized-xyz emit (fp32) ----------------
__global__ __launch_bounds__(256) void ballq_kernel(const float* __restrict__ xyz)
{
    __shared__ float sx[KK], sy[KK], sz[KK];
    __shared__ int sidx[8][SS];
    const int b = blockIdx.x >> 5;
    const float* xb = xyz + (size_t)b*KK*3;
    for (int i=threadIdx.x;i<KK;i+=256){ sx[i]=xb[i*3+0]; sy[i]=xb[i*3+1]; sz[i]=xb[i*3+2]; }
    __syncthreads();
    const int warp = threadIdx.x>>5, lane = threadIdx.x&31;
    const int w = blockIdx.x*8 + warp;
    const float cx=g_NX[w*3+0], cy=g_NX[w*3+1], cz=g_NX[w*3+2];
    int cnt=0, firstIdx=0; bool haveFirst=false;
    for (int j=0;j<KK;j+=32){
        const int i = j + lane;
        const float dd = d2_nofma(sx[i],sy[i],sz[i],cx,cy,cz);
        const bool within = dd < 0.09f;
        const unsigned mask = __ballot_sync(0xffffffffu, within);
        if (mask){
            if (!haveFirst){ firstIdx = j + __ffs(mask) - 1; haveFirst=true; }
            const int rank = __popc(mask & ((1u<<lane)-1u));
            if (within && (cnt+rank) < SS) sidx[warp][cnt+rank] = i;
            cnt += __popc(mask);
            if (cnt >= SS) break;
        }
    }
    if (cnt < SS && lane >= cnt && lane < SS) sidx[warp][lane] = firstIdx;
    __syncwarp();
    if (lane < SS){
        const int i = sidx[warp][lane];
        const int t = w*SS + lane;
        g_IDX[t] = i;
        g_GX[0*NCOL + t] = (sx[i]-cx) / 0.3f;
        g_GX[1*NCOL + t] = (sy[i]-cy) / 0.3f;
        g_GX[2*NCOL + t] = (sz[i]-cz) / 0.3f;
    }
}

// ---------------- merged weight prep ----------------
#define PR_W1T_END (CC*CC)
#define PR_W2_END  (PR_W1T_END + CC*CC)
#define PR_W3_END  (PR_W2_END + CC*CC)
#define PR_P1_END  (PR_W3_END + CC*CC)
#define PR_P2_END  (PR_P1_END + CC*CC)
#define PR_P3_END  (PR_P2_END + MP3*CC)
#define PR_TOTAL   (PR_P3_END + MP3)

__global__ void prep_all(const float* __restrict__ w1, const float* __restrict__ w2,
                         const float* __restrict__ w3, const float* __restrict__ q1,
                         const float* __restrict__ q2, const float* __restrict__ q3,
                         const float* __restrict__ b3)
{
    const int t = blockIdx.x*256 + threadIdx.x;
    if (t >= PR_TOTAL) return;
    if (t >= PR_P3_END){ const int k = t - PR_P3_END; g_B3P[k] = (k < OUTC) ? b3[k] : 0.0f; return; }
    float v; __half *da, *db; int idx;
    if (t < PR_W1T_END){
        idx = t;
        const int c = idx >> 8, oc = idx & 255;
        v = w1[oc*259 + 3 + c];
        da=g_W1Ta; db=g_W1Tb;
    } else if (t < PR_W2_END){ idx=t-PR_W1T_END; v=w2[idx]; da=g_W2a; db=g_W2b; }
    else if (t < PR_W3_END){ idx=t-PR_W2_END; v=w3[idx]; da=g_W3a; db=g_W3b; }
    else if (t < PR_P1_END){ idx=t-PR_W3_END; v=q1[idx]; da=g_P1a; db=g_P1b; }
    else if (t < PR_P2_END){ idx=t-PR_P1_END; v=q2[idx]; da=g_P2a; db=g_P2b; }
    else {
        idx = t-PR_P2_END;
        const int m = idx >> 8;
        v = (m < OUTC) ? q3[idx] : 0.0f;
        da=g_P3a; db=g_P3b;
    }
    __half h,l; split2(v,h,l);
    da[idx]=h; db[idx]=l;
}

// ---------------- featT: features [b][c][j] fp32 -> FT planes [b*2048+j][c] ----------------
__global__ __launch_bounds__(256) void featT_kernel(const float* __restrict__ features)
{
    __shared__ float tile[32][33];
    const int jt = blockIdx.x*32, ct = blockIdx.y*32, b = blockIdx.z;
    const int tid = threadIdx.x;
    {
        const int cl = tid >> 3, j4 = (tid & 7)*4;
        const float4 v = *reinterpret_cast<const float4*>(
            &features[((size_t)b*CC + ct+cl)*KK + jt + j4]);
        tile[cl][j4+0]=v.x; tile[cl][j4+1]=v.y; tile[cl][j4+2]=v.z; tile[cl][j4+3]=v.w;
    }
    __syncthreads();
    {
        const int jl = tid >> 3, c4 = (tid & 7)*4;
        const size_t base = ((size_t)(b*KK + jt + jl))*CC + ct + c4;
        __half ha,la,hb,lb,hc,lc,hd,ld;
        split2(tile[c4+0][jl], ha, la);
        split2(tile[c4+1][jl], hb, lb);
        split2(tile[c4+2][jl], hc, lc);
        split2(tile[c4+3][jl], hd, ld);
        __half2 x;
        x.x=ha; x.y=hb; *reinterpret_cast<__half2*>(&g_FTa[base+0]) = x;
        x.x=hc; x.y=hd; *reinterpret_cast<__half2*>(&g_FTa[base+2]) = x;
        x.x=la; x.y=lb; *reinterpret_cast<__half2*>(&g_FTb[base+0]) = x;
        x.x=lc; x.y=ld; *reinterpret_cast<__half2*>(&g_FTb[base+2]) = x;
    }
}

// ---------------- asm1: gather fp32 Z rows + xyz term + BN/ReLU -> A1 planes ----------------
#define ACOLS 128
__global__ __launch_bounds__(256) void asm1_kernel(const float* __restrict__ w1,
    const float* __restrict__ gamma, const float* __restrict__ beta,
    const float* __restrict__ mean,  const float* __restrict__ var)
{
    __shared__ float sW0[256], sW1[256], sW2[256];
    __shared__ float sScale[256], sShift[256];
    __shared__ float sG0[ACOLS], sG1[ACOLS], sG2[ACOLS];
    __shared__ int   sIdx[ACOLS];
    __shared__ float sT[64][ACOLS+4];
    const int tid = threadIdx.x;
    const int t0 = blockIdx.x * ACOLS;
    const int b  = t0 >> 12;
    {
        const int oc = tid;
        sW0[oc] = w1[oc*259 + 0];
        sW1[oc] = w1[oc*259 + 1];
        sW2[oc] = w1[oc*259 + 2];
        const float sc = gamma[oc]*rsqrtf(var[oc]+1e-5f);
        sScale[oc]=sc; sShift[oc]=beta[oc]-mean[oc]*sc;
    }
    if (tid < ACOLS) sIdx[tid] = g_IDX[t0 + tid];
    for (int i=tid; i<3*ACOLS; i+=256){
        const int r = i >> 7, c = i & 127;
        float v = g_GX[(size_t)r*NCOL + t0 + c];
        if (r==0) sG0[c]=v; else if (r==1) sG1[c]=v; else sG2[c]=v;
    }
    __syncthreads();

    const int cl = tid >> 1;
    const int part = tid & 1;
    const int j = sIdx[cl];
    const float* zrow = g_ZF + ((size_t)(b*KK + j))*CC;
    const float g0=sG0[cl], g1=sG1[cl], g2=sG2[cl];

    #pragma unroll
    for (int s=0; s<4; ++s){
        const int oc0 = s*64 + part*32;
        const float4* pz = reinterpret_cast<const float4*>(&zrow[oc0]);
        #pragma unroll
        for (int q=0;q<8;q++){
            const float4 zv = pz[q];
            const int oc = oc0 + q*4;
            float v0 = zv.x + sW0[oc  ]*g0 + sW1[oc  ]*g1 + sW2[oc  ]*g2;
            float v1 = zv.y + sW0[oc+1]*g0 + sW1[oc+1]*g1 + sW2[oc+1]*g2;
            float v2 = zv.z + sW0[oc+2]*g0 + sW1[oc+2]*g1 + sW2[oc+2]*g2;
            float v3 = zv.w + sW0[oc+3]*g0 + sW1[oc+3]*g1 + sW2[oc+3]*g2;
            v0 = fmaxf(v0*sScale[oc  ] + sShift[oc  ], 0.f);
            v1 = fmaxf(v1*sScale[oc+1] + sShift[oc+1], 0.f);
            v2 = fmaxf(v2*sScale[oc+2] + sShift[oc+2], 0.f);
            v3 = fmaxf(v3*sScale[oc+3] + sShift[oc+3], 0.f);
            sT[oc   - s*64][cl] = v0;
            sT[oc+1 - s*64][cl] = v1;
            sT[oc+2 - s*64][cl] = v2;
            sT[oc+3 - s*64][cl] = v3;
        }
        __syncthreads();
        {
            const int r = tid >> 2;
            const int cseg = (tid & 3) * 32;
            const int oc = s*64 + r;
            __half2* da = reinterpret_cast<__half2*>(&g_A1a[(size_t)oc*NCOL + t0 + cseg]);
            __half2* db = reinterpret_cast<__half2*>(&g_A1b[(size_t)oc*NCOL + t0 + cseg]);
            #pragma unroll
            for (int q=0;q<16;q++){
                const float va = sT[r][cseg + 2*q], vb = sT[r][cseg + 2*q + 1];
                __half ha,la,hb,lb;
                split2(va,ha,la); split2(vb,hb,lb);
                __half2 th; th.x=ha; th.y=hb; da[q]=th;
                __half2 tl; tl.x=la; tl.y=lb; db[q]=tl;
            }
        }
        __syncthreads();
    }
}

// ---------------- shared GEMM geometry ----------------
#define A_PL 10240u
#define A_BUFS (2u*A_PL)
#define B_PL 8704u
#define B_BUFS (2u*B_PL)
#define BUFSZ (A_BUFS + B_BUFS)
#define SMT (4*BUFSZ)          // 151552 (streaming kernel)
#define B_CH (2u*B_PL)
#define BRES_B (8u*B_CH)       // 139264 resident region (fused kernel)
#define SA_STREAM BRES_B
#define SMT3 (BRES_B + 2u*BUFSZ)   // 215040 (fused SA kernel)

// ---------------- streaming mma kernel (Z, FC1, FC2, FC3) ----------------
// mode 0: BN+ReLU -> split planes; mode 2: (+bias if non-null) -> fp32; mode 3: identity -> split planes
__global__ __launch_bounds__(256) void mma_gemm_kernel(
    const __half* __restrict__ Aa, const __half* __restrict__ Ab, int Kw, int nch,
    const __half* __restrict__ Ba, const __half* __restrict__ Bb, int ldB,
    __half* __restrict__ Oa, __half* __restrict__ Ob, int ldO,
    float* __restrict__ OutF, const float* __restrict__ bias,
    const float* __restrict__ gamma, const float* __restrict__ beta,
    const float* __restrict__ mean,  const float* __restrict__ var,
    int mode)
{
    extern __shared__ char smem[];
    const uint32_t sbase = smem_u32(smem);
    const int tid = threadIdx.x, lane = tid & 31, wid = tid >> 5;
    const int wm = wid & 1, wn = wid >> 1;
    const int n0 = blockIdx.x * 128;
    const int mbase = blockIdx.y * 128;

    const size_t aoff = (size_t)mbase * Kw;
    const __half* A0 = Aa + aoff;
    const __half* A1 = Ab + aoff;

    auto stage = [&](int c, int buf){
        const int k0 = c * 32;
        const uint32_t sA = sbase + buf*BUFSZ;
        const uint32_t sB = sA + A_BUFS;
        #pragma unroll
        for (int it=0; it<2; ++it){
            const int idx = it*256 + tid;
            const int m = idx >> 2, kg = (idx & 3) * 8;
            const uint32_t d = sA + (uint32_t)m*80u + (uint32_t)kg*2u;
            const size_t so = (size_t)m*Kw + k0 + kg;
            CP16(d,        A0 + so);
            CP16(d + A_PL, A1 + so);
        }
        #pragma unroll
        for (int it=0; it<2; ++it){
            const int idx = it*256 + tid;
            const int k = idx >> 4, ng = (idx & 15) * 8;
            const uint32_t d = sB + (uint32_t)k*272u + (uint32_t)ng*2u;
            const size_t so = (size_t)(k0+k)*ldB + n0 + ng;
            CP16(d,        Ba + so);
            CP16(d + B_PL, Bb + so);
        }
    };

    float acc[4][4][4] = {};

    const uint32_t aRow = (uint32_t)((wm*64 + (lane & 15)) * 80) + (uint32_t)(((lane >> 4) << 3) * 2);
    const uint32_t bRow = (uint32_t)(((((lane >> 3) & 1) << 3) + (lane & 7)) * 272)
                        + (uint32_t)((wn*32 + ((lane >> 4) << 3)) * 2);

    auto compute_ab = [&](uint32_t aB, uint32_t bB){
        #pragma unroll
        for (int ks=0; ks<2; ++ks){
            uint32_t bfr[2][2][4];
            #pragma unroll
            for (int p=0; p<2; ++p)
                #pragma unroll
                for (int n2=0; n2<2; ++n2)
                    LDSM_X4T(bfr[p][n2], bB + p*B_PL + bRow + (uint32_t)(ks*16*272) + (uint32_t)(n2*32));
            #pragma unroll
            for (int mh=0; mh<2; ++mh){
                uint32_t afr[2][2][4];
                #pragma unroll
                for (int p=0; p<2; ++p)
                    #pragma unroll
                    for (int m2=0; m2<2; ++m2)
                        LDSM_X4(afr[p][m2], aB + p*A_PL + aRow + (uint32_t)((mh*2+m2)*16*80) + (uint32_t)(ks*32));
                #pragma unroll
                for (int m2=0; m2<2; ++m2){
                    const int mi = mh*2 + m2;
                    #pragma unroll
                    for (int ni=0; ni<4; ++ni){
                        const int n2 = ni >> 1, q = (ni & 1) * 2;
                        float* C = acc[mi][ni];
                        MMA_F16(C, afr[0][m2], bfr[0][n2][q], bfr[0][n2][q+1]);
                        MMA_F16(C, afr[0][m2], bfr[1][n2][q], bfr[1][n2][q+1]);
                        MMA_F16(C, afr[1][m2], bfr[0][n2][q], bfr[0][n2][q+1]);
                    }
                }
            }
        }
    };

    stage(0, 0); CP_COMMIT();
    stage(1, 1); CP_COMMIT();
    for (int c=0; c<nch; ++c){
        if (c+2 < nch){ stage(c+2, (c+2)&3); CP_COMMIT(); CP_WAIT2(); }
        else if (c+1 < nch){ CP_WAIT1(); }
        else { CP_WAIT0(); }
        __syncthreads();
        const uint32_t aB = sbase + (c&3)*BUFSZ;
        compute_ab(aB, aB + A_BUFS);
    }

    // ---- epilogue ----
    #pragma unroll
    for (int mi=0; mi<4; ++mi){
        const int mlo = mbase + wm*64 + mi*16 + (lane >> 2);
        const int mhi = mlo + 8;
        float s0, h0, s1, h1;
        if (mode == 2){
            s0 = 1.f; s1 = 1.f;
            h0 = bias ? bias[mlo] : 0.f;
            h1 = bias ? bias[mhi] : 0.f;
        } else if (mode == 3){
            s0 = 1.f; h0 = 0.f; s1 = 1.f; h1 = 0.f;
        } else {
            s0 = gamma[mlo] * rsqrtf(var[mlo] + 1e-5f);
            h0 = beta[mlo] - mean[mlo]*s0;
            s1 = gamma[mhi] * rsqrtf(var[mhi] + 1e-5f);
            h1 = beta[mhi] - mean[mhi]*s1;
        }
        float vlo[4][2], vhi[4][2];
        #pragma unroll
        for (int ni=0; ni<4; ++ni){
            vlo[ni][0] = acc[mi][ni][0]*s0 + h0;
            vlo[ni][1] = acc[mi][ni][1]*s0 + h0;
            vhi[ni][0] = acc[mi][ni][2]*s1 + h1;
            vhi[ni][1] = acc[mi][ni][3]*s1 + h1;
            if (mode == 0){
                vlo[ni][0]=fmaxf(vlo[ni][0],0.f); vlo[ni][1]=fmaxf(vlo[ni][1],0.f);
                vhi[ni][0]=fmaxf(vhi[ni][0],0.f); vhi[ni][1]=fmaxf(vhi[ni][1],0.f);
            }
        }
        if (mode == 2){
            #pragma unroll
            for (int ni=0; ni<4; ++ni){
                const int n = n0 + wn*32 + ni*8 + (lane & 3)*2;
                *reinterpret_cast<float2*>(&OutF[(size_t)mlo*ldO + n]) = make_float2(vlo[ni][0], vlo[ni][1]);
                *reinterpret_cast<float2*>(&OutF[(size_t)mhi*ldO + n]) = make_float2(vhi[ni][0], vhi[ni][1]);
            }
        } else {
            #pragma unroll
            for (int ni=0; ni<4; ++ni){
                const int n = n0 + wn*32 + ni*8 + (lane & 3)*2;
                const size_t ilo = (size_t)mlo*ldO + n, ihi = (size_t)mhi*ldO + n;
                __half ha0,la0, ha1,la1, hb0,lb0, hb1,lb1;
                split2(vlo[ni][0], ha0, la0); split2(vlo[ni][1], ha1, la1);
                split2(vhi[ni][0], hb0, lb0); split2(vhi[ni][1], hb1, lb1);
                __half2 t;
                t.x=ha0; t.y=ha1; *reinterpret_cast<__half2*>(&Oa[ilo]) = t;
                t.x=la0; t.y=la1; *reinterpret_cast<__half2*>(&Ob[ilo]) = t;
                t.x=hb0; t.y=hb1; *reinterpret_cast<__half2*>(&Oa[ihi]) = t;
                t.x=lb0; t.y=lb1; *reinterpret_cast<__half2*>(&Ob[ihi]) = t;
            }
        }
    }
}

// ---------------- fused SA layers 2+3: A2 lives entirely in smem ----------------
// Per CTA (128 cols): layer2 streams A1-chunks + W2-chunks (2-buf pipeline),
// epilogue writes BN+ReLU split-fp16 A2 into the resident smem region in
// B-operand layout; layer3 streams only W3 chunks against resident A2,
// finishing with the fused 16-col maxpool into Y planes.
__global__ __launch_bounds__(256) void sa23_kernel(
    const __half* __restrict__ W2a_, const __half* __restrict__ W2b_,
    const __half* __restrict__ Ba,  const __half* __restrict__ Bb,   // A1 planes
    const __half* __restrict__ W3a_, const __half* __restrict__ W3b_,
    __half* __restrict__ Oa, __half* __restrict__ Ob,                // Y planes (stride NP)
    const float* __restrict__ gamma2, const float* __restrict__ beta2,
    const float* __restrict__ mean2,  const float* __restrict__ var2,
    const float* __restrict__ gamma3, const float* __restrict__ beta3,
    const float* __restrict__ mean3,  const float* __restrict__ var3)
{
    extern __shared__ char smem[];
    const uint32_t sbase = smem_u32(smem);
    const int tid = threadIdx.x, lane = tid & 31, wid = tid >> 5;
    const int wm = wid & 1, wn = wid >> 1;
    const int n0 = blockIdx.x * 128;

    const uint32_t aRow = (uint32_t)((wm*64 + (lane & 15)) * 80) + (uint32_t)(((lane >> 4) << 3) * 2);
    const uint32_t bRow = (uint32_t)(((((lane >> 3) & 1) << 3) + (lane & 7)) * 272)
                        + (uint32_t)((wn*32 + ((lane >> 4) << 3)) * 2);

    float acc[4][4][4] = {};

    auto compute_ab = [&](uint32_t aB, uint32_t bB){
        #pragma unroll
        for (int ks=0; ks<2; ++ks){
            uint32_t bfr[2][2][4];
            #pragma unroll
            for (int p=0; p<2; ++p)
                #pragma unroll
                for (int n2=0; n2<2; ++n2)
                    LDSM_X4T(bfr[p][n2], bB + p*B_PL + bRow + (uint32_t)(ks*16*272) + (uint32_t)(n2*32));
            #pragma unroll
            for (int mh=0; mh<2; ++mh){
                uint32_t afr[2][2][4];
                #pragma unroll
                for (int p=0; p<2; ++p)
                    #pragma unroll
                    for (int m2=0; m2<2; ++m2)
                        LDSM_X4(afr[p][m2], aB + p*A_PL + aRow + (uint32_t)((mh*2+m2)*16*80) + (uint32_t)(ks*32));
                #pragma unroll
                for (int m2=0; m2<2; ++m2){
                    const int mi = mh*2 + m2;
                    #pragma unroll
                    for (int ni=0; ni<4; ++ni){
                        const int n2 = ni >> 1, q = (ni & 1) * 2;
                        float* C = acc[mi][ni];
                        MMA_F16(C, afr[0][m2], bfr[0][n2][q], bfr[0][n2][q+1]);
                        MMA_F16(C, afr[0][m2], bfr[1][n2][q], bfr[1][n2][q+1]);
                        MMA_F16(C, afr[1][m2], bfr[0][n2][q], bfr[0][n2][q+1]);
                    }
                }
            }
        }
    };

    auto clear_acc = [&](){
        #pragma unroll
        for (int mi=0; mi<4; ++mi)
            #pragma unroll
            for (int ni=0; ni<4; ++ni)
                #pragma unroll
                for (int e=0; e<4; ++e) acc[mi][ni][e] = 0.f;
    };

    // ---- layer 2 staging: W2 chunk (A) + A1 chunk (B) ----
    auto stage2 = [&](int c, int buf){
        const int half = c >> 3, k0 = (c & 7) * 32;
        const __half* A0 = W2a_ + (size_t)(half*128)*CC;
        const __half* A1p = W2b_ + (size_t)(half*128)*CC;
        const uint32_t sA = sbase + SA_STREAM + (uint32_t)buf*BUFSZ;
        const uint32_t sB = sA + A_BUFS;
        #pragma unroll
        for (int it=0; it<2; ++it){
            const int idx = it*256 + tid;
            const int m = idx >> 2, kg = (idx & 3) * 8;
            const uint32_t d = sA + (uint32_t)m*80u + (uint32_t)kg*2u;
            const size_t so = (size_t)m*CC + k0 + kg;
            CP16(d,        A0 + so);
            CP16(d + A_PL, A1p + so);
        }
        #pragma unroll
        for (int it=0; it<2; ++it){
            const int idx = it*256 + tid;
            const int k = idx >> 4, ng = (idx & 15) * 8;
            const uint32_t d = sB + (uint32_t)k*272u + (uint32_t)ng*2u;
            const size_t so = (size_t)(k0+k)*NCOL + n0 + ng;
            CP16(d,        Ba + so);
            CP16(d + B_PL, Bb + so);
        }
    };
    // ---- layer 3 staging: W3 chunk only ----
    auto stage3 = [&](int c, int buf){
        const int half = c >> 3, k0 = (c & 7) * 32;
        const __half* A0 = W3a_ + (size_t)(half*128)*CC;
        const __half* A1p = W3b_ + (size_t)(half*128)*CC;
        const uint32_t sA = sbase + SA_STREAM + (uint32_t)buf*BUFSZ;
        #pragma unroll
        for (int it=0; it<2; ++it){
            const int idx = it*256 + tid;
            const int m = idx >> 2, kg = (idx & 3) * 8;
            const uint32_t d = sA + (uint32_t)m*80u + (uint32_t)kg*2u;
            const size_t so = (size_t)m*CC + k0 + kg;
            CP16(d,        A0 + so);
            CP16(d + A_PL, A1p + so);
        }
    };

    // ---- layer2 epilogue -> resident smem region (B-operand layout) ----
    auto epi2 = [&](int mhalf){
        #pragma unroll
        for (int mi=0; mi<4; ++mi){
            const int mlo = mhalf*128 + wm*64 + mi*16 + (lane >> 2);
            const int mhi = mlo + 8;
            const float s0 = gamma2[mlo] * rsqrtf(var2[mlo] + 1e-5f);
            const float h0 = beta2[mlo] - mean2[mlo]*s0;
            const float s1 = gamma2[mhi] * rsqrtf(var2[mhi] + 1e-5f);
            const float h1 = beta2[mhi] - mean2[mhi]*s1;
            #pragma unroll
            for (int ni=0; ni<4; ++ni){
                const int ncl = wn*32 + ni*8 + (lane & 3)*2;
                const float v0 = fmaxf(acc[mi][ni][0]*s0 + h0, 0.f);
                const float v1 = fmaxf(acc[mi][ni][1]*s0 + h0, 0.f);
                const float v2 = fmaxf(acc[mi][ni][2]*s1 + h1, 0.f);
                const float v3 = fmaxf(acc[mi][ni][3]*s1 + h1, 0.f);
                {
                    const uint32_t off = (uint32_t)(mlo>>5)*B_CH + (uint32_t)(mlo&31)*272u + (uint32_t)ncl*2u;
                    __half h,l, h2v,l2v;
                    split2(v0,h,l); split2(v1,h2v,l2v);
                    __half2 th; th.x=h; th.y=h2v; *reinterpret_cast<__half2*>(smem+off) = th;
                    __half2 tl; tl.x=l; tl.y=l2v; *reinterpret_cast<__half2*>(smem+off+B_PL) = tl;
                }
                {
                    const uint32_t off = (uint32_t)(mhi>>5)*B_CH + (uint32_t)(mhi&31)*272u + (uint32_t)ncl*2u;
                    __half h,l, h2v,l2v;
                    split2(v2,h,l); split2(v3,h2v,l2v);
                    __half2 th; th.x=h; th.y=h2v; *reinterpret_cast<__half2*>(smem+off) = th;
                    __half2 tl; tl.x=l; tl.y=l2v; *reinterpret_cast<__half2*>(smem+off+B_PL) = tl;
                }
            }
        }
    };

    // ---- layer3 epilogue: BN+ReLU + fused 16-col maxpool -> Y planes ----
    auto epi3 = [&](int mhalf){
        #pragma unroll
        for (int mi=0; mi<4; ++mi){
            const int mlo = mhalf*128 + wm*64 + mi*16 + (lane >> 2);
            const int mhi = mlo + 8;
            const float s0 = gamma3[mlo] * rsqrtf(var3[mlo] + 1e-5f);
            const float h0 = beta3[mlo] - mean3[mlo]*s0;
            const float s1 = gamma3[mhi] * rsqrtf(var3[mhi] + 1e-5f);
            const float h1 = beta3[mhi] - mean3[mhi]*s1;
            float vlo[4][2], vhi[4][2];
            #pragma unroll
            for (int ni=0; ni<4; ++ni){
                vlo[ni][0] = fmaxf(acc[mi][ni][0]*s0 + h0, 0.f);
                vlo[ni][1] = fmaxf(acc[mi][ni][1]*s0 + h0, 0.f);
                vhi[ni][0] = fmaxf(acc[mi][ni][2]*s1 + h1, 0.f);
                vhi[ni][1] = fmaxf(acc[mi][ni][3]*s1 + h1, 0.f);
            }
            #pragma unroll
            for (int g=0; g<2; ++g){
                float pl = fmaxf(fmaxf(vlo[2*g][0],vlo[2*g][1]), fmaxf(vlo[2*g+1][0],vlo[2*g+1][1]));
                float ph = fmaxf(fmaxf(vhi[2*g][0],vhi[2*g][1]), fmaxf(vhi[2*g+1][0],vhi[2*g+1][1]));
                #pragma unroll
                for (int off=1; off<4; off<<=1){
                    pl = fmaxf(pl, __shfl_xor_sync(0xffffffffu, pl, off));
                    ph = fmaxf(ph, __shfl_xor_sync(0xffffffffu, ph, off));
                }
                if ((lane & 3) == 0){
                    const int p = (n0 >> 4) + wn*2 + g;
                    __half hh, hl;
                    split2(pl, hh, hl);
                    Oa[(size_t)mlo*NP + p] = hh; Ob[(size_t)mlo*NP + p] = hl;
                    split2(ph, hh, hl);
                    Oa[(size_t)mhi*NP + p] = hh; Ob[(size_t)mhi*NP + p] = hl;
                }
            }
        }
    };

    // ======== layer 2 ========
    stage2(0, 0); CP_COMMIT();
    for (int c=0; c<16; ++c){
        if (c+1 < 16){ stage2(c+1, (c+1)&1); CP_COMMIT(); CP_WAIT1(); }
        else         { CP_WAIT0(); }
        __syncthreads();
        const uint32_t aB = sbase + SA_STREAM + (uint32_t)(c&1)*BUFSZ;
        compute_ab(aB, aB + A_BUFS);
        if (c == 7){ epi2(0); clear_acc(); }
        __syncthreads();
    }
    epi2(1); clear_acc();
    __syncthreads();   // resident A2 complete before layer3 reads

    // ======== layer 3 ========
    stage3(0, 0); CP_COMMIT();
    for (int c=0; c<16; ++c){
        if (c+1 < 16){ stage3(c+1, (c+1)&1); CP_COMMIT(); CP_WAIT1(); }
        else         { CP_WAIT0(); }
        __syncthreads();
        const uint32_t aB = sbase + SA_STREAM + (uint32_t)(c&1)*BUFSZ;
        compute_ab(aB, sbase + (uint32_t)(c&7)*B_CH);
        if (c == 7){ epi3(0); clear_acc(); }
        __syncthreads();
    }
    epi3(1);
}

// ---------------- head ----------------
__global__ __launch_bounds__(256) void head_kernel(const float* __restrict__ msa,
                                                   float* __restrict__ out)
{
    const int t = blockIdx.x*256 + threadIdx.x;
    #define NT(j) g_NET[(j)*NP + t]
    const float obj0 = NT(0), obj1 = NT(1);
    out[OFF_OBJ + t*2 + 0] = obj0;
    out[OFF_OBJ + t*2 + 1] = obj1;
    const float c0 = g_NX[t*3+0] + NT(2);
    const float c1 = g_NX[t*3+1] + NT(3);
    const float c2 = g_NX[t*3+2] + NT(4);
    out[OFF_CENTER + t*3 + 0] = c0;
    out[OFF_CENTER + t*3 + 1] = c1;
    out[OFF_CENTER + t*3 + 2] = c2;

    float ss[18];
    #pragma unroll
    for (int k=0;k<18;k++){ ss[k] = NT(29+k); out[OFF_SS + t*18 + k] = ss[k]; }
    int best = 0; float bv = ss[0];
    #pragma unroll
    for (int k=1;k<18;k++) if (ss[k] > bv){ bv = ss[k]; best = k; }

    float ps0=0.f, ps1=0.f, ps2=0.f;
    #pragma unroll
    for (int k=0;k<18;k++){
        const float m0=msa[k*3+0], m1=msa[k*3+1], m2=msa[k*3+2];
        const float r0 = NT(47+k*3+0)*m0;
        const float r1 = NT(47+k*3+1)*m1;
        const float r2 = NT(47+k*3+2)*m2;
        out[OFF_SRES + t*54 + k*3 + 0] = r0;
        out[OFF_SRES + t*54 + k*3 + 1] = r1;
        out[OFF_SRES + t*54 + k*3 + 2] = r2;
        if (k == best){ ps0 = r0+m0; ps1 = r1+m1; ps2 = r2+m2; }
    }
    out[OFF_PSIZE + t*3 + 0] = ps0;
    out[OFF_PSIZE + t*3 + 1] = ps1;
    out[OFF_PSIZE + t*3 + 2] = ps2;

    float sm[18];
    #pragma unroll
    for (int k=0;k<18;k++){ sm[k] = NT(101+k); out[OFF_SEM + t*18 + k] = sm[k]; }

    const float cc0 = c0, cc1 = c2, cc2 = -c1;
    const float hx = ps0*0.5f, hy = ps2*0.5f, hz = ps1*0.5f;
    const float SX[8]={1,1,-1,-1,1,1,-1,-1};
    const float SY[8]={1,1,1,1,-1,-1,-1,-1};
    const float SZ[8]={1,-1,-1,1,1,-1,-1,1};
    #pragma unroll
    for (int i=0;i<8;i++){
        out[OFF_CORN + t*24 + i*3 + 0] = cc0 + hx*SX[i];
        out[OFF_CORN + t*24 + i*3 + 1] = cc1 + hy*SY[i];
        out[OFF_CORN + t*24 + i*3 + 2] = cc2 + hz*SZ[i];
    }

    #pragma unroll
    for (int k=0;k<18;k++) out[OFF_SLOG + t*19 + k] = sm[k];
    out[OFF_SLOG + t*19 + 18] = (obj0 <= obj1) ? 0.0f : 1e10f;

    {
        const float mx = fmaxf(obj0,obj1);
        const float e0 = expf(obj0-mx), e1 = expf(obj1-mx);
        out[OFF_OPROB + t] = e1/(e0+e1);
    }
    {
        float mx = sm[0];
        #pragma unroll
        for (int k=1;k<18;k++) mx = fmaxf(mx, sm[k]);
        float e[18], ssum = 0.f;
        #pragma unroll
        for (int k=0;k<18;k++){ e[k] = expf(sm[k]-mx); ssum += e[k]; }
        #pragma unroll
        for (int k=0;k<18;k++) out[OFF_SPROB + t*18 + k] = e[k]/ssum;
    }
    #undef NT
}

// ---------------- host launcher ----------------
extern "C" void kernel_launch(void* const* d_in, const int* in_sizes, int n_in,
                              void* d_out, int out_size)
{
    const float* xyz      = (const float*)d_in[0];
    const float* features = (const float*)d_in[1];
    const float* sa_w1    = (const float*)d_in[2];
    const float* sa_w2    = (const float*)d_in[3];
    const float* sa_w3    = (const float*)d_in[4];
    const float* sa_gamma = (const float*)d_in[5];
    const float* sa_beta  = (const float*)d_in[6];
    const float* sa_mean  = (const float*)d_in[7];
    const float* sa_var   = (const float*)d_in[8];
    const float* p_w1     = (const float*)d_in[9];
    const float* p_w2     = (const float*)d_in[10];
    const float* p_w3     = (const float*)d_in[11];
    const float* p_b3     = (const float*)d_in[12];
    const float* p_gamma  = (const float*)d_in[13];
    const float* p_beta   = (const float*)d_in[14];
    const float* p_mean   = (const float*)d_in[15];
    const float* p_var    = (const float*)d_in[16];
    const float* msa      = (const float*)d_in[17];
    float* out = (float*)d_out;

    // one-time resources (resource caching only; per-call work is identical)
    static cudaStream_t s1 = nullptr;
    static cudaEvent_t evF = nullptr, evJ = nullptr;
    if (!s1){
        cudaStreamCreateWithFlags(&s1, cudaStreamNonBlocking);
        cudaEventCreateWithFlags(&evF, cudaEventDisableTiming);
        cudaEventCreateWithFlags(&evJ, cudaEventDisableTiming);
        cudaFuncSetAttribute(mma_gemm_kernel, cudaFuncAttributeMaxDynamicSharedMemorySize, SMT);
        cudaFuncSetAttribute(sa23_kernel, cudaFuncAttributeMaxDynamicSharedMemorySize, SMT3);
    }

    void *pFTa,*pFTb, *pZF, *pA1a,*pA1b;
    void *pW1Ta,*pW1Tb, *pW2a,*pW2b, *pW3a,*pW3b;
    void *pP1a,*pP1b, *pP2a,*pP2b, *pP3a,*pP3b, *pB3P;
    void *pYa,*pYb, *pY2a,*pY2b, *pY3a,*pY3b, *pNET;
    cudaGetSymbolAddress(&pFTa, g_FTa); cudaGetSymbolAddress(&pFTb, g_FTb);
    cudaGetSymbolAddress(&pZF,  g_ZF);
    cudaGetSymbolAddress(&pA1a, g_A1a); cudaGetSymbolAddress(&pA1b, g_A1b);
    cudaGetSymbolAddress(&pW1Ta, g_W1Ta); cudaGetSymbolAddress(&pW1Tb, g_W1Tb);
    cudaGetSymbolAddress(&pW2a, g_W2a); cudaGetSymbolAddress(&pW2b, g_W2b);
    cudaGetSymbolAddress(&pW3a, g_W3a); cudaGetSymbolAddress(&pW3b, g_W3b);
    cudaGetSymbolAddress(&pP1a, g_P1a); cudaGetSymbolAddress(&pP1b, g_P1b);
    cudaGetSymbolAddress(&pP2a, g_P2a); cudaGetSymbolAddress(&pP2b, g_P2b);
    cudaGetSymbolAddress(&pP3a, g_P3a); cudaGetSymbolAddress(&pP3b, g_P3b);
    cudaGetSymbolAddress(&pB3P, g_B3P);
    cudaGetSymbolAddress(&pYa,  g_Ya);  cudaGetSymbolAddress(&pYb,  g_Yb);
    cudaGetSymbolAddress(&pY2a, g_Y2a); cudaGetSymbolAddress(&pY2b, g_Y2b);
    cudaGetSymbolAddress(&pY3a, g_Y3a); cudaGetSymbolAddress(&pY3b, g_Y3b);
    cudaGetSymbolAddress(&pNET, g_NET);

    // ---- fork: fps -> ballq on side stream; prep/featT/Z on main stream ----
    cudaEventRecord(evF, 0);
    cudaStreamWaitEvent(s1, evF, 0);
    fps_kernel<<<BB, 256, 0, s1>>>(xyz);
    ballq_kernel<<<1024, 256, 0, s1>>>(xyz);
    cudaEventRecord(evJ, s1);

    prep_all<<<(PR_TOTAL + 255)/256, 256>>>(sa_w1, sa_w2, sa_w3, p_w1, p_w2, p_w3, p_b3);
    featT_kernel<<<dim3(KK/32, CC/32, BB), 256>>>(features);

    // Z = FT @ W1f^T : M=65536, N=256, K=256, identity -> fp32 [n][oc]
    mma_gemm_kernel<<<dim3(2, NPTS/128), 256, SMT>>>(
        (const __half*)pFTa, (const __half*)pFTb, CC, CC/32,
        (const __half*)pW1Ta, (const __half*)pW1Tb, CC,
        nullptr, nullptr, CC,
        (float*)pZF, nullptr,
        nullptr, nullptr, nullptr, nullptr, 2);

    // ---- join: asm1 needs Z (main) + ballq outputs (side) ----
    cudaStreamWaitEvent(0, evJ, 0);

    asm1_kernel<<<NCOL/ACOLS, 256>>>(sa_w1, sa_gamma+0, sa_beta+0, sa_mean+0, sa_var+0);

    // SA layers 2+3 fused (A2 stays in smem) -> Y planes
    sa23_kernel<<<NCOL/128, 256, SMT3>>>(
        (const __half*)pW2a, (const __half*)pW2b,
        (const __half*)pA1a, (const __half*)pA1b,
        (const __half*)pW3a, (const __half*)pW3b,
        (__half*)pYa, (__half*)pYb,
        sa_gamma+256, sa_beta+256, sa_mean+256, sa_var+256,
        sa_gamma+512, sa_beta+512, sa_mean+512, sa_var+512);

    const dim3 gf(NP/128, 2);
    // FC1
    mma_gemm_kernel<<<gf, 256, SMT>>>(
        (const __half*)pP1a, (const __half*)pP1b, CC, CC/32,
        (const __half*)pYa, (const __half*)pYb, NP,
        (__half*)pY2a, (__half*)pY2b, NP,
        nullptr, nullptr,
        p_gamma+0, p_beta+0, p_mean+0, p_var+0, 0);
    // FC2
    mma_gemm_kernel<<<gf, 256, SMT>>>(
        (const __half*)pP2a, (const __half*)pP2b, CC, CC/32,
        (const __half*)pY2a, (const __half*)pY2b, NP,
        (__half*)pY3a, (__half*)pY3b, NP,
        nullptr, nullptr,
        p_gamma+256, p_beta+256, p_mean+256, p_var+256, 0);
    // FC3 (head conv): 128 padded rows, fp32 + bias, no relu
    mma_gemm_kernel<<<dim3(NP/128, 1), 256, SMT>>>(
        (const __half*)pP3a, (const __half*)pP3b, CC, CC/32,
        (const __half*)pY3a, (const __half*)pY3b, NP,
        nullptr, nullptr, NP,
        (float*)pNET, (const float*)pB3P,
        nullptr, nullptr, nullptr, nullptr, 2);

    head_kernel<<<NP/256, 256>>>(msa, out);
}